// round 10
// baseline (speedup 1.0000x reference)
#include <cuda_runtime.h>
#include <cuda_fp16.h>
#include <math.h>
#include <stdint.h>

#define B_    4
#define L_    16384
#define D_    256
#define H_    8
#define DH_   32
#define FF_   1024
#define MTOK  65536
#define NCH   32
#define CHTOK 512

// ---------------- scratch ----------------
__device__ __half g_xh  [MTOK * D_];     // x as half
__device__ __half g_qkvh[MTOK * 768];    // q|k|v per token (half)
__device__ __half g_ah  [MTOK * D_];     // attn readout (half)
__device__ float  g_x1  [MTOK * D_];     // LN1 output (f32, residual for LN2)
__device__ __half g_x1h [MTOK * D_];     // LN1 output (half, FFN A)
__device__ float  g_kvpart[NCH * 32 * 1024];
__device__ float  g_kspart[NCH * 32 * 32];
__device__ float  g_kv[32 * 1024];
__device__ float  g_ksum[32 * 32];
// transposed weights [N,K] row-major, half
__device__ __half g_wqkvT[768 * D_];
__device__ __half g_woT[D_ * D_];
__device__ __half g_w1T[FF_ * D_];
__device__ __half g_w2T[D_ * FF_];
__device__ float  g_bqkv[768];

// ---------------- helpers ----------------
__device__ __forceinline__ uint32_t smem_u32(const void* p) {
    uint32_t a;
    asm("{ .reg .u64 t; cvta.to.shared.u64 t, %1; cvt.u32.u64 %0, t; }" : "=r"(a) : "l"(p));
    return a;
}
__device__ __forceinline__ void cp16(uint32_t dst, const void* src) {
    asm volatile("cp.async.cg.shared.global [%0], [%1], 16;" :: "r"(dst), "l"(src));
}
__device__ __forceinline__ void mma16(float* c, uint32_t a0, uint32_t a1,
                                      uint32_t a2, uint32_t a3,
                                      uint32_t b0, uint32_t b1) {
    asm volatile("mma.sync.aligned.m16n8k16.row.col.f32.f16.f16.f32 "
        "{%0,%1,%2,%3}, {%4,%5,%6,%7}, {%8,%9}, {%0,%1,%2,%3};"
        : "+f"(c[0]), "+f"(c[1]), "+f"(c[2]), "+f"(c[3])
        : "r"(a0), "r"(a1), "r"(a2), "r"(a3), "r"(b0), "r"(b1));
}
#define LDMX4T(r, addr) \
    asm volatile("ldmatrix.sync.aligned.m8n8.x4.trans.shared.b16 {%0,%1,%2,%3}, [%4];" \
        : "=r"((r)[0]), "=r"((r)[1]), "=r"((r)[2]), "=r"((r)[3]) : "r"(addr))

// ============================================================================
// x -> half copy
// ============================================================================
__global__ __launch_bounds__(512) void k_cvtx(const float* __restrict__ x)
{
    int i = blockIdx.x * 512 + threadIdx.x;
    float4 v = *(const float4*)&x[(size_t)i * 4];
    __half2 h0 = __floats2half2_rn(v.x, v.y);
    __half2 h1 = __floats2half2_rn(v.z, v.w);
    *(uint2*)&g_xh[(size_t)i * 4] = make_uint2(*(uint32_t*)&h0, *(uint32_t*)&h1);
}

// ============================================================================
// ALL weight transposes + bias concat in ONE launch.
// ============================================================================
__global__ void k_trall(const float* __restrict__ Wq, const float* __restrict__ Wk,
                        const float* __restrict__ Wv, const float* __restrict__ Wo,
                        const float* __restrict__ W1, const float* __restrict__ W2,
                        const float* __restrict__ bq, const float* __restrict__ bk,
                        const float* __restrict__ bv)
{
    const int bid = blockIdx.x;
    if (bid == 768) {
        int t = threadIdx.y * 32 + threadIdx.x;
        g_bqkv[t] = bq[t]; g_bqkv[256 + t] = bk[t]; g_bqkv[512 + t] = bv[t];
        return;
    }
    const float* W; __half* Wt; int K, N, idx;
    if (bid < 256) {
        idx = bid & 63; K = D_; N = D_;
        int sel = bid >> 6;
        W  = (sel == 0) ? Wq : (sel == 1) ? Wk : (sel == 2) ? Wv : Wo;
        Wt = (sel == 0) ? g_wqkvT : (sel == 1) ? g_wqkvT + 256 * D_
           : (sel == 2) ? g_wqkvT + 512 * D_ : g_woT;
    } else if (bid < 512) {
        idx = bid - 256; K = D_; N = FF_; W = W1; Wt = g_w1T;
    } else {
        idx = bid - 512; K = FF_; N = D_; W = W2; Wt = g_w2T;
    }
    const int xt = N >> 5;
    const int n0 = (idx % xt) * 32, k0 = (idx / xt) * 32;

    __shared__ float t[32][33];
    int x = threadIdx.x, y = threadIdx.y;
    for (int i = y; i < 32; i += 8) t[i][x] = W[(size_t)(k0 + i) * N + n0 + x];
    __syncthreads();
    for (int i = y; i < 32; i += 8)
        Wt[(size_t)(n0 + i) * K + k0 + x] = __float2half(t[x][i]);
}

// ============================================================================
// fp16 mma.sync GEMM (BN=128, 256 thr, 3-stage): QKV projection.
// ============================================================================
__device__ __forceinline__ void stage256(const __half* __restrict__ Ap,
                                         const __half* __restrict__ Bp,
                                         int K, uint32_t sa, uint32_t sb, int tid)
{
#pragma unroll
    for (int t = 0; t < 2; t++) {
        int i = tid + t * 256;
        int row = i >> 2, c = i & 3;
        cp16(sa + row * 96 + c * 16, Ap + (size_t)row * K + c * 8);
    }
#pragma unroll
    for (int t = 0; t < 2; t++) {
        int i = tid + t * 256;
        int row = i >> 2, c = i & 3;
        cp16(sb + row * 96 + c * 16, Bp + (size_t)row * K + c * 8);
    }
}

template <int ACT>
__global__ __launch_bounds__(256, 2) void k_gemm(
    const __half* __restrict__ A, const __half* __restrict__ Bt,
    const float* __restrict__ bias, __half* __restrict__ Out,
    int K, int Nout)
{
    extern __shared__ __half smh[];
    const int tid  = threadIdx.x;
    const int wid  = tid >> 5;
    const int lane = tid & 31;
    const int g = lane >> 2, t = lane & 3;
    const int wm = wid & 3, wn = wid >> 2;
    const int m0 = blockIdx.y * 128;
    const int n0 = blockIdx.x * 128;
    const int NC = K >> 5;

    uint32_t uA[3], uB[3];
#pragma unroll
    for (int s = 0; s < 3; s++) {
        uA[s] = smem_u32(smh + s * 6144);
        uB[s] = smem_u32(smh + 18432 + s * 6144);
    }

    float c[2][8][4] = {};
    const __half* Abase = A + (size_t)m0 * K;
    const __half* Bbase = Bt + (size_t)n0 * K;

    stage256(Abase, Bbase, K, uA[0], uB[0], tid);
    asm volatile("cp.async.commit_group;");
    stage256(Abase + 32, Bbase + 32, K, uA[1], uB[1], tid);
    asm volatile("cp.async.commit_group;");

    for (int cc = 0; cc < NC; cc++) {
        if (cc + 1 < NC) asm volatile("cp.async.wait_group 1;");
        else             asm volatile("cp.async.wait_group 0;");
        __syncthreads();
        if (cc + 2 < NC) {
            const int bs = (cc + 2) % 3;
            stage256(Abase + (cc + 2) * 32, Bbase + (cc + 2) * 32, K, uA[bs], uB[bs], tid);
            asm volatile("cp.async.commit_group;");
        }
        const int cur = cc % 3;
        const __half* a_s = smh + cur * 6144;
        const __half* b_s = smh + 18432 + cur * 6144;
#pragma unroll
        for (int s = 0; s < 2; s++) {
            uint2 va[2][2];
#pragma unroll
            for (int i = 0; i < 2; i++) {
                const int rb = (2 * wm + i) * 16;
                va[i][0] = *(const uint2*)&a_s[(rb + g)     * 48 + s * 16 + 4 * t];
                va[i][1] = *(const uint2*)&a_s[(rb + g + 8) * 48 + s * 16 + 4 * t];
            }
            uint2 vb[8];
#pragma unroll
            for (int j = 0; j < 8; j++) {
                const int n = (wn * 8 + j) * 8 + g;
                vb[j] = *(const uint2*)&b_s[n * 48 + s * 16 + 4 * t];
            }
#pragma unroll
            for (int i = 0; i < 2; i++)
#pragma unroll
                for (int j = 0; j < 8; j++)
                    mma16(c[i][j], va[i][0].x, va[i][1].x, va[i][0].y, va[i][1].y,
                          vb[j].x, vb[j].y);
        }
    }

    const bool do_phi = (ACT == 3) && (n0 < 512);
#pragma unroll
    for (int j = 0; j < 8; j++) {
        const int col = n0 + (wn * 8 + j) * 8 + t * 2;
        const float b0 = __ldg(&bias[col]);
        const float b1 = __ldg(&bias[col + 1]);
#pragma unroll
        for (int i = 0; i < 2; i++) {
            const int r0 = m0 + (2 * wm + i) * 16 + g;
            float v0 = c[i][j][0] + b0, v1 = c[i][j][1] + b1;
            float v2 = c[i][j][2] + b0, v3 = c[i][j][3] + b1;
            if (do_phi) {
                v0 = (v0 > 0.f) ? (v0 + 1.f) : expf(v0);
                v1 = (v1 > 0.f) ? (v1 + 1.f) : expf(v1);
                v2 = (v2 > 0.f) ? (v2 + 1.f) : expf(v2);
                v3 = (v3 > 0.f) ? (v3 + 1.f) : expf(v3);
            }
            __half2 h0 = __floats2half2_rn(v0, v1);
            __half2 h1 = __floats2half2_rn(v2, v3);
            *(__half2*)&Out[(size_t)r0 * Nout + col]       = h0;
            *(__half2*)&Out[(size_t)(r0 + 8) * Nout + col] = h1;
        }
    }
}

// ============================================================================
// fp16 GEMM (BN=256, 512 thr, 3-stage) + bias + residual + LayerNorm fused.
// Used for Wo + LN1.
// ============================================================================
#define LNPITCH 264

__global__ __launch_bounds__(512, 1) void k_gemm_ln(
    const __half* __restrict__ A, const __half* __restrict__ Bt,
    const float* __restrict__ bias, const float* __restrict__ res,
    const float* __restrict__ lg, const float* __restrict__ lb,
    float* __restrict__ o, __half* __restrict__ oh, int K)
{
    extern __shared__ __half smh[];
    const int tid  = threadIdx.x;
    const int wid  = tid >> 5;
    const int lane = tid & 31;
    const int g = lane >> 2, t = lane & 3;
    const int wm = wid & 3, wn = wid >> 2;
    const int m0 = blockIdx.x * 128;
    const int NC = K >> 5;

    uint32_t uA[3], uB[3];
#pragma unroll
    for (int s = 0; s < 3; s++) {
        uA[s] = smem_u32(smh + s * 6144);
        uB[s] = smem_u32(smh + 18432 + s * 12288);
    }

    float c[2][8][4] = {};
    const __half* Abase = A + (size_t)m0 * K;

    auto stage512 = [&](int chunk, int s) {
        const __half* Ap = Abase + chunk * 32;
        const __half* Bp = Bt + chunk * 32;
        {
            int row = tid >> 2, cc4 = tid & 3;
            cp16(uA[s] + row * 96 + cc4 * 16, Ap + (size_t)row * K + cc4 * 8);
        }
#pragma unroll
        for (int tt = 0; tt < 2; tt++) {
            int i = tid + tt * 512;
            int row = i >> 2, cc4 = i & 3;
            cp16(uB[s] + row * 96 + cc4 * 16, Bp + (size_t)row * K + cc4 * 8);
        }
    };

    stage512(0, 0);
    asm volatile("cp.async.commit_group;");
    stage512(1, 1);
    asm volatile("cp.async.commit_group;");

    for (int cc = 0; cc < NC; cc++) {
        if (cc + 1 < NC) asm volatile("cp.async.wait_group 1;");
        else             asm volatile("cp.async.wait_group 0;");
        __syncthreads();
        if (cc + 2 < NC) {
            stage512(cc + 2, (cc + 2) % 3);
            asm volatile("cp.async.commit_group;");
        }
        const int cur = cc % 3;
        const __half* a_s = smh + cur * 6144;
        const __half* b_s = smh + 18432 + cur * 12288;
#pragma unroll
        for (int s = 0; s < 2; s++) {
            uint2 va[2][2];
#pragma unroll
            for (int i = 0; i < 2; i++) {
                const int rb = (2 * wm + i) * 16;
                va[i][0] = *(const uint2*)&a_s[(rb + g)     * 48 + s * 16 + 4 * t];
                va[i][1] = *(const uint2*)&a_s[(rb + g + 8) * 48 + s * 16 + 4 * t];
            }
            uint2 vb[8];
#pragma unroll
            for (int j = 0; j < 8; j++)
                vb[j] = *(const uint2*)&b_s[(wn * 64 + j * 8 + g) * 48 + s * 16 + 4 * t];
#pragma unroll
            for (int i = 0; i < 2; i++)
#pragma unroll
                for (int j = 0; j < 8; j++)
                    mma16(c[i][j], va[i][0].x, va[i][1].x, va[i][0].y, va[i][1].y,
                          vb[j].x, vb[j].y);
        }
    }
    __syncthreads();

    float* se = (float*)smh;
#pragma unroll
    for (int j = 0; j < 8; j++) {
        const int col = wn * 64 + j * 8 + t * 2;
        const float b0 = __ldg(&bias[col]);
        const float b1 = __ldg(&bias[col + 1]);
#pragma unroll
        for (int i = 0; i < 2; i++) {
            const int r = (2 * wm + i) * 16 + g;
            *(float2*)&se[r * LNPITCH + col] = make_float2(c[i][j][0] + b0, c[i][j][1] + b1);
            *(float2*)&se[(r + 8) * LNPITCH + col] = make_float2(c[i][j][2] + b0, c[i][j][3] + b1);
        }
    }
    __syncthreads();

#pragma unroll
    for (int rr = 0; rr < 8; rr++) {
        const int row = wid * 8 + rr;
        const size_t rb = (size_t)(m0 + row) * D_;
        float vals[8];
        float sum = 0.f, sq = 0.f;
#pragma unroll
        for (int i = 0; i < 8; i++) {
            float v = se[row * LNPITCH + lane + i * 32] + res[rb + lane + i * 32];
            vals[i] = v; sum += v; sq += v * v;
        }
#pragma unroll
        for (int off = 16; off > 0; off >>= 1) {
            sum += __shfl_xor_sync(0xffffffffu, sum, off);
            sq  += __shfl_xor_sync(0xffffffffu, sq,  off);
        }
        float mu  = sum * (1.f / 256.f);
        float var = sq * (1.f / 256.f) - mu * mu;
        float rs  = rsqrtf(var + 1e-5f);
#pragma unroll
        for (int i = 0; i < 8; i++) {
            const int col = lane + i * 32;
            float v = (vals[i] - mu) * rs * lg[col] + lb[col];
            o[rb + col] = v;
            oh[rb + col] = __float2half(v);
        }
    }
}

// ============================================================================
// FUSED FFN: out = LN2( x1 + relu(x1h@W1^T + b1) @ W2^T + b2 )
// 512 thr, 128 tokens/CTA, 8 hidden slabs of 128; h lives only in smem.
// smem (halves): A stages 3x6144 @0 | B1 stages 3x6144 @18432 |
//                h 4x6144 @36864   | B2 stages 3x12288 @61440  (total 96K halves)
// ============================================================================
#define FA(s)  ((s) * 6144)
#define FB1(s) (18432 + (s) * 6144)
#define FH     36864
#define FB2(s) (61440 + (s) * 12288)

__global__ __launch_bounds__(512, 1) void k_ffn(
    const __half* __restrict__ A, const __half* __restrict__ W1t,
    const __half* __restrict__ W2t, const float* __restrict__ b1,
    const float* __restrict__ b2, const float* __restrict__ res,
    const float* __restrict__ lg, const float* __restrict__ lb,
    float* __restrict__ o)
{
    extern __shared__ __half smh[];
    const int tid  = threadIdx.x;
    const int wid  = tid >> 5;
    const int lane = tid & 31;
    const int g = lane >> 2, t = lane & 3;
    const int wm = wid & 3, wn = wid >> 2;     // 4m x 4n warps
    const int m0 = blockIdx.x * 128;

    const uint32_t base = smem_u32(smh);
    const __half* Abase = A + (size_t)m0 * D_;

    // phase-1 staging: A chunk (128x32) + B1 chunk (128x32), 1 cp16 each/thread
    auto stage1 = [&](int jc, int kc, int s) {
        int row = tid >> 2, c4 = tid & 3;
        cp16(base + (FA(s) + row * 48) * 2 + c4 * 16,
             Abase + (size_t)row * D_ + kc * 32 + c4 * 8);
        cp16(base + (FB1(s) + row * 48) * 2 + c4 * 16,
             W1t + (size_t)(jc * 128 + row) * D_ + kc * 32 + c4 * 8);
    };
    // phase-2 staging: B2 chunk (256x32), 2 cp16/thread
    auto stage2 = [&](int jc, int kc, int s) {
#pragma unroll
        for (int tt = 0; tt < 2; tt++) {
            int i = tid + tt * 512;
            int row = i >> 2, c4 = i & 3;
            cp16(base + (FB2(s) + row * 48) * 2 + c4 * 16,
                 W2t + (size_t)row * FF_ + jc * 128 + kc * 32 + c4 * 8);
        }
    };

    float c2[2][8][4] = {};   // persistent FFN2 accumulator

    for (int jc = 0; jc < 8; jc++) {
        // ---- phase 1: h[128,128] = relu(x1h @ W1 slab + b1) ----
        float c1[2][4][4] = {};
        stage1(jc, 0, 0);
        asm volatile("cp.async.commit_group;");
        stage1(jc, 1, 1);
        asm volatile("cp.async.commit_group;");
#pragma unroll 1
        for (int cc = 0; cc < 8; cc++) {
            if (cc + 1 < 8) asm volatile("cp.async.wait_group 1;");
            else            asm volatile("cp.async.wait_group 0;");
            __syncthreads();
            if (cc + 2 < 8) {
                stage1(jc, cc + 2, (cc + 2) % 3);
                asm volatile("cp.async.commit_group;");
            }
            const int cur = cc % 3;
            const __half* a_s = smh + FA(cur);
            const __half* b_s = smh + FB1(cur);
#pragma unroll
            for (int s = 0; s < 2; s++) {
                uint2 va[2][2];
#pragma unroll
                for (int i = 0; i < 2; i++) {
                    const int rb = (2 * wm + i) * 16;
                    va[i][0] = *(const uint2*)&a_s[(rb + g)     * 48 + s * 16 + 4 * t];
                    va[i][1] = *(const uint2*)&a_s[(rb + g + 8) * 48 + s * 16 + 4 * t];
                }
                uint2 vb[4];
#pragma unroll
                for (int j = 0; j < 4; j++)
                    vb[j] = *(const uint2*)&b_s[(wn * 32 + j * 8 + g) * 48 + s * 16 + 4 * t];
#pragma unroll
                for (int i = 0; i < 2; i++)
#pragma unroll
                    for (int j = 0; j < 4; j++)
                        mma16(c1[i][j], va[i][0].x, va[i][1].x, va[i][0].y, va[i][1].y,
                              vb[j].x, vb[j].y);
            }
        }

        // ---- h -> smem in A-staging layout (chunk = wn, pos = j*8+2t) ----
        __half* h_s = smh + FH + wn * 6144;
#pragma unroll
        for (int j = 0; j < 4; j++) {
            const int pos = j * 8 + 2 * t;
            const float bb0 = __ldg(&b1[jc * 128 + wn * 32 + pos]);
            const float bb1 = __ldg(&b1[jc * 128 + wn * 32 + pos + 1]);
#pragma unroll
            for (int i = 0; i < 2; i++) {
                const int r = (2 * wm + i) * 16 + g;
                __half2 h0 = __floats2half2_rn(fmaxf(c1[i][j][0] + bb0, 0.f),
                                               fmaxf(c1[i][j][1] + bb1, 0.f));
                __half2 h1 = __floats2half2_rn(fmaxf(c1[i][j][2] + bb0, 0.f),
                                               fmaxf(c1[i][j][3] + bb1, 0.f));
                *(__half2*)&h_s[r * 48 + pos]       = h0;
                *(__half2*)&h_s[(r + 8) * 48 + pos] = h1;
            }
        }

        // ---- phase 2: c2 += h @ W2 slab ----
        stage2(jc, 0, 0);
        asm volatile("cp.async.commit_group;");
        stage2(jc, 1, 1);
        asm volatile("cp.async.commit_group;");
#pragma unroll 1
        for (int cc = 0; cc < 4; cc++) {
            if (cc + 1 < 4) asm volatile("cp.async.wait_group 1;");
            else            asm volatile("cp.async.wait_group 0;");
            __syncthreads();      // iter 0: also publishes h to all warps
            if (cc + 2 < 4) {
                stage2(jc, cc + 2, (cc + 2) % 3);
                asm volatile("cp.async.commit_group;");
            }
            const __half* a_s = smh + FH + cc * 6144;
            const __half* b_s = smh + FB2(cc % 3);
#pragma unroll
            for (int s = 0; s < 2; s++) {
                uint2 va[2][2];
#pragma unroll
                for (int i = 0; i < 2; i++) {
                    const int rb = (2 * wm + i) * 16;
                    va[i][0] = *(const uint2*)&a_s[(rb + g)     * 48 + s * 16 + 4 * t];
                    va[i][1] = *(const uint2*)&a_s[(rb + g + 8) * 48 + s * 16 + 4 * t];
                }
                uint2 vb[8];
#pragma unroll
                for (int j = 0; j < 8; j++)
                    vb[j] = *(const uint2*)&b_s[(wn * 64 + j * 8 + g) * 48 + s * 16 + 4 * t];
#pragma unroll
                for (int i = 0; i < 2; i++)
#pragma unroll
                    for (int j = 0; j < 8; j++)
                        mma16(c2[i][j], va[i][0].x, va[i][1].x, va[i][0].y, va[i][1].y,
                              vb[j].x, vb[j].y);
            }
        }
        __syncthreads();   // all phase-2 reads of h done before next jc rewrites it
    }

    // ---- epilogue: c2 + b2 + residual + LN2 -> o ----
    float* se = (float*)smh;
#pragma unroll
    for (int j = 0; j < 8; j++) {
        const int col = wn * 64 + j * 8 + t * 2;
        const float bb0 = __ldg(&b2[col]);
        const float bb1 = __ldg(&b2[col + 1]);
#pragma unroll
        for (int i = 0; i < 2; i++) {
            const int r = (2 * wm + i) * 16 + g;
            *(float2*)&se[r * LNPITCH + col] = make_float2(c2[i][j][0] + bb0, c2[i][j][1] + bb1);
            *(float2*)&se[(r + 8) * LNPITCH + col] = make_float2(c2[i][j][2] + bb0, c2[i][j][3] + bb1);
        }
    }
    __syncthreads();

#pragma unroll
    for (int rr = 0; rr < 8; rr++) {
        const int row = wid * 8 + rr;
        const size_t rb = (size_t)(m0 + row) * D_;
        float vals[8];
        float sum = 0.f, sq = 0.f;
#pragma unroll
        for (int i = 0; i < 8; i++) {
            float v = se[row * LNPITCH + lane + i * 32] + res[rb + lane + i * 32];
            vals[i] = v; sum += v; sq += v * v;
        }
#pragma unroll
        for (int off = 16; off > 0; off >>= 1) {
            sum += __shfl_xor_sync(0xffffffffu, sum, off);
            sq  += __shfl_xor_sync(0xffffffffu, sq,  off);
        }
        float mu  = sum * (1.f / 256.f);
        float var = sq * (1.f / 256.f) - mu * mu;
        float rs  = rsqrtf(var + 1e-5f);
#pragma unroll
        for (int i = 0; i < 8; i++) {
            const int col = lane + i * 32;
            o[rb + col] = (vals[i] - mu) * rs * lg[col] + lb[col];
        }
    }
}

// ============================================================================
// kv reduction via tensor cores (unchanged from R9)
// ============================================================================
__global__ __launch_bounds__(256) void k_kvred()
{
    extern __shared__ __half sred[];
    const int bh = blockIdx.x;
    const int b = bh >> 3, h = bh & 7;
    const int ch = blockIdx.y;
    const int w = threadIdx.x >> 5, lane = threadIdx.x & 31;
    const int g = lane >> 2, t = lane & 3;

    __half* k_s = sred + w * 5120;
    const uint32_t uk = smem_u32(k_s);
    const uint32_t uv = uk + 2560 * 2;

    const int tok0 = ch * CHTOK + w * 64;
    const __half* kg = g_qkvh + ((size_t)b * L_ + tok0) * 768 + 256 + h * 32;
    const __half* vg = kg + 256;

#pragma unroll
    for (int it = 0; it < 8; it++) {
        int i = lane + it * 32;
        int tok = i >> 2, c4 = i & 3;
        cp16(uk + tok * 80 + c4 * 16, kg + (size_t)tok * 768 + c4 * 8);
        cp16(uv + tok * 80 + c4 * 16, vg + (size_t)tok * 768 + c4 * 8);
    }
    asm volatile("cp.async.commit_group;");
    asm volatile("cp.async.wait_group 0;");
    __syncwarp();

    float acc[2][4][4] = {};
    float cs[2][4] = {};
    const uint32_t ones2 = 0x3C003C00u;

    const int tokA = (lane & 7) + ((lane >> 4) << 3);
    const int dA   = ((lane >> 3) & 1) * 8;
    const int tokB = (lane & 7) + (((lane >> 3) & 1) << 3);
    const int eB   = ((lane >> 4) & 1) * 8;

#pragma unroll
    for (int st = 0; st < 64; st += 16) {
        uint32_t a[2][4], bb[2][4];
#pragma unroll
        for (int mi = 0; mi < 2; mi++)
            LDMX4T(a[mi], uk + (st + tokA) * 80 + (mi * 16 + dA) * 2);
#pragma unroll
        for (int np = 0; np < 2; np++)
            LDMX4T(bb[np], uv + (st + tokB) * 80 + (np * 16 + eB) * 2);
#pragma unroll
        for (int mi = 0; mi < 2; mi++) {
#pragma unroll
            for (int nb = 0; nb < 4; nb++) {
                const int np = nb >> 1, hi = nb & 1;
                mma16(acc[mi][nb], a[mi][0], a[mi][1], a[mi][2], a[mi][3],
                      bb[np][hi * 2], bb[np][hi * 2 + 1]);
            }
            mma16(cs[mi], a[mi][0], a[mi][1], a[mi][2], a[mi][3], ones2, ones2);
        }
    }
    __syncthreads();

    float* s_part = (float*)sred;
    float* s_ksp  = s_part + 8 * 1024;
#pragma unroll
    for (int mi = 0; mi < 2; mi++) {
#pragma unroll
        for (int nb = 0; nb < 4; nb++) {
            const int d0 = mi * 16 + g, e0 = nb * 8 + 2 * t;
            *(float2*)&s_part[w * 1024 + d0 * 32 + e0] =
                make_float2(acc[mi][nb][0], acc[mi][nb][1]);
            *(float2*)&s_part[w * 1024 + (d0 + 8) * 32 + e0] =
                make_float2(acc[mi][nb][2], acc[mi][nb][3]);
        }
        if (t == 0) {
            s_ksp[w * 32 + mi * 16 + g]     = cs[mi][0];
            s_ksp[w * 32 + mi * 16 + g + 8] = cs[mi][2];
        }
    }
    __syncthreads();

    const int tid = threadIdx.x;
    for (int j = tid; j < 1024; j += 256) {
        float s = 0.f;
#pragma unroll
        for (int ww = 0; ww < 8; ww++) s += s_part[ww * 1024 + j];
        g_kvpart[((size_t)ch * 32 + bh) * 1024 + j] = s;
    }
    if (tid < 32) {
        float s = 0.f;
#pragma unroll
        for (int ww = 0; ww < 8; ww++) s += s_ksp[ww * 32 + tid];
        g_kspart[(ch * 32 + bh) * 32 + tid] = s;
    }
}

__global__ __launch_bounds__(256) void k_kvfin()
{
    const int bh = blockIdx.x;
    for (int j = threadIdx.x; j < 1024; j += 256) {
        float s = 0.f;
#pragma unroll
        for (int c = 0; c < NCH; c++) s += g_kvpart[((size_t)c * 32 + bh) * 1024 + j];
        g_kv[bh * 1024 + j] = s;
    }
    if (threadIdx.x < 32) {
        float s = 0.f;
#pragma unroll
        for (int c = 0; c < NCH; c++) s += g_kspart[(c * 32 + bh) * 32 + threadIdx.x];
        g_ksum[bh * 32 + threadIdx.x] = s;
    }
}

// ============================================================================
// attention readout (unchanged)
// ============================================================================
__global__ __launch_bounds__(256) void k_attnread(__half* __restrict__ outa)
{
    extern __shared__ float smr[];
    float* s_kv = smr;
    float* s_ks = smr + 8192;
    float* s_z  = smr + 8448;
    float* s_q  = smr + 8704;

    const int tid  = threadIdx.x;
    const int tok0 = blockIdx.x * 32;
    const int b    = tok0 >> 14;

    for (int i = tid; i < 2048; i += 256)
        *(float4*)&s_kv[i * 4] = *(const float4*)&g_kv[b * 8192 + i * 4];
    if (tid < 64)
        *(float4*)&s_ks[tid * 4] = *(const float4*)&g_ksum[b * 256 + tid * 4];
    for (int i = tid; i < 2048; i += 256) {
        int row = i >> 6, c = i & 63;
        uint2 u = *(const uint2*)&g_qkvh[(size_t)(tok0 + row) * 768 + c * 4];
        float2 f0 = __half22float2(*(__half2*)&u.x);
        float2 f1 = __half22float2(*(__half2*)&u.y);
        *(float4*)&s_q[row * 256 + c * 4] = make_float4(f0.x, f0.y, f1.x, f1.y);
    }
    __syncthreads();

    {
        int r = tid & 31, h = tid >> 5;
        float s = 0.f;
#pragma unroll
        for (int d4 = 0; d4 < 8; d4++) {
            float4 q4 = *(float4*)&s_q[r * 256 + h * 32 + d4 * 4];
            float4 k4 = *(float4*)&s_ks[h * 32 + d4 * 4];
            s += q4.x * k4.x + q4.y * k4.y + q4.z * k4.z + q4.w * k4.w;
        }
        s_z[r * 8 + h] = 1.f / (s + 1e-6f);
    }
    __syncthreads();

    {
        int h = tid >> 5, e = tid & 31;
        float kvc[32];
#pragma unroll
        for (int d = 0; d < 32; d++) kvc[d] = s_kv[(h * 32 + d) * 32 + e];
        for (int r = 0; r < 32; r++) {
            float acc = 0.f;
#pragma unroll
            for (int d4 = 0; d4 < 8; d4++) {
                float4 q4 = *(float4*)&s_q[r * 256 + h * 32 + d4 * 4];
                acc += q4.x * kvc[d4 * 4] + q4.y * kvc[d4 * 4 + 1]
                     + q4.z * kvc[d4 * 4 + 2] + q4.w * kvc[d4 * 4 + 3];
            }
            outa[(size_t)(tok0 + r) * D_ + tid] = __float2half(acc * s_z[r * 8 + h]);
        }
    }
}

// ============================================================================
extern "C" void kernel_launch(void* const* d_in, const int* in_sizes, int n_in,
                              void* d_out, int out_size)
{
    const float* x    = (const float*)d_in[0];
    const float* Wq   = (const float*)d_in[1];
    const float* bq   = (const float*)d_in[2];
    const float* Wk   = (const float*)d_in[3];
    const float* bk   = (const float*)d_in[4];
    const float* Wv   = (const float*)d_in[5];
    const float* bv   = (const float*)d_in[6];
    const float* Wo   = (const float*)d_in[7];
    const float* bo   = (const float*)d_in[8];
    const float* W1   = (const float*)d_in[9];
    const float* b1   = (const float*)d_in[10];
    const float* W2   = (const float*)d_in[11];
    const float* b2   = (const float*)d_in[12];
    const float* ln1g = (const float*)d_in[13];
    const float* ln1b = (const float*)d_in[14];
    const float* ln2g = (const float*)d_in[15];
    const float* ln2b = (const float*)d_in[16];
    float* out = (float*)d_out;

    __half *xh, *qkvh, *ah, *x1h, *wqkvT, *woT, *w1T, *w2T;
    float *x1, *bqkv;
    cudaGetSymbolAddress((void**)&xh,    g_xh);
    cudaGetSymbolAddress((void**)&qkvh,  g_qkvh);
    cudaGetSymbolAddress((void**)&ah,    g_ah);
    cudaGetSymbolAddress((void**)&x1,    g_x1);
    cudaGetSymbolAddress((void**)&x1h,   g_x1h);
    cudaGetSymbolAddress((void**)&wqkvT, g_wqkvT);
    cudaGetSymbolAddress((void**)&woT,   g_woT);
    cudaGetSymbolAddress((void**)&w1T,   g_w1T);
    cudaGetSymbolAddress((void**)&w2T,   g_w2T);
    cudaGetSymbolAddress((void**)&bqkv,  g_bqkv);

    const int GSM   = 73728;
    const int GSMLN = 128 * LNPITCH * 4;          // 135168
    const int GSMFF = 98304 * 2;                  // 196608
    const int GSMKV = 8 * 5120 * 2;               // 81920
    cudaFuncSetAttribute((k_gemm<3>), cudaFuncAttributeMaxDynamicSharedMemorySize, GSM);
    cudaFuncSetAttribute(k_gemm_ln, cudaFuncAttributeMaxDynamicSharedMemorySize, GSMLN);
    cudaFuncSetAttribute(k_ffn, cudaFuncAttributeMaxDynamicSharedMemorySize, GSMFF);
    cudaFuncSetAttribute(k_kvred, cudaFuncAttributeMaxDynamicSharedMemorySize, GSMKV);
    cudaFuncSetAttribute(k_attnread, cudaFuncAttributeMaxDynamicSharedMemorySize, 67584);

    k_cvtx<<<MTOK * D_ / 4 / 512, 512>>>(x);
    k_trall<<<769, dim3(32, 8)>>>(Wq, Wk, Wv, Wo, W1, W2, bq, bk, bv);

    // merged QKV projection (phi fused for q,k cols), half out
    k_gemm<3><<<dim3(6, 512), 256, GSM>>>(xh, wqkvT, bqkv, qkvh, D_, 768);

    k_kvred<<<dim3(32, NCH), 256, GSMKV>>>();
    k_kvfin<<<32, 256>>>();
    k_attnread<<<MTOK / 32, 256, 67584>>>(ah);

    // Wo projection + residual + LN1 (fused) -> x1 (f32) + x1h (half)
    k_gemm_ln<<<512, 512, GSMLN>>>(ah, woT, bo, x, ln1g, ln1b, x1, x1h, D_);

    // fused FFN + residual + LN2 -> out  (hidden never hits HBM)
    k_ffn<<<512, 512, GSMFF>>>(x1h, w1T, w2T, b1, b2, x1, ln2g, ln2b, out);
}

// round 11
// speedup vs baseline: 1.0595x; 1.0595x over previous
#include <cuda_runtime.h>
#include <cuda_fp16.h>
#include <math.h>
#include <stdint.h>

#define B_    4
#define L_    16384
#define D_    256
#define H_    8
#define DH_   32
#define FF_   1024
#define MTOK  65536
#define NCH   32
#define CHTOK 512

// ---------------- scratch ----------------
__device__ __half g_xh  [MTOK * D_];     // x as half
__device__ __half g_qh  [MTOK * D_];     // q_phi, [tok][256]
__device__ __half g_kh  [MTOK * D_];     // k_phi, [(b*8+h)][L][32]
__device__ __half g_vh  [MTOK * D_];     // v,     [(b*8+h)][L][32]
__device__ __half g_ah  [MTOK * D_];     // attn readout (half)
__device__ float  g_x1  [MTOK * D_];     // LN1 out (f32, residual for LN2)
__device__ __half g_x1h [MTOK * D_];     // LN1 out (half, FFN1 A)
__device__ __half g_hh  [MTOK * FF_];    // ffn hidden (half)
__device__ float  g_kvpart[NCH * 32 * 1024];
__device__ float  g_kspart[NCH * 32 * 32];
__device__ float  g_kv[32 * 1024];
__device__ float  g_ksum[32 * 32];
// transposed weights [N,K] row-major, half
__device__ __half g_wqkvT[768 * D_];
__device__ __half g_woT[D_ * D_];
__device__ __half g_w1T[FF_ * D_];
__device__ __half g_w2T[D_ * FF_];
__device__ float  g_bqkv[768];

// ---------------- helpers ----------------
__device__ __forceinline__ uint32_t smem_u32(const void* p) {
    uint32_t a;
    asm("{ .reg .u64 t; cvta.to.shared.u64 t, %1; cvt.u32.u64 %0, t; }" : "=r"(a) : "l"(p));
    return a;
}
__device__ __forceinline__ void cp16(uint32_t dst, const void* src) {
    asm volatile("cp.async.cg.shared.global [%0], [%1], 16;" :: "r"(dst), "l"(src));
}
__device__ __forceinline__ void mma16(float* c, uint32_t a0, uint32_t a1,
                                      uint32_t a2, uint32_t a3,
                                      uint32_t b0, uint32_t b1) {
    asm volatile("mma.sync.aligned.m16n8k16.row.col.f32.f16.f16.f32 "
        "{%0,%1,%2,%3}, {%4,%5,%6,%7}, {%8,%9}, {%0,%1,%2,%3};"
        : "+f"(c[0]), "+f"(c[1]), "+f"(c[2]), "+f"(c[3])
        : "r"(a0), "r"(a1), "r"(a2), "r"(a3), "r"(b0), "r"(b1));
}
#define LDMX4T(r, addr) \
    asm volatile("ldmatrix.sync.aligned.m8n8.x4.trans.shared.b16 {%0,%1,%2,%3}, [%4];" \
        : "=r"((r)[0]), "=r"((r)[1]), "=r"((r)[2]), "=r"((r)[3]) : "r"(addr))

// ============================================================================
// x -> half copy
// ============================================================================
__global__ __launch_bounds__(512) void k_cvtx(const float* __restrict__ x)
{
    int i = blockIdx.x * 512 + threadIdx.x;
    float4 v = *(const float4*)&x[(size_t)i * 4];
    __half2 h0 = __floats2half2_rn(v.x, v.y);
    __half2 h1 = __floats2half2_rn(v.z, v.w);
    *(uint2*)&g_xh[(size_t)i * 4] = make_uint2(*(uint32_t*)&h0, *(uint32_t*)&h1);
}

// ============================================================================
// ALL weight transposes + bias concat in ONE launch.
// ============================================================================
__global__ void k_trall(const float* __restrict__ Wq, const float* __restrict__ Wk,
                        const float* __restrict__ Wv, const float* __restrict__ Wo,
                        const float* __restrict__ W1, const float* __restrict__ W2,
                        const float* __restrict__ bq, const float* __restrict__ bk,
                        const float* __restrict__ bv)
{
    const int bid = blockIdx.x;
    if (bid == 768) {
        int t = threadIdx.y * 32 + threadIdx.x;
        g_bqkv[t] = bq[t]; g_bqkv[256 + t] = bk[t]; g_bqkv[512 + t] = bv[t];
        return;
    }
    const float* W; __half* Wt; int K, N, idx;
    if (bid < 256) {
        idx = bid & 63; K = D_; N = D_;
        int sel = bid >> 6;
        W  = (sel == 0) ? Wq : (sel == 1) ? Wk : (sel == 2) ? Wv : Wo;
        Wt = (sel == 0) ? g_wqkvT : (sel == 1) ? g_wqkvT + 256 * D_
           : (sel == 2) ? g_wqkvT + 512 * D_ : g_woT;
    } else if (bid < 512) {
        idx = bid - 256; K = D_; N = FF_; W = W1; Wt = g_w1T;
    } else {
        idx = bid - 512; K = FF_; N = D_; W = W2; Wt = g_w2T;
    }
    const int xt = N >> 5;
    const int n0 = (idx % xt) * 32, k0 = (idx / xt) * 32;

    __shared__ float t[32][33];
    int x = threadIdx.x, y = threadIdx.y;
    for (int i = y; i < 32; i += 8) t[i][x] = W[(size_t)(k0 + i) * N + n0 + x];
    __syncthreads();
    for (int i = y; i < 32; i += 8)
        Wt[(size_t)(n0 + i) * K + k0 + x] = __float2half(t[x][i]);
}

// ============================================================================
// fp16 mma.sync GEMM (BN=128, 256 thr, 3-stage).
// ACT: 2 relu -> Out (g_hh) | 3 QKV: phi for q,k, head-major scatter to
//      g_qh / g_kh / g_vh (Out unused).
// ============================================================================
__device__ __forceinline__ void stage256(const __half* __restrict__ Ap,
                                         const __half* __restrict__ Bp,
                                         int K, uint32_t sa, uint32_t sb, int tid)
{
#pragma unroll
    for (int t = 0; t < 2; t++) {
        int i = tid + t * 256;
        int row = i >> 2, c = i & 3;
        cp16(sa + row * 96 + c * 16, Ap + (size_t)row * K + c * 8);
    }
#pragma unroll
    for (int t = 0; t < 2; t++) {
        int i = tid + t * 256;
        int row = i >> 2, c = i & 3;
        cp16(sb + row * 96 + c * 16, Bp + (size_t)row * K + c * 8);
    }
}

template <int ACT>
__global__ __launch_bounds__(256, 2) void k_gemm(
    const __half* __restrict__ A, const __half* __restrict__ Bt,
    const float* __restrict__ bias, __half* __restrict__ Out,
    int K, int Nout)
{
    extern __shared__ __half smh[];
    const int tid  = threadIdx.x;
    const int wid  = tid >> 5;
    const int lane = tid & 31;
    const int g = lane >> 2, t = lane & 3;
    const int wm = wid & 3, wn = wid >> 2;
    const int m0 = blockIdx.y * 128;
    const int n0 = blockIdx.x * 128;
    const int NC = K >> 5;

    uint32_t uA[3], uB[3];
#pragma unroll
    for (int s = 0; s < 3; s++) {
        uA[s] = smem_u32(smh + s * 6144);
        uB[s] = smem_u32(smh + 18432 + s * 6144);
    }

    float c[2][8][4] = {};
    const __half* Abase = A + (size_t)m0 * K;
    const __half* Bbase = Bt + (size_t)n0 * K;

    stage256(Abase, Bbase, K, uA[0], uB[0], tid);
    asm volatile("cp.async.commit_group;");
    stage256(Abase + 32, Bbase + 32, K, uA[1], uB[1], tid);
    asm volatile("cp.async.commit_group;");

    for (int cc = 0; cc < NC; cc++) {
        if (cc + 1 < NC) asm volatile("cp.async.wait_group 1;");
        else             asm volatile("cp.async.wait_group 0;");
        __syncthreads();
        if (cc + 2 < NC) {
            const int bs = (cc + 2) % 3;
            stage256(Abase + (cc + 2) * 32, Bbase + (cc + 2) * 32, K, uA[bs], uB[bs], tid);
            asm volatile("cp.async.commit_group;");
        }
        const int cur = cc % 3;
        const __half* a_s = smh + cur * 6144;
        const __half* b_s = smh + 18432 + cur * 6144;
#pragma unroll
        for (int s = 0; s < 2; s++) {
            uint2 va[2][2];
#pragma unroll
            for (int i = 0; i < 2; i++) {
                const int rb = (2 * wm + i) * 16;
                va[i][0] = *(const uint2*)&a_s[(rb + g)     * 48 + s * 16 + 4 * t];
                va[i][1] = *(const uint2*)&a_s[(rb + g + 8) * 48 + s * 16 + 4 * t];
            }
            uint2 vb[8];
#pragma unroll
            for (int j = 0; j < 8; j++) {
                const int n = (wn * 8 + j) * 8 + g;
                vb[j] = *(const uint2*)&b_s[n * 48 + s * 16 + 4 * t];
            }
#pragma unroll
            for (int i = 0; i < 2; i++)
#pragma unroll
                for (int j = 0; j < 8; j++)
                    mma16(c[i][j], va[i][0].x, va[i][1].x, va[i][0].y, va[i][1].y,
                          vb[j].x, vb[j].y);
        }
    }

    const bool do_phi = (ACT == 3) && (n0 < 512);
#pragma unroll
    for (int j = 0; j < 8; j++) {
        const int col = n0 + (wn * 8 + j) * 8 + t * 2;
        const float b0 = __ldg(&bias[col]);
        const float b1 = __ldg(&bias[col + 1]);
#pragma unroll
        for (int i = 0; i < 2; i++) {
            const int r0 = m0 + (2 * wm + i) * 16 + g;
            float v0 = c[i][j][0] + b0, v1 = c[i][j][1] + b1;
            float v2 = c[i][j][2] + b0, v3 = c[i][j][3] + b1;
            if (do_phi) {
                v0 = (v0 > 0.f) ? (v0 + 1.f) : expf(v0);
                v1 = (v1 > 0.f) ? (v1 + 1.f) : expf(v1);
                v2 = (v2 > 0.f) ? (v2 + 1.f) : expf(v2);
                v3 = (v3 > 0.f) ? (v3 + 1.f) : expf(v3);
            }
            if (ACT == 2) {
                v0 = fmaxf(v0, 0.f); v1 = fmaxf(v1, 0.f);
                v2 = fmaxf(v2, 0.f); v3 = fmaxf(v3, 0.f);
            }
            __half2 h0 = __floats2half2_rn(v0, v1);
            __half2 h1 = __floats2half2_rn(v2, v3);
            if (ACT == 3) {
                if (n0 < 256) {
                    // q: [tok][256]
                    *(__half2*)&g_qh[(size_t)r0 * D_ + col]       = h0;
                    *(__half2*)&g_qh[(size_t)(r0 + 8) * D_ + col] = h1;
                } else {
                    // k / v: [(b*8+head)][L][32]
                    __half* dst = (n0 < 512) ? g_kh : g_vh;
                    const int colr = col & 255;
                    const int head = colr >> 5, e = colr & 31;
                    const int b = r0 >> 14, l = r0 & (L_ - 1);
                    const size_t base0 = ((size_t)(b * 8 + head) * L_ + l) * 32 + e;
                    *(__half2*)&dst[base0]          = h0;
                    *(__half2*)&dst[base0 + 8 * 32] = h1;   // l+8 (same 128-block)
                }
            } else {
                *(__half2*)&Out[(size_t)r0 * Nout + col]       = h0;
                *(__half2*)&Out[(size_t)(r0 + 8) * Nout + col] = h1;
            }
        }
    }
}

// ============================================================================
// fp16 GEMM (BN=256, 512 thr, 3-stage) + bias + residual + LayerNorm fused.
// FINAL=0: writes o (f32) and oh (half).  FINAL=1: o only.
// ============================================================================
#define LNPITCH 264

template <int FINAL>
__global__ __launch_bounds__(512, 1) void k_gemm_ln(
    const __half* __restrict__ A, const __half* __restrict__ Bt,
    const float* __restrict__ bias, const float* __restrict__ res,
    const float* __restrict__ lg, const float* __restrict__ lb,
    float* __restrict__ o, __half* __restrict__ oh, int K)
{
    extern __shared__ __half smh[];
    const int tid  = threadIdx.x;
    const int wid  = tid >> 5;
    const int lane = tid & 31;
    const int g = lane >> 2, t = lane & 3;
    const int wm = wid & 3, wn = wid >> 2;
    const int m0 = blockIdx.x * 128;
    const int NC = K >> 5;

    uint32_t uA[3], uB[3];
#pragma unroll
    for (int s = 0; s < 3; s++) {
        uA[s] = smem_u32(smh + s * 6144);
        uB[s] = smem_u32(smh + 18432 + s * 12288);
    }

    float c[2][8][4] = {};
    const __half* Abase = A + (size_t)m0 * K;

    auto stage512 = [&](int chunk, int s) {
        const __half* Ap = Abase + chunk * 32;
        const __half* Bp = Bt + chunk * 32;
        {
            int row = tid >> 2, cc4 = tid & 3;
            cp16(uA[s] + row * 96 + cc4 * 16, Ap + (size_t)row * K + cc4 * 8);
        }
#pragma unroll
        for (int tt = 0; tt < 2; tt++) {
            int i = tid + tt * 512;
            int row = i >> 2, cc4 = i & 3;
            cp16(uB[s] + row * 96 + cc4 * 16, Bp + (size_t)row * K + cc4 * 8);
        }
    };

    stage512(0, 0);
    asm volatile("cp.async.commit_group;");
    stage512(1, 1);
    asm volatile("cp.async.commit_group;");

    for (int cc = 0; cc < NC; cc++) {
        if (cc + 1 < NC) asm volatile("cp.async.wait_group 1;");
        else             asm volatile("cp.async.wait_group 0;");
        __syncthreads();
        if (cc + 2 < NC) {
            stage512(cc + 2, (cc + 2) % 3);
            asm volatile("cp.async.commit_group;");
        }
        const int cur = cc % 3;
        const __half* a_s = smh + cur * 6144;
        const __half* b_s = smh + 18432 + cur * 12288;
#pragma unroll
        for (int s = 0; s < 2; s++) {
            uint2 va[2][2];
#pragma unroll
            for (int i = 0; i < 2; i++) {
                const int rb = (2 * wm + i) * 16;
                va[i][0] = *(const uint2*)&a_s[(rb + g)     * 48 + s * 16 + 4 * t];
                va[i][1] = *(const uint2*)&a_s[(rb + g + 8) * 48 + s * 16 + 4 * t];
            }
            uint2 vb[8];
#pragma unroll
            for (int j = 0; j < 8; j++)
                vb[j] = *(const uint2*)&b_s[(wn * 64 + j * 8 + g) * 48 + s * 16 + 4 * t];
#pragma unroll
            for (int i = 0; i < 2; i++)
#pragma unroll
                for (int j = 0; j < 8; j++)
                    mma16(c[i][j], va[i][0].x, va[i][1].x, va[i][0].y, va[i][1].y,
                          vb[j].x, vb[j].y);
        }
    }
    __syncthreads();

    float* se = (float*)smh;
#pragma unroll
    for (int j = 0; j < 8; j++) {
        const int col = wn * 64 + j * 8 + t * 2;
        const float b0 = __ldg(&bias[col]);
        const float b1 = __ldg(&bias[col + 1]);
#pragma unroll
        for (int i = 0; i < 2; i++) {
            const int r = (2 * wm + i) * 16 + g;
            *(float2*)&se[r * LNPITCH + col] = make_float2(c[i][j][0] + b0, c[i][j][1] + b1);
            *(float2*)&se[(r + 8) * LNPITCH + col] = make_float2(c[i][j][2] + b0, c[i][j][3] + b1);
        }
    }
    __syncthreads();

#pragma unroll
    for (int rr = 0; rr < 8; rr++) {
        const int row = wid * 8 + rr;
        const size_t rb = (size_t)(m0 + row) * D_;
        float vals[8];
        float sum = 0.f, sq = 0.f;
#pragma unroll
        for (int i = 0; i < 8; i++) {
            float v = se[row * LNPITCH + lane + i * 32] + res[rb + lane + i * 32];
            vals[i] = v; sum += v; sq += v * v;
        }
#pragma unroll
        for (int off = 16; off > 0; off >>= 1) {
            sum += __shfl_xor_sync(0xffffffffu, sum, off);
            sq  += __shfl_xor_sync(0xffffffffu, sq,  off);
        }
        float mu  = sum * (1.f / 256.f);
        float var = sq * (1.f / 256.f) - mu * mu;
        float rs  = rsqrtf(var + 1e-5f);
#pragma unroll
        for (int i = 0; i < 8; i++) {
            const int col = lane + i * 32;
            float v = (vals[i] - mu) * rs * lg[col] + lb[col];
            o[rb + col] = v;
            if (!FINAL) oh[rb + col] = __float2half(v);
        }
    }
}

// ============================================================================
// kv reduction via tensor cores; k/v now DENSE head-major [(bh)][L][32].
// ============================================================================
__global__ __launch_bounds__(256) void k_kvred()
{
    extern __shared__ __half sred[];
    const int bh = blockIdx.x;
    const int ch = blockIdx.y;
    const int w = threadIdx.x >> 5, lane = threadIdx.x & 31;
    const int g = lane >> 2, t = lane & 3;

    __half* k_s = sred + w * 5120;
    const uint32_t uk = smem_u32(k_s);
    const uint32_t uv = uk + 2560 * 2;

    const int tok0 = ch * CHTOK + w * 64;
    const __half* kg = g_kh + ((size_t)bh * L_ + tok0) * 32;
    const __half* vg = g_vh + ((size_t)bh * L_ + tok0) * 32;

#pragma unroll
    for (int it = 0; it < 8; it++) {
        int i = lane + it * 32;            // 256 x 16B = 64 tokens x 64B, dense
        int tok = i >> 2, c4 = i & 3;
        cp16(uk + tok * 80 + c4 * 16, kg + (size_t)i * 8);
        cp16(uv + tok * 80 + c4 * 16, vg + (size_t)i * 8);
    }
    asm volatile("cp.async.commit_group;");
    asm volatile("cp.async.wait_group 0;");
    __syncwarp();

    float acc[2][4][4] = {};
    float cs[2][4] = {};
    const uint32_t ones2 = 0x3C003C00u;

    const int tokA = (lane & 7) + ((lane >> 4) << 3);
    const int dA   = ((lane >> 3) & 1) * 8;
    const int tokB = (lane & 7) + (((lane >> 3) & 1) << 3);
    const int eB   = ((lane >> 4) & 1) * 8;

#pragma unroll
    for (int st = 0; st < 64; st += 16) {
        uint32_t a[2][4], bb[2][4];
#pragma unroll
        for (int mi = 0; mi < 2; mi++)
            LDMX4T(a[mi], uk + (st + tokA) * 80 + (mi * 16 + dA) * 2);
#pragma unroll
        for (int np = 0; np < 2; np++)
            LDMX4T(bb[np], uv + (st + tokB) * 80 + (np * 16 + eB) * 2);
#pragma unroll
        for (int mi = 0; mi < 2; mi++) {
#pragma unroll
            for (int nb = 0; nb < 4; nb++) {
                const int np = nb >> 1, hi = nb & 1;
                mma16(acc[mi][nb], a[mi][0], a[mi][1], a[mi][2], a[mi][3],
                      bb[np][hi * 2], bb[np][hi * 2 + 1]);
            }
            mma16(cs[mi], a[mi][0], a[mi][1], a[mi][2], a[mi][3], ones2, ones2);
        }
    }
    __syncthreads();

    float* s_part = (float*)sred;
    float* s_ksp  = s_part + 8 * 1024;
#pragma unroll
    for (int mi = 0; mi < 2; mi++) {
#pragma unroll
        for (int nb = 0; nb < 4; nb++) {
            const int d0 = mi * 16 + g, e0 = nb * 8 + 2 * t;
            *(float2*)&s_part[w * 1024 + d0 * 32 + e0] =
                make_float2(acc[mi][nb][0], acc[mi][nb][1]);
            *(float2*)&s_part[w * 1024 + (d0 + 8) * 32 + e0] =
                make_float2(acc[mi][nb][2], acc[mi][nb][3]);
        }
        if (t == 0) {
            s_ksp[w * 32 + mi * 16 + g]     = cs[mi][0];
            s_ksp[w * 32 + mi * 16 + g + 8] = cs[mi][2];
        }
    }
    __syncthreads();

    const int tid = threadIdx.x;
    for (int j = tid; j < 1024; j += 256) {
        float s = 0.f;
#pragma unroll
        for (int ww = 0; ww < 8; ww++) s += s_part[ww * 1024 + j];
        g_kvpart[((size_t)ch * 32 + bh) * 1024 + j] = s;
    }
    if (tid < 32) {
        float s = 0.f;
#pragma unroll
        for (int ww = 0; ww < 8; ww++) s += s_ksp[ww * 32 + tid];
        g_kspart[(ch * 32 + bh) * 32 + tid] = s;
    }
}

__global__ __launch_bounds__(256) void k_kvfin()
{
    const int bh = blockIdx.x;
    for (int j = threadIdx.x; j < 1024; j += 256) {
        float s = 0.f;
#pragma unroll
        for (int c = 0; c < NCH; c++) s += g_kvpart[((size_t)c * 32 + bh) * 1024 + j];
        g_kv[bh * 1024 + j] = s;
    }
    if (threadIdx.x < 32) {
        float s = 0.f;
#pragma unroll
        for (int c = 0; c < NCH; c++) s += g_kspart[(c * 32 + bh) * 32 + threadIdx.x];
        g_ksum[bh * 32 + threadIdx.x] = s;
    }
}

// ============================================================================
// attention readout (q from dense g_qh); output half
// ============================================================================
__global__ __launch_bounds__(256) void k_attnread(__half* __restrict__ outa)
{
    extern __shared__ float smr[];
    float* s_kv = smr;
    float* s_ks = smr + 8192;
    float* s_z  = smr + 8448;
    float* s_q  = smr + 8704;

    const int tid  = threadIdx.x;
    const int tok0 = blockIdx.x * 32;
    const int b    = tok0 >> 14;

    for (int i = tid; i < 2048; i += 256)
        *(float4*)&s_kv[i * 4] = *(const float4*)&g_kv[b * 8192 + i * 4];
    if (tid < 64)
        *(float4*)&s_ks[tid * 4] = *(const float4*)&g_ksum[b * 256 + tid * 4];
    for (int i = tid; i < 2048; i += 256) {
        uint2 u = *(const uint2*)&g_qh[(size_t)tok0 * D_ + i * 4];
        float2 f0 = __half22float2(*(__half2*)&u.x);
        float2 f1 = __half22float2(*(__half2*)&u.y);
        *(float4*)&s_q[i * 4] = make_float4(f0.x, f0.y, f1.x, f1.y);
    }
    __syncthreads();

    {
        int r = tid & 31, h = tid >> 5;
        float s = 0.f;
#pragma unroll
        for (int d4 = 0; d4 < 8; d4++) {
            float4 q4 = *(float4*)&s_q[r * 256 + h * 32 + d4 * 4];
            float4 k4 = *(float4*)&s_ks[h * 32 + d4 * 4];
            s += q4.x * k4.x + q4.y * k4.y + q4.z * k4.z + q4.w * k4.w;
        }
        s_z[r * 8 + h] = 1.f / (s + 1e-6f);
    }
    __syncthreads();

    {
        int h = tid >> 5, e = tid & 31;
        float kvc[32];
#pragma unroll
        for (int d = 0; d < 32; d++) kvc[d] = s_kv[(h * 32 + d) * 32 + e];
        for (int r = 0; r < 32; r++) {
            float acc = 0.f;
#pragma unroll
            for (int d4 = 0; d4 < 8; d4++) {
                float4 q4 = *(float4*)&s_q[r * 256 + h * 32 + d4 * 4];
                acc += q4.x * kvc[d4 * 4] + q4.y * kvc[d4 * 4 + 1]
                     + q4.z * kvc[d4 * 4 + 2] + q4.w * kvc[d4 * 4 + 3];
            }
            outa[(size_t)(tok0 + r) * D_ + tid] = __float2half(acc * s_z[r * 8 + h]);
        }
    }
}

// ============================================================================
extern "C" void kernel_launch(void* const* d_in, const int* in_sizes, int n_in,
                              void* d_out, int out_size)
{
    const float* x    = (const float*)d_in[0];
    const float* Wq   = (const float*)d_in[1];
    const float* bq   = (const float*)d_in[2];
    const float* Wk   = (const float*)d_in[3];
    const float* bk   = (const float*)d_in[4];
    const float* Wv   = (const float*)d_in[5];
    const float* bv   = (const float*)d_in[6];
    const float* Wo   = (const float*)d_in[7];
    const float* bo   = (const float*)d_in[8];
    const float* W1   = (const float*)d_in[9];
    const float* b1   = (const float*)d_in[10];
    const float* W2   = (const float*)d_in[11];
    const float* b2   = (const float*)d_in[12];
    const float* ln1g = (const float*)d_in[13];
    const float* ln1b = (const float*)d_in[14];
    const float* ln2g = (const float*)d_in[15];
    const float* ln2b = (const float*)d_in[16];
    float* out = (float*)d_out;

    __half *xh, *ah, *x1h, *hh, *wqkvT, *woT, *w1T, *w2T;
    float *x1, *bqkv;
    cudaGetSymbolAddress((void**)&xh,    g_xh);
    cudaGetSymbolAddress((void**)&ah,    g_ah);
    cudaGetSymbolAddress((void**)&x1,    g_x1);
    cudaGetSymbolAddress((void**)&x1h,   g_x1h);
    cudaGetSymbolAddress((void**)&hh,    g_hh);
    cudaGetSymbolAddress((void**)&wqkvT, g_wqkvT);
    cudaGetSymbolAddress((void**)&woT,   g_woT);
    cudaGetSymbolAddress((void**)&w1T,   g_w1T);
    cudaGetSymbolAddress((void**)&w2T,   g_w2T);
    cudaGetSymbolAddress((void**)&bqkv,  g_bqkv);

    const int GSM   = 73728;
    const int GSMLN = 128 * LNPITCH * 4;   // 135168
    const int GSMKV = 8 * 5120 * 2;        // 81920
    cudaFuncSetAttribute((k_gemm<2>), cudaFuncAttributeMaxDynamicSharedMemorySize, GSM);
    cudaFuncSetAttribute((k_gemm<3>), cudaFuncAttributeMaxDynamicSharedMemorySize, GSM);
    cudaFuncSetAttribute((k_gemm_ln<0>), cudaFuncAttributeMaxDynamicSharedMemorySize, GSMLN);
    cudaFuncSetAttribute((k_gemm_ln<1>), cudaFuncAttributeMaxDynamicSharedMemorySize, GSMLN);
    cudaFuncSetAttribute(k_kvred, cudaFuncAttributeMaxDynamicSharedMemorySize, GSMKV);
    cudaFuncSetAttribute(k_attnread, cudaFuncAttributeMaxDynamicSharedMemorySize, 67584);

    k_cvtx<<<MTOK * D_ / 4 / 512, 512>>>(x);
    k_trall<<<769, dim3(32, 8)>>>(Wq, Wk, Wv, Wo, W1, W2, bq, bk, bv);

    // merged QKV projection: phi for q,k; head-major scatter for k,v
    k_gemm<3><<<dim3(6, 512), 256, GSM>>>(xh, wqkvT, bqkv, nullptr, D_, 768);

    k_kvred<<<dim3(32, NCH), 256, GSMKV>>>();
    k_kvfin<<<32, 256>>>();
    k_attnread<<<MTOK / 32, 256, 67584>>>(ah);

    // Wo projection + residual + LN1 (fused) -> x1 (f32) + x1h (half)
    k_gemm_ln<0><<<512, 512, GSMLN>>>(ah, woT, bo, x, ln1g, ln1b, x1, x1h, D_);

    // FFN1 (relu), half out
    k_gemm<2><<<dim3(8, 512), 256, GSM>>>(x1h, w1T, b1, hh, D_, FF_);

    // FFN2 + residual + LN2 (fused) -> out
    k_gemm_ln<1><<<512, 512, GSMLN>>>(hh, w2T, b2, x1, ln2g, ln2b, out, nullptr, FF_);
}

// round 12
// speedup vs baseline: 1.0640x; 1.0042x over previous
#include <cuda_runtime.h>
#include <cuda_fp16.h>
#include <math.h>
#include <stdint.h>

#define B_    4
#define L_    16384
#define D_    256
#define H_    8
#define DH_   32
#define FF_   1024
#define MTOK  65536
#define NCH   32
#define CHTOK 512

// ---------------- scratch ----------------
__device__ __half g_xh  [MTOK * D_];     // x as half
__device__ __half g_qh  [MTOK * D_];     // q_phi, [tok][256]
__device__ __half g_kh  [MTOK * D_];     // k_phi, [(b*8+h)][L][32]
__device__ __half g_vh  [MTOK * D_];     // v,     [(b*8+h)][L][32]
__device__ __half g_ah  [MTOK * D_];     // attn readout (half)
__device__ float  g_x1  [MTOK * D_];     // LN1 out (f32, residual for LN2)
__device__ __half g_x1h [MTOK * D_];     // LN1 out (half, FFN1 A)
__device__ __half g_hh  [MTOK * FF_];    // ffn hidden (half)
__device__ float  g_kvpart[NCH * 32 * 1024];
__device__ float  g_kspart[NCH * 32 * 32];
__device__ float  g_kv[32 * 1024];
__device__ float  g_ksum[32 * 32];
// transposed weights [N,K] row-major, half
__device__ __half g_wqkvT[768 * D_];
__device__ __half g_woT[D_ * D_];
__device__ __half g_w1T[FF_ * D_];
__device__ __half g_w2T[D_ * FF_];
__device__ float  g_bqkv[768];

// ---------------- helpers ----------------
__device__ __forceinline__ uint32_t smem_u32(const void* p) {
    uint32_t a;
    asm("{ .reg .u64 t; cvta.to.shared.u64 t, %1; cvt.u32.u64 %0, t; }" : "=r"(a) : "l"(p));
    return a;
}
__device__ __forceinline__ void cp16(uint32_t dst, const void* src) {
    asm volatile("cp.async.cg.shared.global [%0], [%1], 16;" :: "r"(dst), "l"(src));
}
__device__ __forceinline__ void mma16(float* c, uint32_t a0, uint32_t a1,
                                      uint32_t a2, uint32_t a3,
                                      uint32_t b0, uint32_t b1) {
    asm volatile("mma.sync.aligned.m16n8k16.row.col.f32.f16.f16.f32 "
        "{%0,%1,%2,%3}, {%4,%5,%6,%7}, {%8,%9}, {%0,%1,%2,%3};"
        : "+f"(c[0]), "+f"(c[1]), "+f"(c[2]), "+f"(c[3])
        : "r"(a0), "r"(a1), "r"(a2), "r"(a3), "r"(b0), "r"(b1));
}
#define LDMX4T(r, addr) \
    asm volatile("ldmatrix.sync.aligned.m8n8.x4.trans.shared.b16 {%0,%1,%2,%3}, [%4];" \
        : "=r"((r)[0]), "=r"((r)[1]), "=r"((r)[2]), "=r"((r)[3]) : "r"(addr))

// ============================================================================
// x -> half copy
// ============================================================================
__global__ __launch_bounds__(512) void k_cvtx(const float* __restrict__ x)
{
    int i = blockIdx.x * 512 + threadIdx.x;
    float4 v = *(const float4*)&x[(size_t)i * 4];
    __half2 h0 = __floats2half2_rn(v.x, v.y);
    __half2 h1 = __floats2half2_rn(v.z, v.w);
    *(uint2*)&g_xh[(size_t)i * 4] = make_uint2(*(uint32_t*)&h0, *(uint32_t*)&h1);
}

// ============================================================================
// ALL weight transposes + bias concat in ONE launch.
// ============================================================================
__global__ void k_trall(const float* __restrict__ Wq, const float* __restrict__ Wk,
                        const float* __restrict__ Wv, const float* __restrict__ Wo,
                        const float* __restrict__ W1, const float* __restrict__ W2,
                        const float* __restrict__ bq, const float* __restrict__ bk,
                        const float* __restrict__ bv)
{
    const int bid = blockIdx.x;
    if (bid == 768) {
        int t = threadIdx.y * 32 + threadIdx.x;
        g_bqkv[t] = bq[t]; g_bqkv[256 + t] = bk[t]; g_bqkv[512 + t] = bv[t];
        return;
    }
    const float* W; __half* Wt; int K, N, idx;
    if (bid < 256) {
        idx = bid & 63; K = D_; N = D_;
        int sel = bid >> 6;
        W  = (sel == 0) ? Wq : (sel == 1) ? Wk : (sel == 2) ? Wv : Wo;
        Wt = (sel == 0) ? g_wqkvT : (sel == 1) ? g_wqkvT + 256 * D_
           : (sel == 2) ? g_wqkvT + 512 * D_ : g_woT;
    } else if (bid < 512) {
        idx = bid - 256; K = D_; N = FF_; W = W1; Wt = g_w1T;
    } else {
        idx = bid - 512; K = FF_; N = D_; W = W2; Wt = g_w2T;
    }
    const int xt = N >> 5;
    const int n0 = (idx % xt) * 32, k0 = (idx / xt) * 32;

    __shared__ float t[32][33];
    int x = threadIdx.x, y = threadIdx.y;
    for (int i = y; i < 32; i += 8) t[i][x] = W[(size_t)(k0 + i) * N + n0 + x];
    __syncthreads();
    for (int i = y; i < 32; i += 8)
        Wt[(size_t)(n0 + i) * K + k0 + x] = __float2half(t[x][i]);
}

// ============================================================================
// fp16 mma.sync GEMM (BN=128, 256 thr, 4-stage).
// ACT: 2 relu -> Out (g_hh) | 3 QKV: phi for q,k, head-major scatter.
// ============================================================================
__device__ __forceinline__ void stage256(const __half* __restrict__ Ap,
                                         const __half* __restrict__ Bp,
                                         int K, uint32_t sa, uint32_t sb, int tid)
{
#pragma unroll
    for (int t = 0; t < 2; t++) {
        int i = tid + t * 256;
        int row = i >> 2, c = i & 3;
        cp16(sa + row * 96 + c * 16, Ap + (size_t)row * K + c * 8);
    }
#pragma unroll
    for (int t = 0; t < 2; t++) {
        int i = tid + t * 256;
        int row = i >> 2, c = i & 3;
        cp16(sb + row * 96 + c * 16, Bp + (size_t)row * K + c * 8);
    }
}

template <int ACT>
__global__ __launch_bounds__(256, 2) void k_gemm(
    const __half* __restrict__ A, const __half* __restrict__ Bt,
    const float* __restrict__ bias, __half* __restrict__ Out,
    int K, int Nout)
{
    extern __shared__ __half smh[];
    const int tid  = threadIdx.x;
    const int wid  = tid >> 5;
    const int lane = tid & 31;
    const int g = lane >> 2, t = lane & 3;
    const int wm = wid & 3, wn = wid >> 2;
    const int m0 = blockIdx.y * 128;
    const int n0 = blockIdx.x * 128;
    const int NC = K >> 5;

    uint32_t uA[4], uB[4];
#pragma unroll
    for (int s = 0; s < 4; s++) {
        uA[s] = smem_u32(smh + s * 6144);
        uB[s] = smem_u32(smh + 24576 + s * 6144);
    }

    float c[2][8][4] = {};
    const __half* Abase = A + (size_t)m0 * K;
    const __half* Bbase = Bt + (size_t)n0 * K;

    stage256(Abase,      Bbase,      K, uA[0], uB[0], tid);
    asm volatile("cp.async.commit_group;");
    stage256(Abase + 32, Bbase + 32, K, uA[1], uB[1], tid);
    asm volatile("cp.async.commit_group;");
    stage256(Abase + 64, Bbase + 64, K, uA[2], uB[2], tid);
    asm volatile("cp.async.commit_group;");

    for (int cc = 0; cc < NC; cc++) {
        if (cc + 2 < NC)      asm volatile("cp.async.wait_group 2;");
        else if (cc + 1 < NC) asm volatile("cp.async.wait_group 1;");
        else                  asm volatile("cp.async.wait_group 0;");
        __syncthreads();
        if (cc + 3 < NC) {
            const int bs = (cc + 3) & 3;
            stage256(Abase + (cc + 3) * 32, Bbase + (cc + 3) * 32, K, uA[bs], uB[bs], tid);
            asm volatile("cp.async.commit_group;");
        }
        const int cur = cc & 3;
        const __half* a_s = smh + cur * 6144;
        const __half* b_s = smh + 24576 + cur * 6144;
#pragma unroll
        for (int s = 0; s < 2; s++) {
            uint2 va[2][2];
#pragma unroll
            for (int i = 0; i < 2; i++) {
                const int rb = (2 * wm + i) * 16;
                va[i][0] = *(const uint2*)&a_s[(rb + g)     * 48 + s * 16 + 4 * t];
                va[i][1] = *(const uint2*)&a_s[(rb + g + 8) * 48 + s * 16 + 4 * t];
            }
            uint2 vb[8];
#pragma unroll
            for (int j = 0; j < 8; j++) {
                const int n = (wn * 8 + j) * 8 + g;
                vb[j] = *(const uint2*)&b_s[n * 48 + s * 16 + 4 * t];
            }
#pragma unroll
            for (int i = 0; i < 2; i++)
#pragma unroll
                for (int j = 0; j < 8; j++)
                    mma16(c[i][j], va[i][0].x, va[i][1].x, va[i][0].y, va[i][1].y,
                          vb[j].x, vb[j].y);
        }
    }

    const bool do_phi = (ACT == 3) && (n0 < 512);
#pragma unroll
    for (int j = 0; j < 8; j++) {
        const int col = n0 + (wn * 8 + j) * 8 + t * 2;
        const float b0 = __ldg(&bias[col]);
        const float b1 = __ldg(&bias[col + 1]);
#pragma unroll
        for (int i = 0; i < 2; i++) {
            const int r0 = m0 + (2 * wm + i) * 16 + g;
            float v0 = c[i][j][0] + b0, v1 = c[i][j][1] + b1;
            float v2 = c[i][j][2] + b0, v3 = c[i][j][3] + b1;
            if (do_phi) {
                v0 = (v0 > 0.f) ? (v0 + 1.f) : expf(v0);
                v1 = (v1 > 0.f) ? (v1 + 1.f) : expf(v1);
                v2 = (v2 > 0.f) ? (v2 + 1.f) : expf(v2);
                v3 = (v3 > 0.f) ? (v3 + 1.f) : expf(v3);
            }
            if (ACT == 2) {
                v0 = fmaxf(v0, 0.f); v1 = fmaxf(v1, 0.f);
                v2 = fmaxf(v2, 0.f); v3 = fmaxf(v3, 0.f);
            }
            __half2 h0 = __floats2half2_rn(v0, v1);
            __half2 h1 = __floats2half2_rn(v2, v3);
            if (ACT == 3) {
                if (n0 < 256) {
                    *(__half2*)&g_qh[(size_t)r0 * D_ + col]       = h0;
                    *(__half2*)&g_qh[(size_t)(r0 + 8) * D_ + col] = h1;
                } else {
                    __half* dst = (n0 < 512) ? g_kh : g_vh;
                    const int colr = col & 255;
                    const int head = colr >> 5, e = colr & 31;
                    const int b = r0 >> 14, l = r0 & (L_ - 1);
                    const size_t base0 = ((size_t)(b * 8 + head) * L_ + l) * 32 + e;
                    *(__half2*)&dst[base0]          = h0;
                    *(__half2*)&dst[base0 + 8 * 32] = h1;
                }
            } else {
                *(__half2*)&Out[(size_t)r0 * Nout + col]       = h0;
                *(__half2*)&Out[(size_t)(r0 + 8) * Nout + col] = h1;
            }
        }
    }
}

// ============================================================================
// fp16 GEMM (BN=256, 512 thr, 4-stage) + bias + residual + LayerNorm fused.
// ============================================================================
#define LNPITCH 264

template <int FINAL>
__global__ __launch_bounds__(512, 1) void k_gemm_ln(
    const __half* __restrict__ A, const __half* __restrict__ Bt,
    const float* __restrict__ bias, const float* __restrict__ res,
    const float* __restrict__ lg, const float* __restrict__ lb,
    float* __restrict__ o, __half* __restrict__ oh, int K)
{
    extern __shared__ __half smh[];
    const int tid  = threadIdx.x;
    const int wid  = tid >> 5;
    const int lane = tid & 31;
    const int g = lane >> 2, t = lane & 3;
    const int wm = wid & 3, wn = wid >> 2;
    const int m0 = blockIdx.x * 128;
    const int NC = K >> 5;

    uint32_t uA[4], uB[4];
#pragma unroll
    for (int s = 0; s < 4; s++) {
        uA[s] = smem_u32(smh + s * 6144);
        uB[s] = smem_u32(smh + 24576 + s * 12288);
    }

    float c[2][8][4] = {};
    const __half* Abase = A + (size_t)m0 * K;

    auto stage512 = [&](int chunk, int s) {
        const __half* Ap = Abase + chunk * 32;
        const __half* Bp = Bt + chunk * 32;
        {
            int row = tid >> 2, cc4 = tid & 3;
            cp16(uA[s] + row * 96 + cc4 * 16, Ap + (size_t)row * K + cc4 * 8);
        }
#pragma unroll
        for (int tt = 0; tt < 2; tt++) {
            int i = tid + tt * 512;
            int row = i >> 2, cc4 = i & 3;
            cp16(uB[s] + row * 96 + cc4 * 16, Bp + (size_t)row * K + cc4 * 8);
        }
    };

    stage512(0, 0);
    asm volatile("cp.async.commit_group;");
    stage512(1, 1);
    asm volatile("cp.async.commit_group;");
    stage512(2, 2);
    asm volatile("cp.async.commit_group;");

    for (int cc = 0; cc < NC; cc++) {
        if (cc + 2 < NC)      asm volatile("cp.async.wait_group 2;");
        else if (cc + 1 < NC) asm volatile("cp.async.wait_group 1;");
        else                  asm volatile("cp.async.wait_group 0;");
        __syncthreads();
        if (cc + 3 < NC) {
            stage512(cc + 3, (cc + 3) & 3);
            asm volatile("cp.async.commit_group;");
        }
        const int cur = cc & 3;
        const __half* a_s = smh + cur * 6144;
        const __half* b_s = smh + 24576 + cur * 12288;
#pragma unroll
        for (int s = 0; s < 2; s++) {
            uint2 va[2][2];
#pragma unroll
            for (int i = 0; i < 2; i++) {
                const int rb = (2 * wm + i) * 16;
                va[i][0] = *(const uint2*)&a_s[(rb + g)     * 48 + s * 16 + 4 * t];
                va[i][1] = *(const uint2*)&a_s[(rb + g + 8) * 48 + s * 16 + 4 * t];
            }
            uint2 vb[8];
#pragma unroll
            for (int j = 0; j < 8; j++)
                vb[j] = *(const uint2*)&b_s[(wn * 64 + j * 8 + g) * 48 + s * 16 + 4 * t];
#pragma unroll
            for (int i = 0; i < 2; i++)
#pragma unroll
                for (int j = 0; j < 8; j++)
                    mma16(c[i][j], va[i][0].x, va[i][1].x, va[i][0].y, va[i][1].y,
                          vb[j].x, vb[j].y);
        }
    }
    __syncthreads();

    float* se = (float*)smh;
#pragma unroll
    for (int j = 0; j < 8; j++) {
        const int col = wn * 64 + j * 8 + t * 2;
        const float b0 = __ldg(&bias[col]);
        const float b1 = __ldg(&bias[col + 1]);
#pragma unroll
        for (int i = 0; i < 2; i++) {
            const int r = (2 * wm + i) * 16 + g;
            *(float2*)&se[r * LNPITCH + col] = make_float2(c[i][j][0] + b0, c[i][j][1] + b1);
            *(float2*)&se[(r + 8) * LNPITCH + col] = make_float2(c[i][j][2] + b0, c[i][j][3] + b1);
        }
    }
    __syncthreads();

#pragma unroll
    for (int rr = 0; rr < 8; rr++) {
        const int row = wid * 8 + rr;
        const size_t rb = (size_t)(m0 + row) * D_;
        float vals[8];
        float sum = 0.f, sq = 0.f;
#pragma unroll
        for (int i = 0; i < 8; i++) {
            float v = se[row * LNPITCH + lane + i * 32] + res[rb + lane + i * 32];
            vals[i] = v; sum += v; sq += v * v;
        }
#pragma unroll
        for (int off = 16; off > 0; off >>= 1) {
            sum += __shfl_xor_sync(0xffffffffu, sum, off);
            sq  += __shfl_xor_sync(0xffffffffu, sq,  off);
        }
        float mu  = sum * (1.f / 256.f);
        float var = sq * (1.f / 256.f) - mu * mu;
        float rs  = rsqrtf(var + 1e-5f);
#pragma unroll
        for (int i = 0; i < 8; i++) {
            const int col = lane + i * 32;
            float v = (vals[i] - mu) * rs * lg[col] + lb[col];
            o[rb + col] = v;
            if (!FINAL) oh[rb + col] = __float2half(v);
        }
    }
}

// ============================================================================
// kv reduction via tensor cores; k/v dense head-major [(bh)][L][32].
// ============================================================================
__global__ __launch_bounds__(256) void k_kvred()
{
    extern __shared__ __half sred[];
    const int bh = blockIdx.x;
    const int ch = blockIdx.y;
    const int w = threadIdx.x >> 5, lane = threadIdx.x & 31;
    const int g = lane >> 2, t = lane & 3;

    __half* k_s = sred + w * 5120;
    const uint32_t uk = smem_u32(k_s);
    const uint32_t uv = uk + 2560 * 2;

    const int tok0 = ch * CHTOK + w * 64;
    const __half* kg = g_kh + ((size_t)bh * L_ + tok0) * 32;
    const __half* vg = g_vh + ((size_t)bh * L_ + tok0) * 32;

#pragma unroll
    for (int it = 0; it < 8; it++) {
        int i = lane + it * 32;
        int tok = i >> 2, c4 = i & 3;
        cp16(uk + tok * 80 + c4 * 16, kg + (size_t)i * 8);
        cp16(uv + tok * 80 + c4 * 16, vg + (size_t)i * 8);
    }
    asm volatile("cp.async.commit_group;");
    asm volatile("cp.async.wait_group 0;");
    __syncwarp();

    float acc[2][4][4] = {};
    float cs[2][4] = {};
    const uint32_t ones2 = 0x3C003C00u;

    const int tokA = (lane & 7) + ((lane >> 4) << 3);
    const int dA   = ((lane >> 3) & 1) * 8;
    const int tokB = (lane & 7) + (((lane >> 3) & 1) << 3);
    const int eB   = ((lane >> 4) & 1) * 8;

#pragma unroll
    for (int st = 0; st < 64; st += 16) {
        uint32_t a[2][4], bb[2][4];
#pragma unroll
        for (int mi = 0; mi < 2; mi++)
            LDMX4T(a[mi], uk + (st + tokA) * 80 + (mi * 16 + dA) * 2);
#pragma unroll
        for (int np = 0; np < 2; np++)
            LDMX4T(bb[np], uv + (st + tokB) * 80 + (np * 16 + eB) * 2);
#pragma unroll
        for (int mi = 0; mi < 2; mi++) {
#pragma unroll
            for (int nb = 0; nb < 4; nb++) {
                const int np = nb >> 1, hi = nb & 1;
                mma16(acc[mi][nb], a[mi][0], a[mi][1], a[mi][2], a[mi][3],
                      bb[np][hi * 2], bb[np][hi * 2 + 1]);
            }
            mma16(cs[mi], a[mi][0], a[mi][1], a[mi][2], a[mi][3], ones2, ones2);
        }
    }
    __syncthreads();

    float* s_part = (float*)sred;
    float* s_ksp  = s_part + 8 * 1024;
#pragma unroll
    for (int mi = 0; mi < 2; mi++) {
#pragma unroll
        for (int nb = 0; nb < 4; nb++) {
            const int d0 = mi * 16 + g, e0 = nb * 8 + 2 * t;
            *(float2*)&s_part[w * 1024 + d0 * 32 + e0] =
                make_float2(acc[mi][nb][0], acc[mi][nb][1]);
            *(float2*)&s_part[w * 1024 + (d0 + 8) * 32 + e0] =
                make_float2(acc[mi][nb][2], acc[mi][nb][3]);
        }
        if (t == 0) {
            s_ksp[w * 32 + mi * 16 + g]     = cs[mi][0];
            s_ksp[w * 32 + mi * 16 + g + 8] = cs[mi][2];
        }
    }
    __syncthreads();

    const int tid = threadIdx.x;
    for (int j = tid; j < 1024; j += 256) {
        float s = 0.f;
#pragma unroll
        for (int ww = 0; ww < 8; ww++) s += s_part[ww * 1024 + j];
        g_kvpart[((size_t)ch * 32 + bh) * 1024 + j] = s;
    }
    if (tid < 32) {
        float s = 0.f;
#pragma unroll
        for (int ww = 0; ww < 8; ww++) s += s_ksp[ww * 32 + tid];
        g_kspart[(ch * 32 + bh) * 32 + tid] = s;
    }
}

__global__ __launch_bounds__(256) void k_kvfin()
{
    const int bh = blockIdx.x;
    for (int j = threadIdx.x; j < 1024; j += 256) {
        float s = 0.f;
#pragma unroll
        for (int c = 0; c < NCH; c++) s += g_kvpart[((size_t)c * 32 + bh) * 1024 + j];
        g_kv[bh * 1024 + j] = s;
    }
    if (threadIdx.x < 32) {
        float s = 0.f;
#pragma unroll
        for (int c = 0; c < NCH; c++) s += g_kspart[(c * 32 + bh) * 32 + threadIdx.x];
        g_ksum[bh * 32 + threadIdx.x] = s;
    }
}

// ============================================================================
// attention readout (q from dense g_qh); output half
// ============================================================================
__global__ __launch_bounds__(256) void k_attnread(__half* __restrict__ outa)
{
    extern __shared__ float smr[];
    float* s_kv = smr;
    float* s_ks = smr + 8192;
    float* s_z  = smr + 8448;
    float* s_q  = smr + 8704;

    const int tid  = threadIdx.x;
    const int tok0 = blockIdx.x * 32;
    const int b    = tok0 >> 14;

    for (int i = tid; i < 2048; i += 256)
        *(float4*)&s_kv[i * 4] = *(const float4*)&g_kv[b * 8192 + i * 4];
    if (tid < 64)
        *(float4*)&s_ks[tid * 4] = *(const float4*)&g_ksum[b * 256 + tid * 4];
    for (int i = tid; i < 2048; i += 256) {
        uint2 u = *(const uint2*)&g_qh[(size_t)tok0 * D_ + i * 4];
        float2 f0 = __half22float2(*(__half2*)&u.x);
        float2 f1 = __half22float2(*(__half2*)&u.y);
        *(float4*)&s_q[i * 4] = make_float4(f0.x, f0.y, f1.x, f1.y);
    }
    __syncthreads();

    {
        int r = tid & 31, h = tid >> 5;
        float s = 0.f;
#pragma unroll
        for (int d4 = 0; d4 < 8; d4++) {
            float4 q4 = *(float4*)&s_q[r * 256 + h * 32 + d4 * 4];
            float4 k4 = *(float4*)&s_ks[h * 32 + d4 * 4];
            s += q4.x * k4.x + q4.y * k4.y + q4.z * k4.z + q4.w * k4.w;
        }
        s_z[r * 8 + h] = 1.f / (s + 1e-6f);
    }
    __syncthreads();

    {
        int h = tid >> 5, e = tid & 31;
        float kvc[32];
#pragma unroll
        for (int d = 0; d < 32; d++) kvc[d] = s_kv[(h * 32 + d) * 32 + e];
        for (int r = 0; r < 32; r++) {
            float acc = 0.f;
#pragma unroll
            for (int d4 = 0; d4 < 8; d4++) {
                float4 q4 = *(float4*)&s_q[r * 256 + h * 32 + d4 * 4];
                acc += q4.x * kvc[d4 * 4] + q4.y * kvc[d4 * 4 + 1]
                     + q4.z * kvc[d4 * 4 + 2] + q4.w * kvc[d4 * 4 + 3];
            }
            outa[(size_t)(tok0 + r) * D_ + tid] = __float2half(acc * s_z[r * 8 + h]);
        }
    }
}

// ============================================================================
extern "C" void kernel_launch(void* const* d_in, const int* in_sizes, int n_in,
                              void* d_out, int out_size)
{
    const float* x    = (const float*)d_in[0];
    const float* Wq   = (const float*)d_in[1];
    const float* bq   = (const float*)d_in[2];
    const float* Wk   = (const float*)d_in[3];
    const float* bk   = (const float*)d_in[4];
    const float* Wv   = (const float*)d_in[5];
    const float* bv   = (const float*)d_in[6];
    const float* Wo   = (const float*)d_in[7];
    const float* bo   = (const float*)d_in[8];
    const float* W1   = (const float*)d_in[9];
    const float* b1   = (const float*)d_in[10];
    const float* W2   = (const float*)d_in[11];
    const float* b2   = (const float*)d_in[12];
    const float* ln1g = (const float*)d_in[13];
    const float* ln1b = (const float*)d_in[14];
    const float* ln2g = (const float*)d_in[15];
    const float* ln2b = (const float*)d_in[16];
    float* out = (float*)d_out;

    __half *xh, *ah, *x1h, *hh, *wqkvT, *woT, *w1T, *w2T;
    float *x1, *bqkv;
    cudaGetSymbolAddress((void**)&xh,    g_xh);
    cudaGetSymbolAddress((void**)&ah,    g_ah);
    cudaGetSymbolAddress((void**)&x1,    g_x1);
    cudaGetSymbolAddress((void**)&x1h,   g_x1h);
    cudaGetSymbolAddress((void**)&hh,    g_hh);
    cudaGetSymbolAddress((void**)&wqkvT, g_wqkvT);
    cudaGetSymbolAddress((void**)&woT,   g_woT);
    cudaGetSymbolAddress((void**)&w1T,   g_w1T);
    cudaGetSymbolAddress((void**)&w2T,   g_w2T);
    cudaGetSymbolAddress((void**)&bqkv,  g_bqkv);

    const int GSM   = 98304;               // 4-stage: (A 4x6144 + B 4x6144) halves
    const int GSMLN = 147456;              // 4-stage: (A 4x6144 + B 4x12288) halves
    const int GSMKV = 8 * 5120 * 2;        // 81920
    cudaFuncSetAttribute((k_gemm<2>), cudaFuncAttributeMaxDynamicSharedMemorySize, GSM);
    cudaFuncSetAttribute((k_gemm<3>), cudaFuncAttributeMaxDynamicSharedMemorySize, GSM);
    cudaFuncSetAttribute((k_gemm_ln<0>), cudaFuncAttributeMaxDynamicSharedMemorySize, GSMLN);
    cudaFuncSetAttribute((k_gemm_ln<1>), cudaFuncAttributeMaxDynamicSharedMemorySize, GSMLN);
    cudaFuncSetAttribute(k_kvred, cudaFuncAttributeMaxDynamicSharedMemorySize, GSMKV);
    cudaFuncSetAttribute(k_attnread, cudaFuncAttributeMaxDynamicSharedMemorySize, 67584);

    k_cvtx<<<MTOK * D_ / 4 / 512, 512>>>(x);
    k_trall<<<769, dim3(32, 8)>>>(Wq, Wk, Wv, Wo, W1, W2, bq, bk, bv);

    // merged QKV projection: phi for q,k; head-major scatter for k,v
    k_gemm<3><<<dim3(6, 512), 256, GSM>>>(xh, wqkvT, bqkv, nullptr, D_, 768);

    k_kvred<<<dim3(32, NCH), 256, GSMKV>>>();
    k_kvfin<<<32, 256>>>();
    k_attnread<<<MTOK / 32, 256, 67584>>>(ah);

    // Wo projection + residual + LN1 (fused) -> x1 (f32) + x1h (half)
    k_gemm_ln<0><<<512, 512, GSMLN>>>(ah, woT, bo, x, ln1g, ln1b, x1, x1h, D_);

    // FFN1 (relu), half out
    k_gemm<2><<<dim3(8, 512), 256, GSM>>>(x1h, w1T, b1, hh, D_, FF_);

    // FFN2 + residual + LN2 (fused) -> out
    k_gemm_ln<1><<<512, 512, GSMLN>>>(hh, w2T, b2, x1, ln2g, ln2b, out, nullptr, FF_);
}

// round 13
// speedup vs baseline: 1.1169x; 1.0498x over previous
#include <cuda_runtime.h>
#include <cuda_fp16.h>
#include <math.h>
#include <stdint.h>

#define B_    4
#define L_    16384
#define D_    256
#define H_    8
#define DH_   32
#define FF_   1024
#define MTOK  65536
#define NCH   32
#define CHTOK 512

// ---------------- scratch ----------------
__device__ __half g_xh  [MTOK * D_];     // x as half
__device__ __half g_qh  [MTOK * D_];     // q_phi, [tok][256]
__device__ __half g_kh  [MTOK * D_];     // k_phi, [(b*8+h)][L][32]
__device__ __half g_vh  [MTOK * D_];     // v,     [(b*8+h)][L][32]
__device__ __half g_ah  [MTOK * D_];     // attn readout (half)
__device__ float  g_x1  [MTOK * D_];     // LN1 out (f32, residual for LN2)
__device__ __half g_x1h [MTOK * D_];     // LN1 out (half, FFN1 A)
__device__ __half g_hh  [MTOK * FF_];    // ffn hidden (half)
__device__ float  g_kvpart[NCH * 32 * 1024];
__device__ float  g_kspart[NCH * 32 * 32];
__device__ float  g_kv[32 * 1024];
__device__ float  g_ksum[32 * 32];
// transposed weights [N,K] row-major, half
__device__ __half g_wqkvT[768 * D_];
__device__ __half g_woT[D_ * D_];
__device__ __half g_w1T[FF_ * D_];
__device__ __half g_w2T[D_ * FF_];
__device__ float  g_bqkv[768];

// ---------------- helpers ----------------
__device__ __forceinline__ uint32_t smem_u32(const void* p) {
    uint32_t a;
    asm("{ .reg .u64 t; cvta.to.shared.u64 t, %1; cvt.u32.u64 %0, t; }" : "=r"(a) : "l"(p));
    return a;
}
__device__ __forceinline__ void cp16(uint32_t dst, const void* src) {
    asm volatile("cp.async.cg.shared.global [%0], [%1], 16;" :: "r"(dst), "l"(src));
}
__device__ __forceinline__ void mma16(float* c, uint32_t a0, uint32_t a1,
                                      uint32_t a2, uint32_t a3,
                                      uint32_t b0, uint32_t b1) {
    asm volatile("mma.sync.aligned.m16n8k16.row.col.f32.f16.f16.f32 "
        "{%0,%1,%2,%3}, {%4,%5,%6,%7}, {%8,%9}, {%0,%1,%2,%3};"
        : "+f"(c[0]), "+f"(c[1]), "+f"(c[2]), "+f"(c[3])
        : "r"(a0), "r"(a1), "r"(a2), "r"(a3), "r"(b0), "r"(b1));
}
#define LDMX4T(r, addr) \
    asm volatile("ldmatrix.sync.aligned.m8n8.x4.trans.shared.b16 {%0,%1,%2,%3}, [%4];" \
        : "=r"((r)[0]), "=r"((r)[1]), "=r"((r)[2]), "=r"((r)[3]) : "r"(addr))

// ============================================================================
// x -> half copy
// ============================================================================
__global__ __launch_bounds__(512) void k_cvtx(const float* __restrict__ x)
{
    int i = blockIdx.x * 512 + threadIdx.x;
    float4 v = *(const float4*)&x[(size_t)i * 4];
    __half2 h0 = __floats2half2_rn(v.x, v.y);
    __half2 h1 = __floats2half2_rn(v.z, v.w);
    *(uint2*)&g_xh[(size_t)i * 4] = make_uint2(*(uint32_t*)&h0, *(uint32_t*)&h1);
}

// ============================================================================
// ALL weight transposes + bias concat in ONE launch.
// ============================================================================
__global__ void k_trall(const float* __restrict__ Wq, const float* __restrict__ Wk,
                        const float* __restrict__ Wv, const float* __restrict__ Wo,
                        const float* __restrict__ W1, const float* __restrict__ W2,
                        const float* __restrict__ bq, const float* __restrict__ bk,
                        const float* __restrict__ bv)
{
    const int bid = blockIdx.x;
    if (bid == 768) {
        int t = threadIdx.y * 32 + threadIdx.x;
        g_bqkv[t] = bq[t]; g_bqkv[256 + t] = bk[t]; g_bqkv[512 + t] = bv[t];
        return;
    }
    const float* W; __half* Wt; int K, N, idx;
    if (bid < 256) {
        idx = bid & 63; K = D_; N = D_;
        int sel = bid >> 6;
        W  = (sel == 0) ? Wq : (sel == 1) ? Wk : (sel == 2) ? Wv : Wo;
        Wt = (sel == 0) ? g_wqkvT : (sel == 1) ? g_wqkvT + 256 * D_
           : (sel == 2) ? g_wqkvT + 512 * D_ : g_woT;
    } else if (bid < 512) {
        idx = bid - 256; K = D_; N = FF_; W = W1; Wt = g_w1T;
    } else {
        idx = bid - 512; K = FF_; N = D_; W = W2; Wt = g_w2T;
    }
    const int xt = N >> 5;
    const int n0 = (idx % xt) * 32, k0 = (idx / xt) * 32;

    __shared__ float t[32][33];
    int x = threadIdx.x, y = threadIdx.y;
    for (int i = y; i < 32; i += 8) t[i][x] = W[(size_t)(k0 + i) * N + n0 + x];
    __syncthreads();
    for (int i = y; i < 32; i += 8)
        Wt[(size_t)(n0 + i) * K + k0 + x] = __float2half(t[x][i]);
}

// ============================================================================
// fp16 mma.sync GEMM (BN=128, 256 thr, 4-stage).
// ACT: 2 relu -> Out (g_hh) | 3 QKV: phi for q,k, head-major scatter.
// ============================================================================
__device__ __forceinline__ void stage256(const __half* __restrict__ Ap,
                                         const __half* __restrict__ Bp,
                                         int K, uint32_t sa, uint32_t sb, int tid)
{
#pragma unroll
    for (int t = 0; t < 2; t++) {
        int i = tid + t * 256;
        int row = i >> 2, c = i & 3;
        cp16(sa + row * 96 + c * 16, Ap + (size_t)row * K + c * 8);
    }
#pragma unroll
    for (int t = 0; t < 2; t++) {
        int i = tid + t * 256;
        int row = i >> 2, c = i & 3;
        cp16(sb + row * 96 + c * 16, Bp + (size_t)row * K + c * 8);
    }
}

template <int ACT>
__global__ __launch_bounds__(256, 2) void k_gemm(
    const __half* __restrict__ A, const __half* __restrict__ Bt,
    const float* __restrict__ bias, __half* __restrict__ Out,
    int K, int Nout)
{
    extern __shared__ __half smh[];
    const int tid  = threadIdx.x;
    const int wid  = tid >> 5;
    const int lane = tid & 31;
    const int g = lane >> 2, t = lane & 3;
    const int wm = wid & 3, wn = wid >> 2;
    const int m0 = blockIdx.y * 128;
    const int n0 = blockIdx.x * 128;
    const int NC = K >> 5;

    uint32_t uA[4], uB[4];
#pragma unroll
    for (int s = 0; s < 4; s++) {
        uA[s] = smem_u32(smh + s * 6144);
        uB[s] = smem_u32(smh + 24576 + s * 6144);
    }

    float c[2][8][4] = {};
    const __half* Abase = A + (size_t)m0 * K;
    const __half* Bbase = Bt + (size_t)n0 * K;

    stage256(Abase,      Bbase,      K, uA[0], uB[0], tid);
    asm volatile("cp.async.commit_group;");
    stage256(Abase + 32, Bbase + 32, K, uA[1], uB[1], tid);
    asm volatile("cp.async.commit_group;");
    stage256(Abase + 64, Bbase + 64, K, uA[2], uB[2], tid);
    asm volatile("cp.async.commit_group;");

    for (int cc = 0; cc < NC; cc++) {
        if (cc + 2 < NC)      asm volatile("cp.async.wait_group 2;");
        else if (cc + 1 < NC) asm volatile("cp.async.wait_group 1;");
        else                  asm volatile("cp.async.wait_group 0;");
        __syncthreads();
        if (cc + 3 < NC) {
            const int bs = (cc + 3) & 3;
            stage256(Abase + (cc + 3) * 32, Bbase + (cc + 3) * 32, K, uA[bs], uB[bs], tid);
            asm volatile("cp.async.commit_group;");
        }
        const int cur = cc & 3;
        const __half* a_s = smh + cur * 6144;
        const __half* b_s = smh + 24576 + cur * 6144;
#pragma unroll
        for (int s = 0; s < 2; s++) {
            uint2 va[2][2];
#pragma unroll
            for (int i = 0; i < 2; i++) {
                const int rb = (2 * wm + i) * 16;
                va[i][0] = *(const uint2*)&a_s[(rb + g)     * 48 + s * 16 + 4 * t];
                va[i][1] = *(const uint2*)&a_s[(rb + g + 8) * 48 + s * 16 + 4 * t];
            }
            uint2 vb[8];
#pragma unroll
            for (int j = 0; j < 8; j++) {
                const int n = (wn * 8 + j) * 8 + g;
                vb[j] = *(const uint2*)&b_s[n * 48 + s * 16 + 4 * t];
            }
#pragma unroll
            for (int i = 0; i < 2; i++)
#pragma unroll
                for (int j = 0; j < 8; j++)
                    mma16(c[i][j], va[i][0].x, va[i][1].x, va[i][0].y, va[i][1].y,
                          vb[j].x, vb[j].y);
        }
    }

    const bool do_phi = (ACT == 3) && (n0 < 512);
#pragma unroll
    for (int j = 0; j < 8; j++) {
        const int col = n0 + (wn * 8 + j) * 8 + t * 2;
        const float b0 = __ldg(&bias[col]);
        const float b1 = __ldg(&bias[col + 1]);
#pragma unroll
        for (int i = 0; i < 2; i++) {
            const int r0 = m0 + (2 * wm + i) * 16 + g;
            float v0 = c[i][j][0] + b0, v1 = c[i][j][1] + b1;
            float v2 = c[i][j][2] + b0, v3 = c[i][j][3] + b1;
            if (do_phi) {
                v0 = (v0 > 0.f) ? (v0 + 1.f) : expf(v0);
                v1 = (v1 > 0.f) ? (v1 + 1.f) : expf(v1);
                v2 = (v2 > 0.f) ? (v2 + 1.f) : expf(v2);
                v3 = (v3 > 0.f) ? (v3 + 1.f) : expf(v3);
            }
            if (ACT == 2) {
                v0 = fmaxf(v0, 0.f); v1 = fmaxf(v1, 0.f);
                v2 = fmaxf(v2, 0.f); v3 = fmaxf(v3, 0.f);
            }
            __half2 h0 = __floats2half2_rn(v0, v1);
            __half2 h1 = __floats2half2_rn(v2, v3);
            if (ACT == 3) {
                if (n0 < 256) {
                    *(__half2*)&g_qh[(size_t)r0 * D_ + col]       = h0;
                    *(__half2*)&g_qh[(size_t)(r0 + 8) * D_ + col] = h1;
                } else {
                    __half* dst = (n0 < 512) ? g_kh : g_vh;
                    const int colr = col & 255;
                    const int head = colr >> 5, e = colr & 31;
                    const int b = r0 >> 14, l = r0 & (L_ - 1);
                    const size_t base0 = ((size_t)(b * 8 + head) * L_ + l) * 32 + e;
                    *(__half2*)&dst[base0]          = h0;
                    *(__half2*)&dst[base0 + 8 * 32] = h1;
                }
            } else {
                *(__half2*)&Out[(size_t)r0 * Nout + col]       = h0;
                *(__half2*)&Out[(size_t)(r0 + 8) * Nout + col] = h1;
            }
        }
    }
}

// ============================================================================
// fp16 GEMM (BM=64, BN=256, 256 thr, 3-stage, 2 CTAs/SM) + bias + residual
// + LayerNorm fused.  Warp grid 2m x 4n; warp tile 32x64.
// smem halves: A 3x3072 @0 | B 3x12288 @9216  (46080 halves = 92160 B)
// epilogue: se = f32 [64][LNPITCH] (67584 B, fits in same region)
// ============================================================================
#define LNPITCH 264

template <int FINAL>
__global__ __launch_bounds__(256, 2) void k_gemm_ln(
    const __half* __restrict__ A, const __half* __restrict__ Bt,
    const float* __restrict__ bias, const float* __restrict__ res,
    const float* __restrict__ lg, const float* __restrict__ lb,
    float* __restrict__ o, __half* __restrict__ oh, int K)
{
    extern __shared__ __half smh[];
    const int tid  = threadIdx.x;
    const int wid  = tid >> 5;
    const int lane = tid & 31;
    const int g = lane >> 2, t = lane & 3;
    const int wm = wid & 1, wn = wid >> 1;   // 2m x 4n
    const int m0 = blockIdx.x * 64;
    const int NC = K >> 5;

    uint32_t uA[3], uB[3];
#pragma unroll
    for (int s = 0; s < 3; s++) {
        uA[s] = smem_u32(smh + s * 3072);
        uB[s] = smem_u32(smh + 9216 + s * 12288);
    }

    float c[2][8][4] = {};
    const __half* Abase = A + (size_t)m0 * K;

    auto stage = [&](int chunk, int s) {
        const __half* Ap = Abase + chunk * 32;
        const __half* Bp = Bt + chunk * 32;
        {   // A: 64 rows x 4 cp16 = 256
            int row = tid >> 2, c4 = tid & 3;
            cp16(uA[s] + row * 96 + c4 * 16, Ap + (size_t)row * K + c4 * 8);
        }
#pragma unroll
        for (int tt = 0; tt < 4; tt++) {   // B: 256 rows x 4 cp16 = 1024
            int i = tid + tt * 256;
            int row = i >> 2, c4 = i & 3;
            cp16(uB[s] + row * 96 + c4 * 16, Bp + (size_t)row * K + c4 * 8);
        }
    };

    stage(0, 0);
    asm volatile("cp.async.commit_group;");
    stage(1, 1);
    asm volatile("cp.async.commit_group;");

    for (int cc = 0; cc < NC; cc++) {
        if (cc + 1 < NC) asm volatile("cp.async.wait_group 1;");
        else             asm volatile("cp.async.wait_group 0;");
        __syncthreads();
        if (cc + 2 < NC) {
            stage(cc + 2, (cc + 2) % 3);
            asm volatile("cp.async.commit_group;");
        }
        const int cur = cc % 3;
        const __half* a_s = smh + cur * 3072;
        const __half* b_s = smh + 9216 + cur * 12288;
#pragma unroll
        for (int s = 0; s < 2; s++) {
            uint2 va[2][2];
#pragma unroll
            for (int i = 0; i < 2; i++) {
                const int rb = (2 * wm + i) * 16;
                va[i][0] = *(const uint2*)&a_s[(rb + g)     * 48 + s * 16 + 4 * t];
                va[i][1] = *(const uint2*)&a_s[(rb + g + 8) * 48 + s * 16 + 4 * t];
            }
            uint2 vb[8];
#pragma unroll
            for (int j = 0; j < 8; j++)
                vb[j] = *(const uint2*)&b_s[(wn * 64 + j * 8 + g) * 48 + s * 16 + 4 * t];
#pragma unroll
            for (int i = 0; i < 2; i++)
#pragma unroll
                for (int j = 0; j < 8; j++)
                    mma16(c[i][j], va[i][0].x, va[i][1].x, va[i][0].y, va[i][1].y,
                          vb[j].x, vb[j].y);
        }
    }
    __syncthreads();

    float* se = (float*)smh;   // 64 x LNPITCH
#pragma unroll
    for (int j = 0; j < 8; j++) {
        const int col = wn * 64 + j * 8 + t * 2;
        const float b0 = __ldg(&bias[col]);
        const float b1 = __ldg(&bias[col + 1]);
#pragma unroll
        for (int i = 0; i < 2; i++) {
            const int r = (2 * wm + i) * 16 + g;
            *(float2*)&se[r * LNPITCH + col] = make_float2(c[i][j][0] + b0, c[i][j][1] + b1);
            *(float2*)&se[(r + 8) * LNPITCH + col] = make_float2(c[i][j][2] + b0, c[i][j][3] + b1);
        }
    }
    __syncthreads();

    // LN: warp w handles rows w*8 .. w*8+7 (8 warps x 8 = 64 rows)
#pragma unroll
    for (int rr = 0; rr < 8; rr++) {
        const int row = wid * 8 + rr;
        const size_t rb = (size_t)(m0 + row) * D_;
        float vals[8];
        float sum = 0.f, sq = 0.f;
#pragma unroll
        for (int i = 0; i < 8; i++) {
            float v = se[row * LNPITCH + lane + i * 32] + res[rb + lane + i * 32];
            vals[i] = v; sum += v; sq += v * v;
        }
#pragma unroll
        for (int off = 16; off > 0; off >>= 1) {
            sum += __shfl_xor_sync(0xffffffffu, sum, off);
            sq  += __shfl_xor_sync(0xffffffffu, sq,  off);
        }
        float mu  = sum * (1.f / 256.f);
        float var = sq * (1.f / 256.f) - mu * mu;
        float rs  = rsqrtf(var + 1e-5f);
#pragma unroll
        for (int i = 0; i < 8; i++) {
            const int col = lane + i * 32;
            float v = (vals[i] - mu) * rs * lg[col] + lb[col];
            o[rb + col] = v;
            if (!FINAL) oh[rb + col] = __float2half(v);
        }
    }
}

// ============================================================================
// kv reduction via tensor cores; k/v dense head-major [(bh)][L][32].
// ============================================================================
__global__ __launch_bounds__(256) void k_kvred()
{
    extern __shared__ __half sred[];
    const int bh = blockIdx.x;
    const int ch = blockIdx.y;
    const int w = threadIdx.x >> 5, lane = threadIdx.x & 31;
    const int g = lane >> 2, t = lane & 3;

    __half* k_s = sred + w * 5120;
    const uint32_t uk = smem_u32(k_s);
    const uint32_t uv = uk + 2560 * 2;

    const int tok0 = ch * CHTOK + w * 64;
    const __half* kg = g_kh + ((size_t)bh * L_ + tok0) * 32;
    const __half* vg = g_vh + ((size_t)bh * L_ + tok0) * 32;

#pragma unroll
    for (int it = 0; it < 8; it++) {
        int i = lane + it * 32;
        int tok = i >> 2, c4 = i & 3;
        cp16(uk + tok * 80 + c4 * 16, kg + (size_t)i * 8);
        cp16(uv + tok * 80 + c4 * 16, vg + (size_t)i * 8);
    }
    asm volatile("cp.async.commit_group;");
    asm volatile("cp.async.wait_group 0;");
    __syncwarp();

    float acc[2][4][4] = {};
    float cs[2][4] = {};
    const uint32_t ones2 = 0x3C003C00u;

    const int tokA = (lane & 7) + ((lane >> 4) << 3);
    const int dA   = ((lane >> 3) & 1) * 8;
    const int tokB = (lane & 7) + (((lane >> 3) & 1) << 3);
    const int eB   = ((lane >> 4) & 1) * 8;

#pragma unroll
    for (int st = 0; st < 64; st += 16) {
        uint32_t a[2][4], bb[2][4];
#pragma unroll
        for (int mi = 0; mi < 2; mi++)
            LDMX4T(a[mi], uk + (st + tokA) * 80 + (mi * 16 + dA) * 2);
#pragma unroll
        for (int np = 0; np < 2; np++)
            LDMX4T(bb[np], uv + (st + tokB) * 80 + (np * 16 + eB) * 2);
#pragma unroll
        for (int mi = 0; mi < 2; mi++) {
#pragma unroll
            for (int nb = 0; nb < 4; nb++) {
                const int np = nb >> 1, hi = nb & 1;
                mma16(acc[mi][nb], a[mi][0], a[mi][1], a[mi][2], a[mi][3],
                      bb[np][hi * 2], bb[np][hi * 2 + 1]);
            }
            mma16(cs[mi], a[mi][0], a[mi][1], a[mi][2], a[mi][3], ones2, ones2);
        }
    }
    __syncthreads();

    float* s_part = (float*)sred;
    float* s_ksp  = s_part + 8 * 1024;
#pragma unroll
    for (int mi = 0; mi < 2; mi++) {
#pragma unroll
        for (int nb = 0; nb < 4; nb++) {
            const int d0 = mi * 16 + g, e0 = nb * 8 + 2 * t;
            *(float2*)&s_part[w * 1024 + d0 * 32 + e0] =
                make_float2(acc[mi][nb][0], acc[mi][nb][1]);
            *(float2*)&s_part[w * 1024 + (d0 + 8) * 32 + e0] =
                make_float2(acc[mi][nb][2], acc[mi][nb][3]);
        }
        if (t == 0) {
            s_ksp[w * 32 + mi * 16 + g]     = cs[mi][0];
            s_ksp[w * 32 + mi * 16 + g + 8] = cs[mi][2];
        }
    }
    __syncthreads();

    const int tid = threadIdx.x;
    for (int j = tid; j < 1024; j += 256) {
        float s = 0.f;
#pragma unroll
        for (int ww = 0; ww < 8; ww++) s += s_part[ww * 1024 + j];
        g_kvpart[((size_t)ch * 32 + bh) * 1024 + j] = s;
    }
    if (tid < 32) {
        float s = 0.f;
#pragma unroll
        for (int ww = 0; ww < 8; ww++) s += s_ksp[ww * 32 + tid];
        g_kspart[(ch * 32 + bh) * 32 + tid] = s;
    }
}

__global__ __launch_bounds__(256) void k_kvfin()
{
    const int bh = blockIdx.x;
    for (int j = threadIdx.x; j < 1024; j += 256) {
        float s = 0.f;
#pragma unroll
        for (int c = 0; c < NCH; c++) s += g_kvpart[((size_t)c * 32 + bh) * 1024 + j];
        g_kv[bh * 1024 + j] = s;
    }
    if (threadIdx.x < 32) {
        float s = 0.f;
#pragma unroll
        for (int c = 0; c < NCH; c++) s += g_kspart[(c * 32 + bh) * 32 + threadIdx.x];
        g_ksum[bh * 32 + threadIdx.x] = s;
    }
}

// ============================================================================
// attention readout (q from dense g_qh); output half
// ============================================================================
__global__ __launch_bounds__(256) void k_attnread(__half* __restrict__ outa)
{
    extern __shared__ float smr[];
    float* s_kv = smr;
    float* s_ks = smr + 8192;
    float* s_z  = smr + 8448;
    float* s_q  = smr + 8704;

    const int tid  = threadIdx.x;
    const int tok0 = blockIdx.x * 32;
    const int b    = tok0 >> 14;

    for (int i = tid; i < 2048; i += 256)
        *(float4*)&s_kv[i * 4] = *(const float4*)&g_kv[b * 8192 + i * 4];
    if (tid < 64)
        *(float4*)&s_ks[tid * 4] = *(const float4*)&g_ksum[b * 256 + tid * 4];
    for (int i = tid; i < 2048; i += 256) {
        uint2 u = *(const uint2*)&g_qh[(size_t)tok0 * D_ + i * 4];
        float2 f0 = __half22float2(*(__half2*)&u.x);
        float2 f1 = __half22float2(*(__half2*)&u.y);
        *(float4*)&s_q[i * 4] = make_float4(f0.x, f0.y, f1.x, f1.y);
    }
    __syncthreads();

    {
        int r = tid & 31, h = tid >> 5;
        float s = 0.f;
#pragma unroll
        for (int d4 = 0; d4 < 8; d4++) {
            float4 q4 = *(float4*)&s_q[r * 256 + h * 32 + d4 * 4];
            float4 k4 = *(float4*)&s_ks[h * 32 + d4 * 4];
            s += q4.x * k4.x + q4.y * k4.y + q4.z * k4.z + q4.w * k4.w;
        }
        s_z[r * 8 + h] = 1.f / (s + 1e-6f);
    }
    __syncthreads();

    {
        int h = tid >> 5, e = tid & 31;
        float kvc[32];
#pragma unroll
        for (int d = 0; d < 32; d++) kvc[d] = s_kv[(h * 32 + d) * 32 + e];
        for (int r = 0; r < 32; r++) {
            float acc = 0.f;
#pragma unroll
            for (int d4 = 0; d4 < 8; d4++) {
                float4 q4 = *(float4*)&s_q[r * 256 + h * 32 + d4 * 4];
                acc += q4.x * kvc[d4 * 4] + q4.y * kvc[d4 * 4 + 1]
                     + q4.z * kvc[d4 * 4 + 2] + q4.w * kvc[d4 * 4 + 3];
            }
            outa[(size_t)(tok0 + r) * D_ + tid] = __float2half(acc * s_z[r * 8 + h]);
        }
    }
}

// ============================================================================
extern "C" void kernel_launch(void* const* d_in, const int* in_sizes, int n_in,
                              void* d_out, int out_size)
{
    const float* x    = (const float*)d_in[0];
    const float* Wq   = (const float*)d_in[1];
    const float* bq   = (const float*)d_in[2];
    const float* Wk   = (const float*)d_in[3];
    const float* bk   = (const float*)d_in[4];
    const float* Wv   = (const float*)d_in[5];
    const float* bv   = (const float*)d_in[6];
    const float* Wo   = (const float*)d_in[7];
    const float* bo   = (const float*)d_in[8];
    const float* W1   = (const float*)d_in[9];
    const float* b1   = (const float*)d_in[10];
    const float* W2   = (const float*)d_in[11];
    const float* b2   = (const float*)d_in[12];
    const float* ln1g = (const float*)d_in[13];
    const float* ln1b = (const float*)d_in[14];
    const float* ln2g = (const float*)d_in[15];
    const float* ln2b = (const float*)d_in[16];
    float* out = (float*)d_out;

    __half *xh, *ah, *x1h, *hh, *wqkvT, *woT, *w1T, *w2T;
    float *x1, *bqkv;
    cudaGetSymbolAddress((void**)&xh,    g_xh);
    cudaGetSymbolAddress((void**)&ah,    g_ah);
    cudaGetSymbolAddress((void**)&x1,    g_x1);
    cudaGetSymbolAddress((void**)&x1h,   g_x1h);
    cudaGetSymbolAddress((void**)&hh,    g_hh);
    cudaGetSymbolAddress((void**)&wqkvT, g_wqkvT);
    cudaGetSymbolAddress((void**)&woT,   g_woT);
    cudaGetSymbolAddress((void**)&w1T,   g_w1T);
    cudaGetSymbolAddress((void**)&w2T,   g_w2T);
    cudaGetSymbolAddress((void**)&bqkv,  g_bqkv);

    const int GSM   = 98304;               // k_gemm 4-stage
    const int GSMLN = 92160;               // k_gemm_ln 3-stage BM=64 (2 CTA/SM)
    const int GSMKV = 8 * 5120 * 2;        // 81920
    cudaFuncSetAttribute((k_gemm<2>), cudaFuncAttributeMaxDynamicSharedMemorySize, GSM);
    cudaFuncSetAttribute((k_gemm<3>), cudaFuncAttributeMaxDynamicSharedMemorySize, GSM);
    cudaFuncSetAttribute((k_gemm_ln<0>), cudaFuncAttributeMaxDynamicSharedMemorySize, GSMLN);
    cudaFuncSetAttribute((k_gemm_ln<1>), cudaFuncAttributeMaxDynamicSharedMemorySize, GSMLN);
    cudaFuncSetAttribute(k_kvred, cudaFuncAttributeMaxDynamicSharedMemorySize, GSMKV);
    cudaFuncSetAttribute(k_attnread, cudaFuncAttributeMaxDynamicSharedMemorySize, 67584);

    k_cvtx<<<MTOK * D_ / 4 / 512, 512>>>(x);
    k_trall<<<769, dim3(32, 8)>>>(Wq, Wk, Wv, Wo, W1, W2, bq, bk, bv);

    // merged QKV projection: phi for q,k; head-major scatter for k,v
    k_gemm<3><<<dim3(6, 512), 256, GSM>>>(xh, wqkvT, bqkv, nullptr, D_, 768);

    k_kvred<<<dim3(32, NCH), 256, GSMKV>>>();
    k_kvfin<<<32, 256>>>();
    k_attnread<<<MTOK / 32, 256, 67584>>>(ah);

    // Wo projection + residual + LN1 (fused) -> x1 (f32) + x1h (half)
    k_gemm_ln<0><<<1024, 256, GSMLN>>>(ah, woT, bo, x, ln1g, ln1b, x1, x1h, D_);

    // FFN1 (relu), half out
    k_gemm<2><<<dim3(8, 512), 256, GSM>>>(x1h, w1T, b1, hh, D_, FF_);

    // FFN2 + residual + LN2 (fused) -> out
    k_gemm_ln<1><<<1024, 256, GSMLN>>>(hh, w2T, b2, x1, ln2g, ln2b, out, nullptr, FF_);
}

// round 14
// speedup vs baseline: 1.1289x; 1.0107x over previous
#include <cuda_runtime.h>
#include <cuda_fp16.h>
#include <math.h>
#include <stdint.h>

#define B_    4
#define L_    16384
#define D_    256
#define H_    8
#define DH_   32
#define FF_   1024
#define MTOK  65536
#define NCH   32
#define CHTOK 512

// ---------------- scratch ----------------
__device__ __half g_xh  [MTOK * D_];     // x as half (QKV A + LN1 residual)
__device__ __half g_qh  [MTOK * D_];     // q_phi, [tok][256]
__device__ __half g_kh  [MTOK * D_];     // k_phi, [(b*8+h)][L][32]
__device__ __half g_vh  [MTOK * D_];     // v,     [(b*8+h)][L][32]
__device__ __half g_ah  [MTOK * D_];     // attn readout (half)
__device__ __half g_x1h [MTOK * D_];     // LN1 out (half: FFN1 A + LN2 residual)
__device__ __half g_hh  [MTOK * FF_];    // ffn hidden (half)
__device__ float  g_kvpart[NCH * 32 * 1024];
__device__ float  g_kspart[NCH * 32 * 32];
__device__ float  g_kv[32 * 1024];
__device__ float  g_ksum[32 * 32];
// transposed weights [N,K] row-major, half
__device__ __half g_wqkvT[768 * D_];
__device__ __half g_woT[D_ * D_];
__device__ __half g_w1T[FF_ * D_];
__device__ __half g_w2T[D_ * FF_];
__device__ float  g_bqkv[768];

// ---------------- helpers ----------------
__device__ __forceinline__ uint32_t smem_u32(const void* p) {
    uint32_t a;
    asm("{ .reg .u64 t; cvta.to.shared.u64 t, %1; cvt.u32.u64 %0, t; }" : "=r"(a) : "l"(p));
    return a;
}
__device__ __forceinline__ void cp16(uint32_t dst, const void* src) {
    asm volatile("cp.async.cg.shared.global [%0], [%1], 16;" :: "r"(dst), "l"(src));
}
__device__ __forceinline__ void mma16(float* c, uint32_t a0, uint32_t a1,
                                      uint32_t a2, uint32_t a3,
                                      uint32_t b0, uint32_t b1) {
    asm volatile("mma.sync.aligned.m16n8k16.row.col.f32.f16.f16.f32 "
        "{%0,%1,%2,%3}, {%4,%5,%6,%7}, {%8,%9}, {%0,%1,%2,%3};"
        : "+f"(c[0]), "+f"(c[1]), "+f"(c[2]), "+f"(c[3])
        : "r"(a0), "r"(a1), "r"(a2), "r"(a3), "r"(b0), "r"(b1));
}
#define LDMX4T(r, addr) \
    asm volatile("ldmatrix.sync.aligned.m8n8.x4.trans.shared.b16 {%0,%1,%2,%3}, [%4];" \
        : "=r"((r)[0]), "=r"((r)[1]), "=r"((r)[2]), "=r"((r)[3]) : "r"(addr))

// ============================================================================
// x -> half copy
// ============================================================================
__global__ __launch_bounds__(512) void k_cvtx(const float* __restrict__ x)
{
    int i = blockIdx.x * 512 + threadIdx.x;
    float4 v = *(const float4*)&x[(size_t)i * 4];
    __half2 h0 = __floats2half2_rn(v.x, v.y);
    __half2 h1 = __floats2half2_rn(v.z, v.w);
    *(uint2*)&g_xh[(size_t)i * 4] = make_uint2(*(uint32_t*)&h0, *(uint32_t*)&h1);
}

// ============================================================================
// ALL weight transposes + bias concat in ONE launch.
// ============================================================================
__global__ void k_trall(const float* __restrict__ Wq, const float* __restrict__ Wk,
                        const float* __restrict__ Wv, const float* __restrict__ Wo,
                        const float* __restrict__ W1, const float* __restrict__ W2,
                        const float* __restrict__ bq, const float* __restrict__ bk,
                        const float* __restrict__ bv)
{
    const int bid = blockIdx.x;
    if (bid == 768) {
        int t = threadIdx.y * 32 + threadIdx.x;
        g_bqkv[t] = bq[t]; g_bqkv[256 + t] = bk[t]; g_bqkv[512 + t] = bv[t];
        return;
    }
    const float* W; __half* Wt; int K, N, idx;
    if (bid < 256) {
        idx = bid & 63; K = D_; N = D_;
        int sel = bid >> 6;
        W  = (sel == 0) ? Wq : (sel == 1) ? Wk : (sel == 2) ? Wv : Wo;
        Wt = (sel == 0) ? g_wqkvT : (sel == 1) ? g_wqkvT + 256 * D_
           : (sel == 2) ? g_wqkvT + 512 * D_ : g_woT;
    } else if (bid < 512) {
        idx = bid - 256; K = D_; N = FF_; W = W1; Wt = g_w1T;
    } else {
        idx = bid - 512; K = FF_; N = D_; W = W2; Wt = g_w2T;
    }
    const int xt = N >> 5;
    const int n0 = (idx % xt) * 32, k0 = (idx / xt) * 32;

    __shared__ float t[32][33];
    int x = threadIdx.x, y = threadIdx.y;
    for (int i = y; i < 32; i += 8) t[i][x] = W[(size_t)(k0 + i) * N + n0 + x];
    __syncthreads();
    for (int i = y; i < 32; i += 8)
        Wt[(size_t)(n0 + i) * K + k0 + x] = __float2half(t[x][i]);
}

// ============================================================================
// fp16 mma.sync GEMM (BN=128, 256 thr, 4-stage).
// ACT: 2 relu -> Out (g_hh) | 3 QKV: phi for q,k, head-major scatter.
// ============================================================================
__device__ __forceinline__ void stage256(const __half* __restrict__ Ap,
                                         const __half* __restrict__ Bp,
                                         int K, uint32_t sa, uint32_t sb, int tid)
{
#pragma unroll
    for (int t = 0; t < 2; t++) {
        int i = tid + t * 256;
        int row = i >> 2, c = i & 3;
        cp16(sa + row * 96 + c * 16, Ap + (size_t)row * K + c * 8);
    }
#pragma unroll
    for (int t = 0; t < 2; t++) {
        int i = tid + t * 256;
        int row = i >> 2, c = i & 3;
        cp16(sb + row * 96 + c * 16, Bp + (size_t)row * K + c * 8);
    }
}

template <int ACT>
__global__ __launch_bounds__(256, 2) void k_gemm(
    const __half* __restrict__ A, const __half* __restrict__ Bt,
    const float* __restrict__ bias, __half* __restrict__ Out,
    int K, int Nout)
{
    extern __shared__ __half smh[];
    const int tid  = threadIdx.x;
    const int wid  = tid >> 5;
    const int lane = tid & 31;
    const int g = lane >> 2, t = lane & 3;
    const int wm = wid & 3, wn = wid >> 2;
    const int m0 = blockIdx.y * 128;
    const int n0 = blockIdx.x * 128;
    const int NC = K >> 5;

    uint32_t uA[4], uB[4];
#pragma unroll
    for (int s = 0; s < 4; s++) {
        uA[s] = smem_u32(smh + s * 6144);
        uB[s] = smem_u32(smh + 24576 + s * 6144);
    }

    float c[2][8][4] = {};
    const __half* Abase = A + (size_t)m0 * K;
    const __half* Bbase = Bt + (size_t)n0 * K;

    stage256(Abase,      Bbase,      K, uA[0], uB[0], tid);
    asm volatile("cp.async.commit_group;");
    stage256(Abase + 32, Bbase + 32, K, uA[1], uB[1], tid);
    asm volatile("cp.async.commit_group;");
    stage256(Abase + 64, Bbase + 64, K, uA[2], uB[2], tid);
    asm volatile("cp.async.commit_group;");

    for (int cc = 0; cc < NC; cc++) {
        if (cc + 2 < NC)      asm volatile("cp.async.wait_group 2;");
        else if (cc + 1 < NC) asm volatile("cp.async.wait_group 1;");
        else                  asm volatile("cp.async.wait_group 0;");
        __syncthreads();
        if (cc + 3 < NC) {
            const int bs = (cc + 3) & 3;
            stage256(Abase + (cc + 3) * 32, Bbase + (cc + 3) * 32, K, uA[bs], uB[bs], tid);
            asm volatile("cp.async.commit_group;");
        }
        const int cur = cc & 3;
        const __half* a_s = smh + cur * 6144;
        const __half* b_s = smh + 24576 + cur * 6144;
#pragma unroll
        for (int s = 0; s < 2; s++) {
            uint2 va[2][2];
#pragma unroll
            for (int i = 0; i < 2; i++) {
                const int rb = (2 * wm + i) * 16;
                va[i][0] = *(const uint2*)&a_s[(rb + g)     * 48 + s * 16 + 4 * t];
                va[i][1] = *(const uint2*)&a_s[(rb + g + 8) * 48 + s * 16 + 4 * t];
            }
            uint2 vb[8];
#pragma unroll
            for (int j = 0; j < 8; j++) {
                const int n = (wn * 8 + j) * 8 + g;
                vb[j] = *(const uint2*)&b_s[n * 48 + s * 16 + 4 * t];
            }
#pragma unroll
            for (int i = 0; i < 2; i++)
#pragma unroll
                for (int j = 0; j < 8; j++)
                    mma16(c[i][j], va[i][0].x, va[i][1].x, va[i][0].y, va[i][1].y,
                          vb[j].x, vb[j].y);
        }
    }

    const bool do_phi = (ACT == 3) && (n0 < 512);
#pragma unroll
    for (int j = 0; j < 8; j++) {
        const int col = n0 + (wn * 8 + j) * 8 + t * 2;
        const float b0 = __ldg(&bias[col]);
        const float b1 = __ldg(&bias[col + 1]);
#pragma unroll
        for (int i = 0; i < 2; i++) {
            const int r0 = m0 + (2 * wm + i) * 16 + g;
            float v0 = c[i][j][0] + b0, v1 = c[i][j][1] + b1;
            float v2 = c[i][j][2] + b0, v3 = c[i][j][3] + b1;
            if (do_phi) {
                v0 = (v0 > 0.f) ? (v0 + 1.f) : expf(v0);
                v1 = (v1 > 0.f) ? (v1 + 1.f) : expf(v1);
                v2 = (v2 > 0.f) ? (v2 + 1.f) : expf(v2);
                v3 = (v3 > 0.f) ? (v3 + 1.f) : expf(v3);
            }
            if (ACT == 2) {
                v0 = fmaxf(v0, 0.f); v1 = fmaxf(v1, 0.f);
                v2 = fmaxf(v2, 0.f); v3 = fmaxf(v3, 0.f);
            }
            __half2 h0 = __floats2half2_rn(v0, v1);
            __half2 h1 = __floats2half2_rn(v2, v3);
            if (ACT == 3) {
                if (n0 < 256) {
                    *(__half2*)&g_qh[(size_t)r0 * D_ + col]       = h0;
                    *(__half2*)&g_qh[(size_t)(r0 + 8) * D_ + col] = h1;
                } else {
                    __half* dst = (n0 < 512) ? g_kh : g_vh;
                    const int colr = col & 255;
                    const int head = colr >> 5, e = colr & 31;
                    const int b = r0 >> 14, l = r0 & (L_ - 1);
                    const size_t base0 = ((size_t)(b * 8 + head) * L_ + l) * 32 + e;
                    *(__half2*)&dst[base0]          = h0;
                    *(__half2*)&dst[base0 + 8 * 32] = h1;
                }
            } else {
                *(__half2*)&Out[(size_t)r0 * Nout + col]       = h0;
                *(__half2*)&Out[(size_t)(r0 + 8) * Nout + col] = h1;
            }
        }
    }
}

// ============================================================================
// fp16 GEMM (BM=64, BN=256, 256 thr, 3-stage, 2 CTAs/SM) + bias + HALF
// residual + LayerNorm fused.
// FINAL=0 -> writes oh (half) only.  FINAL=1 -> writes o (f32) only.
// ============================================================================
#define LNPITCH 264

template <int FINAL>
__global__ __launch_bounds__(256, 2) void k_gemm_ln(
    const __half* __restrict__ A, const __half* __restrict__ Bt,
    const float* __restrict__ bias, const __half* __restrict__ res,
    const float* __restrict__ lg, const float* __restrict__ lb,
    float* __restrict__ o, __half* __restrict__ oh, int K)
{
    extern __shared__ __half smh[];
    const int tid  = threadIdx.x;
    const int wid  = tid >> 5;
    const int lane = tid & 31;
    const int g = lane >> 2, t = lane & 3;
    const int wm = wid & 1, wn = wid >> 1;   // 2m x 4n
    const int m0 = blockIdx.x * 64;
    const int NC = K >> 5;

    uint32_t uA[3], uB[3];
#pragma unroll
    for (int s = 0; s < 3; s++) {
        uA[s] = smem_u32(smh + s * 3072);
        uB[s] = smem_u32(smh + 9216 + s * 12288);
    }

    float c[2][8][4] = {};
    const __half* Abase = A + (size_t)m0 * K;

    auto stage = [&](int chunk, int s) {
        const __half* Ap = Abase + chunk * 32;
        const __half* Bp = Bt + chunk * 32;
        {
            int row = tid >> 2, c4 = tid & 3;
            cp16(uA[s] + row * 96 + c4 * 16, Ap + (size_t)row * K + c4 * 8);
        }
#pragma unroll
        for (int tt = 0; tt < 4; tt++) {
            int i = tid + tt * 256;
            int row = i >> 2, c4 = i & 3;
            cp16(uB[s] + row * 96 + c4 * 16, Bp + (size_t)row * K + c4 * 8);
        }
    };

    stage(0, 0);
    asm volatile("cp.async.commit_group;");
    stage(1, 1);
    asm volatile("cp.async.commit_group;");

    for (int cc = 0; cc < NC; cc++) {
        if (cc + 1 < NC) asm volatile("cp.async.wait_group 1;");
        else             asm volatile("cp.async.wait_group 0;");
        __syncthreads();
        if (cc + 2 < NC) {
            stage(cc + 2, (cc + 2) % 3);
            asm volatile("cp.async.commit_group;");
        }
        const int cur = cc % 3;
        const __half* a_s = smh + cur * 3072;
        const __half* b_s = smh + 9216 + cur * 12288;
#pragma unroll
        for (int s = 0; s < 2; s++) {
            uint2 va[2][2];
#pragma unroll
            for (int i = 0; i < 2; i++) {
                const int rb = (2 * wm + i) * 16;
                va[i][0] = *(const uint2*)&a_s[(rb + g)     * 48 + s * 16 + 4 * t];
                va[i][1] = *(const uint2*)&a_s[(rb + g + 8) * 48 + s * 16 + 4 * t];
            }
            uint2 vb[8];
#pragma unroll
            for (int j = 0; j < 8; j++)
                vb[j] = *(const uint2*)&b_s[(wn * 64 + j * 8 + g) * 48 + s * 16 + 4 * t];
#pragma unroll
            for (int i = 0; i < 2; i++)
#pragma unroll
                for (int j = 0; j < 8; j++)
                    mma16(c[i][j], va[i][0].x, va[i][1].x, va[i][0].y, va[i][1].y,
                          vb[j].x, vb[j].y);
        }
    }
    __syncthreads();

    float* se = (float*)smh;   // 64 x LNPITCH
#pragma unroll
    for (int j = 0; j < 8; j++) {
        const int col = wn * 64 + j * 8 + t * 2;
        const float b0 = __ldg(&bias[col]);
        const float b1 = __ldg(&bias[col + 1]);
#pragma unroll
        for (int i = 0; i < 2; i++) {
            const int r = (2 * wm + i) * 16 + g;
            *(float2*)&se[r * LNPITCH + col] = make_float2(c[i][j][0] + b0, c[i][j][1] + b1);
            *(float2*)&se[(r + 8) * LNPITCH + col] = make_float2(c[i][j][2] + b0, c[i][j][3] + b1);
        }
    }
    __syncthreads();

    // LN: warp w handles rows w*8 .. w*8+7
#pragma unroll
    for (int rr = 0; rr < 8; rr++) {
        const int row = wid * 8 + rr;
        const size_t rb = (size_t)(m0 + row) * D_;
        float vals[8];
        float sum = 0.f, sq = 0.f;
#pragma unroll
        for (int i = 0; i < 8; i++) {
            float v = se[row * LNPITCH + lane + i * 32]
                    + __half2float(res[rb + lane + i * 32]);
            vals[i] = v; sum += v; sq += v * v;
        }
#pragma unroll
        for (int off = 16; off > 0; off >>= 1) {
            sum += __shfl_xor_sync(0xffffffffu, sum, off);
            sq  += __shfl_xor_sync(0xffffffffu, sq,  off);
        }
        float mu  = sum * (1.f / 256.f);
        float var = sq * (1.f / 256.f) - mu * mu;
        float rs  = rsqrtf(var + 1e-5f);
#pragma unroll
        for (int i = 0; i < 8; i++) {
            const int col = lane + i * 32;
            float v = (vals[i] - mu) * rs * lg[col] + lb[col];
            if (FINAL) o[rb + col] = v;
            else       oh[rb + col] = __float2half(v);
        }
    }
}

// ============================================================================
// kv reduction via tensor cores; k/v dense head-major [(bh)][L][32].
// ============================================================================
__global__ __launch_bounds__(256) void k_kvred()
{
    extern __shared__ __half sred[];
    const int bh = blockIdx.x;
    const int ch = blockIdx.y;
    const int w = threadIdx.x >> 5, lane = threadIdx.x & 31;
    const int g = lane >> 2, t = lane & 3;

    __half* k_s = sred + w * 5120;
    const uint32_t uk = smem_u32(k_s);
    const uint32_t uv = uk + 2560 * 2;

    const int tok0 = ch * CHTOK + w * 64;
    const __half* kg = g_kh + ((size_t)bh * L_ + tok0) * 32;
    const __half* vg = g_vh + ((size_t)bh * L_ + tok0) * 32;

#pragma unroll
    for (int it = 0; it < 8; it++) {
        int i = lane + it * 32;
        int tok = i >> 2, c4 = i & 3;
        cp16(uk + tok * 80 + c4 * 16, kg + (size_t)i * 8);
        cp16(uv + tok * 80 + c4 * 16, vg + (size_t)i * 8);
    }
    asm volatile("cp.async.commit_group;");
    asm volatile("cp.async.wait_group 0;");
    __syncwarp();

    float acc[2][4][4] = {};
    float cs[2][4] = {};
    const uint32_t ones2 = 0x3C003C00u;

    const int tokA = (lane & 7) + ((lane >> 4) << 3);
    const int dA   = ((lane >> 3) & 1) * 8;
    const int tokB = (lane & 7) + (((lane >> 3) & 1) << 3);
    const int eB   = ((lane >> 4) & 1) * 8;

#pragma unroll
    for (int st = 0; st < 64; st += 16) {
        uint32_t a[2][4], bb[2][4];
#pragma unroll
        for (int mi = 0; mi < 2; mi++)
            LDMX4T(a[mi], uk + (st + tokA) * 80 + (mi * 16 + dA) * 2);
#pragma unroll
        for (int np = 0; np < 2; np++)
            LDMX4T(bb[np], uv + (st + tokB) * 80 + (np * 16 + eB) * 2);
#pragma unroll
        for (int mi = 0; mi < 2; mi++) {
#pragma unroll
            for (int nb = 0; nb < 4; nb++) {
                const int np = nb >> 1, hi = nb & 1;
                mma16(acc[mi][nb], a[mi][0], a[mi][1], a[mi][2], a[mi][3],
                      bb[np][hi * 2], bb[np][hi * 2 + 1]);
            }
            mma16(cs[mi], a[mi][0], a[mi][1], a[mi][2], a[mi][3], ones2, ones2);
        }
    }
    __syncthreads();

    float* s_part = (float*)sred;
    float* s_ksp  = s_part + 8 * 1024;
#pragma unroll
    for (int mi = 0; mi < 2; mi++) {
#pragma unroll
        for (int nb = 0; nb < 4; nb++) {
            const int d0 = mi * 16 + g, e0 = nb * 8 + 2 * t;
            *(float2*)&s_part[w * 1024 + d0 * 32 + e0] =
                make_float2(acc[mi][nb][0], acc[mi][nb][1]);
            *(float2*)&s_part[w * 1024 + (d0 + 8) * 32 + e0] =
                make_float2(acc[mi][nb][2], acc[mi][nb][3]);
        }
        if (t == 0) {
            s_ksp[w * 32 + mi * 16 + g]     = cs[mi][0];
            s_ksp[w * 32 + mi * 16 + g + 8] = cs[mi][2];
        }
    }
    __syncthreads();

    const int tid = threadIdx.x;
    for (int j = tid; j < 1024; j += 256) {
        float s = 0.f;
#pragma unroll
        for (int ww = 0; ww < 8; ww++) s += s_part[ww * 1024 + j];
        g_kvpart[((size_t)ch * 32 + bh) * 1024 + j] = s;
    }
    if (tid < 32) {
        float s = 0.f;
#pragma unroll
        for (int ww = 0; ww < 8; ww++) s += s_ksp[ww * 32 + tid];
        g_kspart[(ch * 32 + bh) * 32 + tid] = s;
    }
}

__global__ __launch_bounds__(256) void k_kvfin()
{
    const int bh = blockIdx.x;
    for (int j = threadIdx.x; j < 1024; j += 256) {
        float s = 0.f;
#pragma unroll
        for (int c = 0; c < NCH; c++) s += g_kvpart[((size_t)c * 32 + bh) * 1024 + j];
        g_kv[bh * 1024 + j] = s;
    }
    if (threadIdx.x < 32) {
        float s = 0.f;
#pragma unroll
        for (int c = 0; c < NCH; c++) s += g_kspart[(c * 32 + bh) * 32 + threadIdx.x];
        g_ksum[bh * 32 + threadIdx.x] = s;
    }
}

// ============================================================================
// attention readout (q from dense g_qh); output half
// ============================================================================
__global__ __launch_bounds__(256) void k_attnread(__half* __restrict__ outa)
{
    extern __shared__ float smr[];
    float* s_kv = smr;
    float* s_ks = smr + 8192;
    float* s_z  = smr + 8448;
    float* s_q  = smr + 8704;

    const int tid  = threadIdx.x;
    const int tok0 = blockIdx.x * 32;
    const int b    = tok0 >> 14;

    for (int i = tid; i < 2048; i += 256)
        *(float4*)&s_kv[i * 4] = *(const float4*)&g_kv[b * 8192 + i * 4];
    if (tid < 64)
        *(float4*)&s_ks[tid * 4] = *(const float4*)&g_ksum[b * 256 + tid * 4];
    for (int i = tid; i < 2048; i += 256) {
        uint2 u = *(const uint2*)&g_qh[(size_t)tok0 * D_ + i * 4];
        float2 f0 = __half22float2(*(__half2*)&u.x);
        float2 f1 = __half22float2(*(__half2*)&u.y);
        *(float4*)&s_q[i * 4] = make_float4(f0.x, f0.y, f1.x, f1.y);
    }
    __syncthreads();

    {
        int r = tid & 31, h = tid >> 5;
        float s = 0.f;
#pragma unroll
        for (int d4 = 0; d4 < 8; d4++) {
            float4 q4 = *(float4*)&s_q[r * 256 + h * 32 + d4 * 4];
            float4 k4 = *(float4*)&s_ks[h * 32 + d4 * 4];
            s += q4.x * k4.x + q4.y * k4.y + q4.z * k4.z + q4.w * k4.w;
        }
        s_z[r * 8 + h] = 1.f / (s + 1e-6f);
    }
    __syncthreads();

    {
        int h = tid >> 5, e = tid & 31;
        float kvc[32];
#pragma unroll
        for (int d = 0; d < 32; d++) kvc[d] = s_kv[(h * 32 + d) * 32 + e];
        for (int r = 0; r < 32; r++) {
            float acc = 0.f;
#pragma unroll
            for (int d4 = 0; d4 < 8; d4++) {
                float4 q4 = *(float4*)&s_q[r * 256 + h * 32 + d4 * 4];
                acc += q4.x * kvc[d4 * 4] + q4.y * kvc[d4 * 4 + 1]
                     + q4.z * kvc[d4 * 4 + 2] + q4.w * kvc[d4 * 4 + 3];
            }
            outa[(size_t)(tok0 + r) * D_ + tid] = __float2half(acc * s_z[r * 8 + h]);
        }
    }
}

// ============================================================================
extern "C" void kernel_launch(void* const* d_in, const int* in_sizes, int n_in,
                              void* d_out, int out_size)
{
    const float* x    = (const float*)d_in[0];
    const float* Wq   = (const float*)d_in[1];
    const float* bq   = (const float*)d_in[2];
    const float* Wk   = (const float*)d_in[3];
    const float* bk   = (const float*)d_in[4];
    const float* Wv   = (const float*)d_in[5];
    const float* bv   = (const float*)d_in[6];
    const float* Wo   = (const float*)d_in[7];
    const float* bo   = (const float*)d_in[8];
    const float* W1   = (const float*)d_in[9];
    const float* b1   = (const float*)d_in[10];
    const float* W2   = (const float*)d_in[11];
    const float* b2   = (const float*)d_in[12];
    const float* ln1g = (const float*)d_in[13];
    const float* ln1b = (const float*)d_in[14];
    const float* ln2g = (const float*)d_in[15];
    const float* ln2b = (const float*)d_in[16];
    float* out = (float*)d_out;

    __half *xh, *ah, *x1h, *hh, *wqkvT, *woT, *w1T, *w2T;
    float *bqkv;
    cudaGetSymbolAddress((void**)&xh,    g_xh);
    cudaGetSymbolAddress((void**)&ah,    g_ah);
    cudaGetSymbolAddress((void**)&x1h,   g_x1h);
    cudaGetSymbolAddress((void**)&hh,    g_hh);
    cudaGetSymbolAddress((void**)&wqkvT, g_wqkvT);
    cudaGetSymbolAddress((void**)&woT,   g_woT);
    cudaGetSymbolAddress((void**)&w1T,   g_w1T);
    cudaGetSymbolAddress((void**)&w2T,   g_w2T);
    cudaGetSymbolAddress((void**)&bqkv,  g_bqkv);

    const int GSM   = 98304;               // k_gemm 4-stage
    const int GSMLN = 92160;               // k_gemm_ln 3-stage BM=64 (2 CTA/SM)
    const int GSMKV = 8 * 5120 * 2;        // 81920
    cudaFuncSetAttribute((k_gemm<2>), cudaFuncAttributeMaxDynamicSharedMemorySize, GSM);
    cudaFuncSetAttribute((k_gemm<3>), cudaFuncAttributeMaxDynamicSharedMemorySize, GSM);
    cudaFuncSetAttribute((k_gemm_ln<0>), cudaFuncAttributeMaxDynamicSharedMemorySize, GSMLN);
    cudaFuncSetAttribute((k_gemm_ln<1>), cudaFuncAttributeMaxDynamicSharedMemorySize, GSMLN);
    cudaFuncSetAttribute(k_kvred, cudaFuncAttributeMaxDynamicSharedMemorySize, GSMKV);
    cudaFuncSetAttribute(k_attnread, cudaFuncAttributeMaxDynamicSharedMemorySize, 67584);

    k_cvtx<<<MTOK * D_ / 4 / 512, 512>>>(x);
    k_trall<<<769, dim3(32, 8)>>>(Wq, Wk, Wv, Wo, W1, W2, bq, bk, bv);

    // merged QKV projection: phi for q,k; head-major scatter for k,v
    k_gemm<3><<<dim3(6, 512), 256, GSM>>>(xh, wqkvT, bqkv, nullptr, D_, 768);

    k_kvred<<<dim3(32, NCH), 256, GSMKV>>>();
    k_kvfin<<<32, 256>>>();
    k_attnread<<<MTOK / 32, 256, 67584>>>(ah);

    // Wo projection + half residual (xh) + LN1 -> x1h (half only)
    k_gemm_ln<0><<<1024, 256, GSMLN>>>(ah, woT, bo, xh, ln1g, ln1b, nullptr, x1h, D_);

    // FFN1 (relu), half out
    k_gemm<2><<<dim3(8, 512), 256, GSM>>>(x1h, w1T, b1, hh, D_, FF_);

    // FFN2 + half residual (x1h) + LN2 -> out (f32)
    k_gemm_ln<1><<<1024, 256, GSMLN>>>(hh, w2T, b2, x1h, ln2g, ln2b, out, nullptr, FF_);
}

// round 15
// speedup vs baseline: 1.2508x; 1.1079x over previous
#include <cuda_runtime.h>
#include <cuda_fp16.h>
#include <math.h>
#include <stdint.h>

#define B_    4
#define L_    16384
#define D_    256
#define H_    8
#define DH_   32
#define FF_   1024
#define MTOK  65536
#define NCH   32
#define CHTOK 512

// ---------------- scratch ----------------
__device__ __half g_xh  [MTOK * D_];     // x as half (QKV A + LN1 residual)
__device__ __half g_qh  [MTOK * D_];     // q_phi, [tok][256]
__device__ __half g_kh  [MTOK * D_];     // k_phi, [(b*8+h)][L][32]
__device__ __half g_vh  [MTOK * D_];     // v,     [(b*8+h)][L][32]
__device__ __half g_ah  [MTOK * D_];     // attn readout (half)
__device__ __half g_x1h [MTOK * D_];     // LN1 out (half: FFN1 A + LN2 residual)
__device__ __half g_hh  [MTOK * FF_];    // ffn hidden (half)
__device__ float  g_kvpart[NCH * 32 * 1024];
__device__ float  g_kspart[NCH * 32 * 32];
__device__ __half g_kvh[32 * 32 * 40];   // [bh][d][40] half, ldmatrix pitch
__device__ float  g_ksum[32 * 32];
// transposed weights [N,K] row-major, half
__device__ __half g_wqkvT[768 * D_];
__device__ __half g_woT[D_ * D_];
__device__ __half g_w1T[FF_ * D_];
__device__ __half g_w2T[D_ * FF_];
__device__ float  g_bqkv[768];

// ---------------- helpers ----------------
__device__ __forceinline__ uint32_t smem_u32(const void* p) {
    uint32_t a;
    asm("{ .reg .u64 t; cvta.to.shared.u64 t, %1; cvt.u32.u64 %0, t; }" : "=r"(a) : "l"(p));
    return a;
}
__device__ __forceinline__ void cp16(uint32_t dst, const void* src) {
    asm volatile("cp.async.cg.shared.global [%0], [%1], 16;" :: "r"(dst), "l"(src));
}
__device__ __forceinline__ void mma16(float* c, uint32_t a0, uint32_t a1,
                                      uint32_t a2, uint32_t a3,
                                      uint32_t b0, uint32_t b1) {
    asm volatile("mma.sync.aligned.m16n8k16.row.col.f32.f16.f16.f32 "
        "{%0,%1,%2,%3}, {%4,%5,%6,%7}, {%8,%9}, {%0,%1,%2,%3};"
        : "+f"(c[0]), "+f"(c[1]), "+f"(c[2]), "+f"(c[3])
        : "r"(a0), "r"(a1), "r"(a2), "r"(a3), "r"(b0), "r"(b1));
}
#define LDMX4T(r, addr) \
    asm volatile("ldmatrix.sync.aligned.m8n8.x4.trans.shared.b16 {%0,%1,%2,%3}, [%4];" \
        : "=r"((r)[0]), "=r"((r)[1]), "=r"((r)[2]), "=r"((r)[3]) : "r"(addr))
#define LDMX4(r, addr) \
    asm volatile("ldmatrix.sync.aligned.m8n8.x4.shared.b16 {%0,%1,%2,%3}, [%4];" \
        : "=r"((r)[0]), "=r"((r)[1]), "=r"((r)[2]), "=r"((r)[3]) : "r"(addr))

// ============================================================================
// x -> half copy
// ============================================================================
__global__ __launch_bounds__(512) void k_cvtx(const float* __restrict__ x)
{
    int i = blockIdx.x * 512 + threadIdx.x;
    float4 v = *(const float4*)&x[(size_t)i * 4];
    __half2 h0 = __floats2half2_rn(v.x, v.y);
    __half2 h1 = __floats2half2_rn(v.z, v.w);
    *(uint2*)&g_xh[(size_t)i * 4] = make_uint2(*(uint32_t*)&h0, *(uint32_t*)&h1);
}

// ============================================================================
// ALL weight transposes + bias concat in ONE launch.
// ============================================================================
__global__ void k_trall(const float* __restrict__ Wq, const float* __restrict__ Wk,
                        const float* __restrict__ Wv, const float* __restrict__ Wo,
                        const float* __restrict__ W1, const float* __restrict__ W2,
                        const float* __restrict__ bq, const float* __restrict__ bk,
                        const float* __restrict__ bv)
{
    const int bid = blockIdx.x;
    if (bid == 768) {
        int t = threadIdx.y * 32 + threadIdx.x;
        g_bqkv[t] = bq[t]; g_bqkv[256 + t] = bk[t]; g_bqkv[512 + t] = bv[t];
        return;
    }
    const float* W; __half* Wt; int K, N, idx;
    if (bid < 256) {
        idx = bid & 63; K = D_; N = D_;
        int sel = bid >> 6;
        W  = (sel == 0) ? Wq : (sel == 1) ? Wk : (sel == 2) ? Wv : Wo;
        Wt = (sel == 0) ? g_wqkvT : (sel == 1) ? g_wqkvT + 256 * D_
           : (sel == 2) ? g_wqkvT + 512 * D_ : g_woT;
    } else if (bid < 512) {
        idx = bid - 256; K = D_; N = FF_; W = W1; Wt = g_w1T;
    } else {
        idx = bid - 512; K = FF_; N = D_; W = W2; Wt = g_w2T;
    }
    const int xt = N >> 5;
    const int n0 = (idx % xt) * 32, k0 = (idx / xt) * 32;

    __shared__ float t[32][33];
    int x = threadIdx.x, y = threadIdx.y;
    for (int i = y; i < 32; i += 8) t[i][x] = W[(size_t)(k0 + i) * N + n0 + x];
    __syncthreads();
    for (int i = y; i < 32; i += 8)
        Wt[(size_t)(n0 + i) * K + k0 + x] = __float2half(t[x][i]);
}

// ============================================================================
// fp16 mma.sync GEMM (BN=128, 256 thr, 4-stage).
// ACT: 2 relu -> Out (g_hh) | 3 QKV: phi for q,k, head-major scatter.
// ============================================================================
__device__ __forceinline__ void stage256(const __half* __restrict__ Ap,
                                         const __half* __restrict__ Bp,
                                         int K, uint32_t sa, uint32_t sb, int tid)
{
#pragma unroll
    for (int t = 0; t < 2; t++) {
        int i = tid + t * 256;
        int row = i >> 2, c = i & 3;
        cp16(sa + row * 96 + c * 16, Ap + (size_t)row * K + c * 8);
    }
#pragma unroll
    for (int t = 0; t < 2; t++) {
        int i = tid + t * 256;
        int row = i >> 2, c = i & 3;
        cp16(sb + row * 96 + c * 16, Bp + (size_t)row * K + c * 8);
    }
}

template <int ACT>
__global__ __launch_bounds__(256, 2) void k_gemm(
    const __half* __restrict__ A, const __half* __restrict__ Bt,
    const float* __restrict__ bias, __half* __restrict__ Out,
    int K, int Nout)
{
    extern __shared__ __half smh[];
    const int tid  = threadIdx.x;
    const int wid  = tid >> 5;
    const int lane = tid & 31;
    const int g = lane >> 2, t = lane & 3;
    const int wm = wid & 3, wn = wid >> 2;
    const int m0 = blockIdx.y * 128;
    const int n0 = blockIdx.x * 128;
    const int NC = K >> 5;

    uint32_t uA[4], uB[4];
#pragma unroll
    for (int s = 0; s < 4; s++) {
        uA[s] = smem_u32(smh + s * 6144);
        uB[s] = smem_u32(smh + 24576 + s * 6144);
    }

    float c[2][8][4] = {};
    const __half* Abase = A + (size_t)m0 * K;
    const __half* Bbase = Bt + (size_t)n0 * K;

    stage256(Abase,      Bbase,      K, uA[0], uB[0], tid);
    asm volatile("cp.async.commit_group;");
    stage256(Abase + 32, Bbase + 32, K, uA[1], uB[1], tid);
    asm volatile("cp.async.commit_group;");
    stage256(Abase + 64, Bbase + 64, K, uA[2], uB[2], tid);
    asm volatile("cp.async.commit_group;");

    for (int cc = 0; cc < NC; cc++) {
        if (cc + 2 < NC)      asm volatile("cp.async.wait_group 2;");
        else if (cc + 1 < NC) asm volatile("cp.async.wait_group 1;");
        else                  asm volatile("cp.async.wait_group 0;");
        __syncthreads();
        if (cc + 3 < NC) {
            const int bs = (cc + 3) & 3;
            stage256(Abase + (cc + 3) * 32, Bbase + (cc + 3) * 32, K, uA[bs], uB[bs], tid);
            asm volatile("cp.async.commit_group;");
        }
        const int cur = cc & 3;
        const __half* a_s = smh + cur * 6144;
        const __half* b_s = smh + 24576 + cur * 6144;
#pragma unroll
        for (int s = 0; s < 2; s++) {
            uint2 va[2][2];
#pragma unroll
            for (int i = 0; i < 2; i++) {
                const int rb = (2 * wm + i) * 16;
                va[i][0] = *(const uint2*)&a_s[(rb + g)     * 48 + s * 16 + 4 * t];
                va[i][1] = *(const uint2*)&a_s[(rb + g + 8) * 48 + s * 16 + 4 * t];
            }
            uint2 vb[8];
#pragma unroll
            for (int j = 0; j < 8; j++) {
                const int n = (wn * 8 + j) * 8 + g;
                vb[j] = *(const uint2*)&b_s[n * 48 + s * 16 + 4 * t];
            }
#pragma unroll
            for (int i = 0; i < 2; i++)
#pragma unroll
                for (int j = 0; j < 8; j++)
                    mma16(c[i][j], va[i][0].x, va[i][1].x, va[i][0].y, va[i][1].y,
                          vb[j].x, vb[j].y);
        }
    }

    const bool do_phi = (ACT == 3) && (n0 < 512);
#pragma unroll
    for (int j = 0; j < 8; j++) {
        const int col = n0 + (wn * 8 + j) * 8 + t * 2;
        const float b0 = __ldg(&bias[col]);
        const float b1 = __ldg(&bias[col + 1]);
#pragma unroll
        for (int i = 0; i < 2; i++) {
            const int r0 = m0 + (2 * wm + i) * 16 + g;
            float v0 = c[i][j][0] + b0, v1 = c[i][j][1] + b1;
            float v2 = c[i][j][2] + b0, v3 = c[i][j][3] + b1;
            if (do_phi) {
                v0 = (v0 > 0.f) ? (v0 + 1.f) : expf(v0);
                v1 = (v1 > 0.f) ? (v1 + 1.f) : expf(v1);
                v2 = (v2 > 0.f) ? (v2 + 1.f) : expf(v2);
                v3 = (v3 > 0.f) ? (v3 + 1.f) : expf(v3);
            }
            if (ACT == 2) {
                v0 = fmaxf(v0, 0.f); v1 = fmaxf(v1, 0.f);
                v2 = fmaxf(v2, 0.f); v3 = fmaxf(v3, 0.f);
            }
            __half2 h0 = __floats2half2_rn(v0, v1);
            __half2 h1 = __floats2half2_rn(v2, v3);
            if (ACT == 3) {
                if (n0 < 256) {
                    *(__half2*)&g_qh[(size_t)r0 * D_ + col]       = h0;
                    *(__half2*)&g_qh[(size_t)(r0 + 8) * D_ + col] = h1;
                } else {
                    __half* dst = (n0 < 512) ? g_kh : g_vh;
                    const int colr = col & 255;
                    const int head = colr >> 5, e = colr & 31;
                    const int b = r0 >> 14, l = r0 & (L_ - 1);
                    const size_t base0 = ((size_t)(b * 8 + head) * L_ + l) * 32 + e;
                    *(__half2*)&dst[base0]          = h0;
                    *(__half2*)&dst[base0 + 8 * 32] = h1;
                }
            } else {
                *(__half2*)&Out[(size_t)r0 * Nout + col]       = h0;
                *(__half2*)&Out[(size_t)(r0 + 8) * Nout + col] = h1;
            }
        }
    }
}

// ============================================================================
// fp16 GEMM (BM=64, BN=256, 256 thr, 3-stage, 2 CTAs/SM) + bias + HALF
// residual + LayerNorm fused.
// ============================================================================
#define LNPITCH 264

template <int FINAL>
__global__ __launch_bounds__(256, 2) void k_gemm_ln(
    const __half* __restrict__ A, const __half* __restrict__ Bt,
    const float* __restrict__ bias, const __half* __restrict__ res,
    const float* __restrict__ lg, const float* __restrict__ lb,
    float* __restrict__ o, __half* __restrict__ oh, int K)
{
    extern __shared__ __half smh[];
    const int tid  = threadIdx.x;
    const int wid  = tid >> 5;
    const int lane = tid & 31;
    const int g = lane >> 2, t = lane & 3;
    const int wm = wid & 1, wn = wid >> 1;
    const int m0 = blockIdx.x * 64;
    const int NC = K >> 5;

    uint32_t uA[3], uB[3];
#pragma unroll
    for (int s = 0; s < 3; s++) {
        uA[s] = smem_u32(smh + s * 3072);
        uB[s] = smem_u32(smh + 9216 + s * 12288);
    }

    float c[2][8][4] = {};
    const __half* Abase = A + (size_t)m0 * K;

    auto stage = [&](int chunk, int s) {
        const __half* Ap = Abase + chunk * 32;
        const __half* Bp = Bt + chunk * 32;
        {
            int row = tid >> 2, c4 = tid & 3;
            cp16(uA[s] + row * 96 + c4 * 16, Ap + (size_t)row * K + c4 * 8);
        }
#pragma unroll
        for (int tt = 0; tt < 4; tt++) {
            int i = tid + tt * 256;
            int row = i >> 2, c4 = i & 3;
            cp16(uB[s] + row * 96 + c4 * 16, Bp + (size_t)row * K + c4 * 8);
        }
    };

    stage(0, 0);
    asm volatile("cp.async.commit_group;");
    stage(1, 1);
    asm volatile("cp.async.commit_group;");

    for (int cc = 0; cc < NC; cc++) {
        if (cc + 1 < NC) asm volatile("cp.async.wait_group 1;");
        else             asm volatile("cp.async.wait_group 0;");
        __syncthreads();
        if (cc + 2 < NC) {
            stage(cc + 2, (cc + 2) % 3);
            asm volatile("cp.async.commit_group;");
        }
        const int cur = cc % 3;
        const __half* a_s = smh + cur * 3072;
        const __half* b_s = smh + 9216 + cur * 12288;
#pragma unroll
        for (int s = 0; s < 2; s++) {
            uint2 va[2][2];
#pragma unroll
            for (int i = 0; i < 2; i++) {
                const int rb = (2 * wm + i) * 16;
                va[i][0] = *(const uint2*)&a_s[(rb + g)     * 48 + s * 16 + 4 * t];
                va[i][1] = *(const uint2*)&a_s[(rb + g + 8) * 48 + s * 16 + 4 * t];
            }
            uint2 vb[8];
#pragma unroll
            for (int j = 0; j < 8; j++)
                vb[j] = *(const uint2*)&b_s[(wn * 64 + j * 8 + g) * 48 + s * 16 + 4 * t];
#pragma unroll
            for (int i = 0; i < 2; i++)
#pragma unroll
                for (int j = 0; j < 8; j++)
                    mma16(c[i][j], va[i][0].x, va[i][1].x, va[i][0].y, va[i][1].y,
                          vb[j].x, vb[j].y);
        }
    }
    __syncthreads();

    float* se = (float*)smh;
#pragma unroll
    for (int j = 0; j < 8; j++) {
        const int col = wn * 64 + j * 8 + t * 2;
        const float b0 = __ldg(&bias[col]);
        const float b1 = __ldg(&bias[col + 1]);
#pragma unroll
        for (int i = 0; i < 2; i++) {
            const int r = (2 * wm + i) * 16 + g;
            *(float2*)&se[r * LNPITCH + col] = make_float2(c[i][j][0] + b0, c[i][j][1] + b1);
            *(float2*)&se[(r + 8) * LNPITCH + col] = make_float2(c[i][j][2] + b0, c[i][j][3] + b1);
        }
    }
    __syncthreads();

#pragma unroll
    for (int rr = 0; rr < 8; rr++) {
        const int row = wid * 8 + rr;
        const size_t rb = (size_t)(m0 + row) * D_;
        float vals[8];
        float sum = 0.f, sq = 0.f;
#pragma unroll
        for (int i = 0; i < 8; i++) {
            float v = se[row * LNPITCH + lane + i * 32]
                    + __half2float(res[rb + lane + i * 32]);
            vals[i] = v; sum += v; sq += v * v;
        }
#pragma unroll
        for (int off = 16; off > 0; off >>= 1) {
            sum += __shfl_xor_sync(0xffffffffu, sum, off);
            sq  += __shfl_xor_sync(0xffffffffu, sq,  off);
        }
        float mu  = sum * (1.f / 256.f);
        float var = sq * (1.f / 256.f) - mu * mu;
        float rs  = rsqrtf(var + 1e-5f);
#pragma unroll
        for (int i = 0; i < 8; i++) {
            const int col = lane + i * 32;
            float v = (vals[i] - mu) * rs * lg[col] + lb[col];
            if (FINAL) o[rb + col] = v;
            else       oh[rb + col] = __float2half(v);
        }
    }
}

// ============================================================================
// kv reduction via tensor cores; k/v dense head-major [(bh)][L][32].
// ============================================================================
__global__ __launch_bounds__(256) void k_kvred()
{
    extern __shared__ __half sred[];
    const int bh = blockIdx.x;
    const int ch = blockIdx.y;
    const int w = threadIdx.x >> 5, lane = threadIdx.x & 31;
    const int g = lane >> 2, t = lane & 3;

    __half* k_s = sred + w * 5120;
    const uint32_t uk = smem_u32(k_s);
    const uint32_t uv = uk + 2560 * 2;

    const int tok0 = ch * CHTOK + w * 64;
    const __half* kg = g_kh + ((size_t)bh * L_ + tok0) * 32;
    const __half* vg = g_vh + ((size_t)bh * L_ + tok0) * 32;

#pragma unroll
    for (int it = 0; it < 8; it++) {
        int i = lane + it * 32;
        int tok = i >> 2, c4 = i & 3;
        cp16(uk + tok * 80 + c4 * 16, kg + (size_t)i * 8);
        cp16(uv + tok * 80 + c4 * 16, vg + (size_t)i * 8);
    }
    asm volatile("cp.async.commit_group;");
    asm volatile("cp.async.wait_group 0;");
    __syncwarp();

    float acc[2][4][4] = {};
    float cs[2][4] = {};
    const uint32_t ones2 = 0x3C003C00u;

    const int tokA = (lane & 7) + ((lane >> 4) << 3);
    const int dA   = ((lane >> 3) & 1) * 8;
    const int tokB = (lane & 7) + (((lane >> 3) & 1) << 3);
    const int eB   = ((lane >> 4) & 1) * 8;

#pragma unroll
    for (int st = 0; st < 64; st += 16) {
        uint32_t a[2][4], bb[2][4];
#pragma unroll
        for (int mi = 0; mi < 2; mi++)
            LDMX4T(a[mi], uk + (st + tokA) * 80 + (mi * 16 + dA) * 2);
#pragma unroll
        for (int np = 0; np < 2; np++)
            LDMX4T(bb[np], uv + (st + tokB) * 80 + (np * 16 + eB) * 2);
#pragma unroll
        for (int mi = 0; mi < 2; mi++) {
#pragma unroll
            for (int nb = 0; nb < 4; nb++) {
                const int np = nb >> 1, hi = nb & 1;
                mma16(acc[mi][nb], a[mi][0], a[mi][1], a[mi][2], a[mi][3],
                      bb[np][hi * 2], bb[np][hi * 2 + 1]);
            }
            mma16(cs[mi], a[mi][0], a[mi][1], a[mi][2], a[mi][3], ones2, ones2);
        }
    }
    __syncthreads();

    float* s_part = (float*)sred;
    float* s_ksp  = s_part + 8 * 1024;
#pragma unroll
    for (int mi = 0; mi < 2; mi++) {
#pragma unroll
        for (int nb = 0; nb < 4; nb++) {
            const int d0 = mi * 16 + g, e0 = nb * 8 + 2 * t;
            *(float2*)&s_part[w * 1024 + d0 * 32 + e0] =
                make_float2(acc[mi][nb][0], acc[mi][nb][1]);
            *(float2*)&s_part[w * 1024 + (d0 + 8) * 32 + e0] =
                make_float2(acc[mi][nb][2], acc[mi][nb][3]);
        }
        if (t == 0) {
            s_ksp[w * 32 + mi * 16 + g]     = cs[mi][0];
            s_ksp[w * 32 + mi * 16 + g + 8] = cs[mi][2];
        }
    }
    __syncthreads();

    const int tid = threadIdx.x;
    for (int j = tid; j < 1024; j += 256) {
        float s = 0.f;
#pragma unroll
        for (int ww = 0; ww < 8; ww++) s += s_part[ww * 1024 + j];
        g_kvpart[((size_t)ch * 32 + bh) * 1024 + j] = s;
    }
    if (tid < 32) {
        float s = 0.f;
#pragma unroll
        for (int ww = 0; ww < 8; ww++) s += s_ksp[ww * 32 + tid];
        g_kspart[(ch * 32 + bh) * 32 + tid] = s;
    }
}

// kvfin: final chunk reduction; kv -> HALF pitch-40 layout, ksum stays f32.
__global__ __launch_bounds__(256) void k_kvfin()
{
    const int bh = blockIdx.x;
    for (int j = threadIdx.x; j < 1024; j += 256) {
        float s = 0.f;
#pragma unroll
        for (int c = 0; c < NCH; c++) s += g_kvpart[((size_t)c * 32 + bh) * 1024 + j];
        const int d = j >> 5, e = j & 31;
        g_kvh[(size_t)bh * 1280 + d * 40 + e] = __float2half(s);
    }
    if (threadIdx.x < 32) {
        float s = 0.f;
#pragma unroll
        for (int c = 0; c < NCH; c++) s += g_kspart[(c * 32 + bh) * 32 + threadIdx.x];
        g_ksum[bh * 32 + threadIdx.x] = s;
    }
}

// ============================================================================
// attention readout via tensor cores.  Warp h computes C[32,32] = Q_h @ KV_h,
// scaled by z.  smem: q half [32][264] | kv half 8x[32][40] | ksum,z f32.
// ============================================================================
__global__ __launch_bounds__(256) void k_attnread(__half* __restrict__ outa)
{
    extern __shared__ __half sma[];
    __half* s_q  = sma;                       // 8448 halves (pitch 264)
    __half* s_kv = sma + 8448;                // 10240 halves (8 heads x 32 x 40)
    float*  s_ks = (float*)(sma + 18688);     // 256
    float*  s_z  = s_ks + 256;                // 256 ([r*8+h])

    const int tid  = threadIdx.x;
    const int lane = tid & 31;
    const int h    = tid >> 5;                // warp = head
    const int tok0 = blockIdx.x * 32;
    const int b    = tok0 >> 14;

    const uint32_t uq  = smem_u32(s_q);
    const uint32_t ukv = smem_u32(s_kv);

#pragma unroll
    for (int t = 0; t < 4; t++) {             // q: 1024 cp16
        int i = tid + t * 256;
        int r = i >> 5, c = i & 31;
        cp16(uq + r * 528 + c * 16, g_qh + (size_t)(tok0 + r) * D_ + c * 8);
    }
#pragma unroll
    for (int t = 0; t < 5; t++) {             // kv: 1280 cp16 (dense copy)
        int i = tid + t * 256;
        cp16(ukv + i * 16, g_kvh + (size_t)b * 10240 + i * 8);
    }
    if (tid < 64)
        cp16(smem_u32(s_ks) + tid * 16, g_ksum + b * 256 + tid * 4);
    asm volatile("cp.async.commit_group;");
    asm volatile("cp.async.wait_group 0;");
    __syncthreads();

    {   // z[r][h] = 1/(q . ksum + 1e-6)
        int r = tid & 31, hh = tid >> 5;
        float s = 0.f;
#pragma unroll
        for (int d2 = 0; d2 < 16; d2++) {
            float2 f = __half22float2(*(__half2*)&s_q[r * 264 + hh * 32 + d2 * 2]);
            s += f.x * s_ks[hh * 32 + d2 * 2] + f.y * s_ks[hh * 32 + d2 * 2 + 1];
        }
        s_z[r * 8 + hh] = 1.f / (s + 1e-6f);
    }
    __syncthreads();

    // fragments
    const int lr = lane & 15, lc = lane >> 4;
    uint32_t a[2][2][4];                      // [mi][ks]
#pragma unroll
    for (int mi = 0; mi < 2; mi++)
#pragma unroll
        for (int ks = 0; ks < 2; ks++)
            LDMX4(a[mi][ks], uq + (mi * 16 + lr) * 528 + (h * 32 + ks * 16 + lc * 8) * 2);

    uint32_t bb[2][2][4];                     // [ks][eh]
#pragma unroll
    for (int ks = 0; ks < 2; ks++)
#pragma unroll
        for (int eh = 0; eh < 2; eh++)
            LDMX4T(bb[ks][eh], ukv + (h * 32 + ks * 16 + lr) * 80 + (eh * 16 + lc * 8) * 2);

    float c[2][4][4] = {};
#pragma unroll
    for (int mi = 0; mi < 2; mi++)
#pragma unroll
        for (int nb = 0; nb < 4; nb++) {
            const int eh = nb >> 1, hi = nb & 1;
#pragma unroll
            for (int ks = 0; ks < 2; ks++)
                mma16(c[mi][nb], a[mi][ks][0], a[mi][ks][1], a[mi][ks][2], a[mi][ks][3],
                      bb[ks][eh][hi * 2], bb[ks][eh][hi * 2 + 1]);
        }

    // epilogue: scale by z, store half2
    const int g = lane >> 2, t = lane & 3;
#pragma unroll
    for (int mi = 0; mi < 2; mi++) {
        const int r0 = mi * 16 + g;
        const float z0 = s_z[r0 * 8 + h];
        const float z1 = s_z[(r0 + 8) * 8 + h];
#pragma unroll
        for (int nb = 0; nb < 4; nb++) {
            const int col = h * 32 + nb * 8 + 2 * t;
            __half2 h0 = __floats2half2_rn(c[mi][nb][0] * z0, c[mi][nb][1] * z0);
            __half2 h1 = __floats2half2_rn(c[mi][nb][2] * z1, c[mi][nb][3] * z1);
            *(__half2*)&outa[(size_t)(tok0 + r0) * D_ + col]     = h0;
            *(__half2*)&outa[(size_t)(tok0 + r0 + 8) * D_ + col] = h1;
        }
    }
}

// ============================================================================
extern "C" void kernel_launch(void* const* d_in, const int* in_sizes, int n_in,
                              void* d_out, int out_size)
{
    const float* x    = (const float*)d_in[0];
    const float* Wq   = (const float*)d_in[1];
    const float* bq   = (const float*)d_in[2];
    const float* Wk   = (const float*)d_in[3];
    const float* bk   = (const float*)d_in[4];
    const float* Wv   = (const float*)d_in[5];
    const float* bv   = (const float*)d_in[6];
    const float* Wo   = (const float*)d_in[7];
    const float* bo   = (const float*)d_in[8];
    const float* W1   = (const float*)d_in[9];
    const float* b1   = (const float*)d_in[10];
    const float* W2   = (const float*)d_in[11];
    const float* b2   = (const float*)d_in[12];
    const float* ln1g = (const float*)d_in[13];
    const float* ln1b = (const float*)d_in[14];
    const float* ln2g = (const float*)d_in[15];
    const float* ln2b = (const float*)d_in[16];
    float* out = (float*)d_out;

    __half *xh, *ah, *x1h, *hh, *wqkvT, *woT, *w1T, *w2T;
    float *bqkv;
    cudaGetSymbolAddress((void**)&xh,    g_xh);
    cudaGetSymbolAddress((void**)&ah,    g_ah);
    cudaGetSymbolAddress((void**)&x1h,   g_x1h);
    cudaGetSymbolAddress((void**)&hh,    g_hh);
    cudaGetSymbolAddress((void**)&wqkvT, g_wqkvT);
    cudaGetSymbolAddress((void**)&woT,   g_woT);
    cudaGetSymbolAddress((void**)&w1T,   g_w1T);
    cudaGetSymbolAddress((void**)&w2T,   g_w2T);
    cudaGetSymbolAddress((void**)&bqkv,  g_bqkv);

    const int GSM   = 98304;               // k_gemm 4-stage
    const int GSMLN = 92160;               // k_gemm_ln 3-stage BM=64 (2 CTA/SM)
    const int GSMKV = 8 * 5120 * 2;        // 81920
    const int GSMAR = 18688 * 2 + 512 * 4; // 39424: q + kv halves + ksum/z f32
    cudaFuncSetAttribute((k_gemm<2>), cudaFuncAttributeMaxDynamicSharedMemorySize, GSM);
    cudaFuncSetAttribute((k_gemm<3>), cudaFuncAttributeMaxDynamicSharedMemorySize, GSM);
    cudaFuncSetAttribute((k_gemm_ln<0>), cudaFuncAttributeMaxDynamicSharedMemorySize, GSMLN);
    cudaFuncSetAttribute((k_gemm_ln<1>), cudaFuncAttributeMaxDynamicSharedMemorySize, GSMLN);
    cudaFuncSetAttribute(k_kvred, cudaFuncAttributeMaxDynamicSharedMemorySize, GSMKV);
    cudaFuncSetAttribute(k_attnread, cudaFuncAttributeMaxDynamicSharedMemorySize, GSMAR);

    k_cvtx<<<MTOK * D_ / 4 / 512, 512>>>(x);
    k_trall<<<769, dim3(32, 8)>>>(Wq, Wk, Wv, Wo, W1, W2, bq, bk, bv);

    // merged QKV projection: phi for q,k; head-major scatter for k,v
    k_gemm<3><<<dim3(6, 512), 256, GSM>>>(xh, wqkvT, bqkv, nullptr, D_, 768);

    k_kvred<<<dim3(32, NCH), 256, GSMKV>>>();
    k_kvfin<<<32, 256>>>();
    k_attnread<<<MTOK / 32, 256, GSMAR>>>(ah);

    // Wo projection + half residual (xh) + LN1 -> x1h (half only)
    k_gemm_ln<0><<<1024, 256, GSMLN>>>(ah, woT, bo, xh, ln1g, ln1b, nullptr, x1h, D_);

    // FFN1 (relu), half out
    k_gemm<2><<<dim3(8, 512), 256, GSM>>>(x1h, w1T, b1, hh, D_, FF_);

    // FFN2 + half residual (x1h) + LN2 -> out (f32)
    k_gemm_ln<1><<<1024, 256, GSMLN>>>(hh, w2T, b2, x1h, ln2g, ln2b, out, nullptr, FF_);
}

// round 16
// speedup vs baseline: 1.2665x; 1.0126x over previous
#include <cuda_runtime.h>
#include <cuda_fp16.h>
#include <math.h>
#include <stdint.h>

#define B_    4
#define L_    16384
#define D_    256
#define H_    8
#define DH_   32
#define FF_   1024
#define MTOK  65536
#define NCH   32
#define CHTOK 512

// ---------------- scratch ----------------
__device__ __half g_xh  [MTOK * D_];     // x as half (QKV A + LN1 residual)
__device__ __half g_qh  [MTOK * D_];     // q_phi, [tok][256]
__device__ __half g_kh  [MTOK * D_];     // k_phi, [(b*8+h)][L][32]
__device__ __half g_vh  [MTOK * D_];     // v,     [(b*8+h)][L][32]
__device__ __half g_x1h [MTOK * D_];     // LN1 out (half: FFN1 A + LN2 residual)
__device__ __half g_hh  [MTOK * FF_];    // ffn hidden (half)
__device__ float  g_kvpart[NCH * 32 * 1024];
__device__ float  g_kspart[NCH * 32 * 32];
__device__ __half g_kvh[32 * 32 * 40];   // [bh][d][40] half, ldmatrix pitch
__device__ float  g_ksum[32 * 32];
// transposed weights [N,K] row-major, half
__device__ __half g_wqkvT[768 * D_];
__device__ __half g_woT[D_ * D_];
__device__ __half g_w1T[FF_ * D_];
__device__ __half g_w2T[D_ * FF_];
__device__ float  g_bqkv[768];

// ---------------- helpers ----------------
__device__ __forceinline__ uint32_t smem_u32(const void* p) {
    uint32_t a;
    asm("{ .reg .u64 t; cvta.to.shared.u64 t, %1; cvt.u32.u64 %0, t; }" : "=r"(a) : "l"(p));
    return a;
}
__device__ __forceinline__ void cp16(uint32_t dst, const void* src) {
    asm volatile("cp.async.cg.shared.global [%0], [%1], 16;" :: "r"(dst), "l"(src));
}
__device__ __forceinline__ void mma16(float* c, uint32_t a0, uint32_t a1,
                                      uint32_t a2, uint32_t a3,
                                      uint32_t b0, uint32_t b1) {
    asm volatile("mma.sync.aligned.m16n8k16.row.col.f32.f16.f16.f32 "
        "{%0,%1,%2,%3}, {%4,%5,%6,%7}, {%8,%9}, {%0,%1,%2,%3};"
        : "+f"(c[0]), "+f"(c[1]), "+f"(c[2]), "+f"(c[3])
        : "r"(a0), "r"(a1), "r"(a2), "r"(a3), "r"(b0), "r"(b1));
}
#define LDMX4T(r, addr) \
    asm volatile("ldmatrix.sync.aligned.m8n8.x4.trans.shared.b16 {%0,%1,%2,%3}, [%4];" \
        : "=r"((r)[0]), "=r"((r)[1]), "=r"((r)[2]), "=r"((r)[3]) : "r"(addr))
#define LDMX4(r, addr) \
    asm volatile("ldmatrix.sync.aligned.m8n8.x4.shared.b16 {%0,%1,%2,%3}, [%4];" \
        : "=r"((r)[0]), "=r"((r)[1]), "=r"((r)[2]), "=r"((r)[3]) : "r"(addr))

// ============================================================================
// x -> half copy
// ============================================================================
__global__ __launch_bounds__(512) void k_cvtx(const float* __restrict__ x)
{
    int i = blockIdx.x * 512 + threadIdx.x;
    float4 v = *(const float4*)&x[(size_t)i * 4];
    __half2 h0 = __floats2half2_rn(v.x, v.y);
    __half2 h1 = __floats2half2_rn(v.z, v.w);
    *(uint2*)&g_xh[(size_t)i * 4] = make_uint2(*(uint32_t*)&h0, *(uint32_t*)&h1);
}

// ============================================================================
// ALL weight transposes + bias concat in ONE launch.
// ============================================================================
__global__ void k_trall(const float* __restrict__ Wq, const float* __restrict__ Wk,
                        const float* __restrict__ Wv, const float* __restrict__ Wo,
                        const float* __restrict__ W1, const float* __restrict__ W2,
                        const float* __restrict__ bq, const float* __restrict__ bk,
                        const float* __restrict__ bv)
{
    const int bid = blockIdx.x;
    if (bid == 768) {
        int t = threadIdx.y * 32 + threadIdx.x;
        g_bqkv[t] = bq[t]; g_bqkv[256 + t] = bk[t]; g_bqkv[512 + t] = bv[t];
        return;
    }
    const float* W; __half* Wt; int K, N, idx;
    if (bid < 256) {
        idx = bid & 63; K = D_; N = D_;
        int sel = bid >> 6;
        W  = (sel == 0) ? Wq : (sel == 1) ? Wk : (sel == 2) ? Wv : Wo;
        Wt = (sel == 0) ? g_wqkvT : (sel == 1) ? g_wqkvT + 256 * D_
           : (sel == 2) ? g_wqkvT + 512 * D_ : g_woT;
    } else if (bid < 512) {
        idx = bid - 256; K = D_; N = FF_; W = W1; Wt = g_w1T;
    } else {
        idx = bid - 512; K = FF_; N = D_; W = W2; Wt = g_w2T;
    }
    const int xt = N >> 5;
    const int n0 = (idx % xt) * 32, k0 = (idx / xt) * 32;

    __shared__ float t[32][33];
    int x = threadIdx.x, y = threadIdx.y;
    for (int i = y; i < 32; i += 8) t[i][x] = W[(size_t)(k0 + i) * N + n0 + x];
    __syncthreads();
    for (int i = y; i < 32; i += 8)
        Wt[(size_t)(n0 + i) * K + k0 + x] = __float2half(t[x][i]);
}

// ============================================================================
// fp16 mma.sync GEMM (BN=128, 256 thr, 4-stage).
// ACT: 2 relu -> Out (g_hh) | 3 QKV: phi for q,k, head-major scatter.
// ============================================================================
__device__ __forceinline__ void stage256(const __half* __restrict__ Ap,
                                         const __half* __restrict__ Bp,
                                         int K, uint32_t sa, uint32_t sb, int tid)
{
#pragma unroll
    for (int t = 0; t < 2; t++) {
        int i = tid + t * 256;
        int row = i >> 2, c = i & 3;
        cp16(sa + row * 96 + c * 16, Ap + (size_t)row * K + c * 8);
    }
#pragma unroll
    for (int t = 0; t < 2; t++) {
        int i = tid + t * 256;
        int row = i >> 2, c = i & 3;
        cp16(sb + row * 96 + c * 16, Bp + (size_t)row * K + c * 8);
    }
}

template <int ACT>
__global__ __launch_bounds__(256, 2) void k_gemm(
    const __half* __restrict__ A, const __half* __restrict__ Bt,
    const float* __restrict__ bias, __half* __restrict__ Out,
    int K, int Nout)
{
    extern __shared__ __half smh[];
    const int tid  = threadIdx.x;
    const int wid  = tid >> 5;
    const int lane = tid & 31;
    const int g = lane >> 2, t = lane & 3;
    const int wm = wid & 3, wn = wid >> 2;
    const int m0 = blockIdx.y * 128;
    const int n0 = blockIdx.x * 128;
    const int NC = K >> 5;

    uint32_t uA[4], uB[4];
#pragma unroll
    for (int s = 0; s < 4; s++) {
        uA[s] = smem_u32(smh + s * 6144);
        uB[s] = smem_u32(smh + 24576 + s * 6144);
    }

    float c[2][8][4] = {};
    const __half* Abase = A + (size_t)m0 * K;
    const __half* Bbase = Bt + (size_t)n0 * K;

    stage256(Abase,      Bbase,      K, uA[0], uB[0], tid);
    asm volatile("cp.async.commit_group;");
    stage256(Abase + 32, Bbase + 32, K, uA[1], uB[1], tid);
    asm volatile("cp.async.commit_group;");
    stage256(Abase + 64, Bbase + 64, K, uA[2], uB[2], tid);
    asm volatile("cp.async.commit_group;");

    for (int cc = 0; cc < NC; cc++) {
        if (cc + 2 < NC)      asm volatile("cp.async.wait_group 2;");
        else if (cc + 1 < NC) asm volatile("cp.async.wait_group 1;");
        else                  asm volatile("cp.async.wait_group 0;");
        __syncthreads();
        if (cc + 3 < NC) {
            const int bs = (cc + 3) & 3;
            stage256(Abase + (cc + 3) * 32, Bbase + (cc + 3) * 32, K, uA[bs], uB[bs], tid);
            asm volatile("cp.async.commit_group;");
        }
        const int cur = cc & 3;
        const __half* a_s = smh + cur * 6144;
        const __half* b_s = smh + 24576 + cur * 6144;
#pragma unroll
        for (int s = 0; s < 2; s++) {
            uint2 va[2][2];
#pragma unroll
            for (int i = 0; i < 2; i++) {
                const int rb = (2 * wm + i) * 16;
                va[i][0] = *(const uint2*)&a_s[(rb + g)     * 48 + s * 16 + 4 * t];
                va[i][1] = *(const uint2*)&a_s[(rb + g + 8) * 48 + s * 16 + 4 * t];
            }
            uint2 vb[8];
#pragma unroll
            for (int j = 0; j < 8; j++) {
                const int n = (wn * 8 + j) * 8 + g;
                vb[j] = *(const uint2*)&b_s[n * 48 + s * 16 + 4 * t];
            }
#pragma unroll
            for (int i = 0; i < 2; i++)
#pragma unroll
                for (int j = 0; j < 8; j++)
                    mma16(c[i][j], va[i][0].x, va[i][1].x, va[i][0].y, va[i][1].y,
                          vb[j].x, vb[j].y);
        }
    }

    const bool do_phi = (ACT == 3) && (n0 < 512);
#pragma unroll
    for (int j = 0; j < 8; j++) {
        const int col = n0 + (wn * 8 + j) * 8 + t * 2;
        const float b0 = __ldg(&bias[col]);
        const float b1 = __ldg(&bias[col + 1]);
#pragma unroll
        for (int i = 0; i < 2; i++) {
            const int r0 = m0 + (2 * wm + i) * 16 + g;
            float v0 = c[i][j][0] + b0, v1 = c[i][j][1] + b1;
            float v2 = c[i][j][2] + b0, v3 = c[i][j][3] + b1;
            if (do_phi) {
                v0 = (v0 > 0.f) ? (v0 + 1.f) : expf(v0);
                v1 = (v1 > 0.f) ? (v1 + 1.f) : expf(v1);
                v2 = (v2 > 0.f) ? (v2 + 1.f) : expf(v2);
                v3 = (v3 > 0.f) ? (v3 + 1.f) : expf(v3);
            }
            if (ACT == 2) {
                v0 = fmaxf(v0, 0.f); v1 = fmaxf(v1, 0.f);
                v2 = fmaxf(v2, 0.f); v3 = fmaxf(v3, 0.f);
            }
            __half2 h0 = __floats2half2_rn(v0, v1);
            __half2 h1 = __floats2half2_rn(v2, v3);
            if (ACT == 3) {
                if (n0 < 256) {
                    *(__half2*)&g_qh[(size_t)r0 * D_ + col]       = h0;
                    *(__half2*)&g_qh[(size_t)(r0 + 8) * D_ + col] = h1;
                } else {
                    __half* dst = (n0 < 512) ? g_kh : g_vh;
                    const int colr = col & 255;
                    const int head = colr >> 5, e = colr & 31;
                    const int b = r0 >> 14, l = r0 & (L_ - 1);
                    const size_t base0 = ((size_t)(b * 8 + head) * L_ + l) * 32 + e;
                    *(__half2*)&dst[base0]          = h0;
                    *(__half2*)&dst[base0 + 8 * 32] = h1;
                }
            } else {
                *(__half2*)&Out[(size_t)r0 * Nout + col]       = h0;
                *(__half2*)&Out[(size_t)(r0 + 8) * Nout + col] = h1;
            }
        }
    }
}

// ============================================================================
// fp16 GEMM (BM=64, BN=256, 256 thr, 3-stage, 2 CTAs/SM) + bias + HALF
// residual + LayerNorm fused.  (FFN2 path)
// ============================================================================
#define LNPITCH 264

template <int FINAL>
__global__ __launch_bounds__(256, 2) void k_gemm_ln(
    const __half* __restrict__ A, const __half* __restrict__ Bt,
    const float* __restrict__ bias, const __half* __restrict__ res,
    const float* __restrict__ lg, const float* __restrict__ lb,
    float* __restrict__ o, __half* __restrict__ oh, int K)
{
    extern __shared__ __half smh[];
    const int tid  = threadIdx.x;
    const int wid  = tid >> 5;
    const int lane = tid & 31;
    const int g = lane >> 2, t = lane & 3;
    const int wm = wid & 1, wn = wid >> 1;
    const int m0 = blockIdx.x * 64;
    const int NC = K >> 5;

    uint32_t uA[3], uB[3];
#pragma unroll
    for (int s = 0; s < 3; s++) {
        uA[s] = smem_u32(smh + s * 3072);
        uB[s] = smem_u32(smh + 9216 + s * 12288);
    }

    float c[2][8][4] = {};
    const __half* Abase = A + (size_t)m0 * K;

    auto stage = [&](int chunk, int s) {
        const __half* Ap = Abase + chunk * 32;
        const __half* Bp = Bt + chunk * 32;
        {
            int row = tid >> 2, c4 = tid & 3;
            cp16(uA[s] + row * 96 + c4 * 16, Ap + (size_t)row * K + c4 * 8);
        }
#pragma unroll
        for (int tt = 0; tt < 4; tt++) {
            int i = tid + tt * 256;
            int row = i >> 2, c4 = i & 3;
            cp16(uB[s] + row * 96 + c4 * 16, Bp + (size_t)row * K + c4 * 8);
        }
    };

    stage(0, 0);
    asm volatile("cp.async.commit_group;");
    stage(1, 1);
    asm volatile("cp.async.commit_group;");

    for (int cc = 0; cc < NC; cc++) {
        if (cc + 1 < NC) asm volatile("cp.async.wait_group 1;");
        else             asm volatile("cp.async.wait_group 0;");
        __syncthreads();
        if (cc + 2 < NC) {
            stage(cc + 2, (cc + 2) % 3);
            asm volatile("cp.async.commit_group;");
        }
        const int cur = cc % 3;
        const __half* a_s = smh + cur * 3072;
        const __half* b_s = smh + 9216 + cur * 12288;
#pragma unroll
        for (int s = 0; s < 2; s++) {
            uint2 va[2][2];
#pragma unroll
            for (int i = 0; i < 2; i++) {
                const int rb = (2 * wm + i) * 16;
                va[i][0] = *(const uint2*)&a_s[(rb + g)     * 48 + s * 16 + 4 * t];
                va[i][1] = *(const uint2*)&a_s[(rb + g + 8) * 48 + s * 16 + 4 * t];
            }
            uint2 vb[8];
#pragma unroll
            for (int j = 0; j < 8; j++)
                vb[j] = *(const uint2*)&b_s[(wn * 64 + j * 8 + g) * 48 + s * 16 + 4 * t];
#pragma unroll
            for (int i = 0; i < 2; i++)
#pragma unroll
                for (int j = 0; j < 8; j++)
                    mma16(c[i][j], va[i][0].x, va[i][1].x, va[i][0].y, va[i][1].y,
                          vb[j].x, vb[j].y);
        }
    }
    __syncthreads();

    float* se = (float*)smh;
#pragma unroll
    for (int j = 0; j < 8; j++) {
        const int col = wn * 64 + j * 8 + t * 2;
        const float b0 = __ldg(&bias[col]);
        const float b1 = __ldg(&bias[col + 1]);
#pragma unroll
        for (int i = 0; i < 2; i++) {
            const int r = (2 * wm + i) * 16 + g;
            *(float2*)&se[r * LNPITCH + col] = make_float2(c[i][j][0] + b0, c[i][j][1] + b1);
            *(float2*)&se[(r + 8) * LNPITCH + col] = make_float2(c[i][j][2] + b0, c[i][j][3] + b1);
        }
    }
    __syncthreads();

#pragma unroll
    for (int rr = 0; rr < 8; rr++) {
        const int row = wid * 8 + rr;
        const size_t rb = (size_t)(m0 + row) * D_;
        float vals[8];
        float sum = 0.f, sq = 0.f;
#pragma unroll
        for (int i = 0; i < 8; i++) {
            float v = se[row * LNPITCH + lane + i * 32]
                    + __half2float(res[rb + lane + i * 32]);
            vals[i] = v; sum += v; sq += v * v;
        }
#pragma unroll
        for (int off = 16; off > 0; off >>= 1) {
            sum += __shfl_xor_sync(0xffffffffu, sum, off);
            sq  += __shfl_xor_sync(0xffffffffu, sq,  off);
        }
        float mu  = sum * (1.f / 256.f);
        float var = sq * (1.f / 256.f) - mu * mu;
        float rs  = rsqrtf(var + 1e-5f);
#pragma unroll
        for (int i = 0; i < 8; i++) {
            const int col = lane + i * 32;
            float v = (vals[i] - mu) * rs * lg[col] + lb[col];
            if (FINAL) o[rb + col] = v;
            else       oh[rb + col] = __float2half(v);
        }
    }
}

// ============================================================================
// FUSED attention readout + Wo GEMM + bias + half residual + LN1 -> x1h.
// BM=64 tokens/CTA, 256 thr, 2 CTAs/SM.
// Prologue: stage q(64x264) + kv(8x32x40) + ksum; compute z; per-head warp
// tensor-core attn; write z-scaled A directly into smem in GEMM A-layout
// (chunk h = head h, natural k order, pitch 48).  A region aliases q/kv.
// Mainloop: Wo via 2-stage B pipeline, A from smem.
// smem halves: [0,27136) q+kv / A(24576) | [27136,51712) B 2x12288 |
//              [51712,52224) ksum f32 | [52224,53248) z f32   = 106496 B
// ============================================================================
__global__ __launch_bounds__(256, 2) void k_attn_ln(
    const __half* __restrict__ Bt, const float* __restrict__ bias,
    const __half* __restrict__ res, const float* __restrict__ lg,
    const float* __restrict__ lb, __half* __restrict__ oh)
{
    extern __shared__ __half smh[];
    __half* s_q  = smh;                    // 64 x 264
    __half* s_kv = smh + 16896;            // 10240
    __half* s_A  = smh;                    // 8 x 3072 (aliases q/kv)
    __half* s_B  = smh + 27136;            // 2 x 12288
    float*  s_ks = (float*)(smh + 51712);  // 256
    float*  s_z  = (float*)(smh + 52224);  // 512  ([r*8+h])

    const int tid  = threadIdx.x;
    const int wid  = tid >> 5;
    const int lane = tid & 31;
    const int g = lane >> 2, t = lane & 3;
    const int wm = wid & 1, wn = wid >> 1;   // mainloop: 2m x 4n
    const int tok0 = blockIdx.x * 64;
    const int b    = tok0 >> 14;

    const uint32_t uq  = smem_u32(s_q);
    const uint32_t ukv = smem_u32(s_kv);
    const uint32_t uB  = smem_u32(s_B);

    auto stageB = [&](int chunk, int s) {
#pragma unroll
        for (int tt = 0; tt < 4; tt++) {
            int i = tid + tt * 256;
            int row = i >> 2, c4 = i & 3;
            cp16(uB + s * 24576 + row * 96 + c4 * 16,
                 Bt + (size_t)row * D_ + chunk * 32 + c4 * 8);
        }
    };

    // ---- prologue staging ----
#pragma unroll
    for (int tt = 0; tt < 8; tt++) {          // q: 2048 cp16
        int i = tid + tt * 256;
        int r = i >> 5, c = i & 31;
        cp16(uq + r * 528 + c * 16, g_qh + (size_t)(tok0 + r) * D_ + c * 8);
    }
#pragma unroll
    for (int tt = 0; tt < 5; tt++) {          // kv: 1280 cp16
        int i = tid + tt * 256;
        cp16(ukv + i * 16, g_kvh + (size_t)b * 10240 + i * 8);
    }
    if (tid < 64)
        cp16(smem_u32(s_ks) + tid * 16, g_ksum + b * 256 + tid * 4);
    asm volatile("cp.async.commit_group;");   // g0: q/kv/ksum
    stageB(0, 0);
    asm volatile("cp.async.commit_group;");   // g1: B0
    asm volatile("cp.async.wait_group 1;");   // q/kv/ksum ready
    __syncthreads();

    // ---- z[r][h] = 1/(q . ksum + 1e-6), 512 entries ----
    for (int e = tid; e < 512; e += 256) {
        const int r = e >> 3, hh = e & 7;
        float s = 0.f;
#pragma unroll
        for (int d2 = 0; d2 < 16; d2++) {
            float2 f = __half22float2(*(__half2*)&s_q[r * 264 + hh * 32 + d2 * 2]);
            s += f.x * s_ks[hh * 32 + d2 * 2] + f.y * s_ks[hh * 32 + d2 * 2 + 1];
        }
        s_z[e] = 1.f / (s + 1e-6f);
    }
    __syncthreads();

    // ---- attn: warp = head; load ALL fragments, then store into s_A ----
    const int lr = lane & 15, lc = lane >> 4;
    uint32_t bb[2][2][4];                     // [ks][eh]
#pragma unroll
    for (int ks = 0; ks < 2; ks++)
#pragma unroll
        for (int eh = 0; eh < 2; eh++)
            LDMX4T(bb[ks][eh], ukv + (wid * 32 + ks * 16 + lr) * 80 + (eh * 16 + lc * 8) * 2);
    uint32_t am[4][2][4];                     // [m-tile of 16 rows][ks]
#pragma unroll
    for (int mt = 0; mt < 4; mt++)
#pragma unroll
        for (int ks = 0; ks < 2; ks++)
            LDMX4(am[mt][ks], uq + (mt * 16 + lr) * 528 + (wid * 32 + ks * 16 + lc * 8) * 2);
    __syncthreads();   // all warps done reading q/kv -> safe to overwrite with A

    __half* a_h = s_A + wid * 3072;           // chunk = head
#pragma unroll
    for (int mt = 0; mt < 4; mt++) {
        float c[4][4] = {};
#pragma unroll
        for (int nb = 0; nb < 4; nb++) {
            const int eh = nb >> 1, hi = nb & 1;
#pragma unroll
            for (int ks = 0; ks < 2; ks++)
                mma16(c[nb], am[mt][ks][0], am[mt][ks][1], am[mt][ks][2], am[mt][ks][3],
                      bb[ks][eh][hi * 2], bb[ks][eh][hi * 2 + 1]);
        }
        const int r0 = mt * 16 + g;
        const float z0 = s_z[r0 * 8 + wid];
        const float z1 = s_z[(r0 + 8) * 8 + wid];
#pragma unroll
        for (int nb = 0; nb < 4; nb++) {
            const int e = nb * 8 + 2 * t;
            *(__half2*)&a_h[r0 * 48 + e]       = __floats2half2_rn(c[nb][0] * z0, c[nb][1] * z0);
            *(__half2*)&a_h[(r0 + 8) * 48 + e] = __floats2half2_rn(c[nb][2] * z1, c[nb][3] * z1);
        }
    }
    __syncthreads();   // A complete

    // ---- Wo mainloop: 8 chunks, 2-stage B, A from smem ----
    float c[2][8][4] = {};
#pragma unroll 1
    for (int cc = 0; cc < 8; cc++) {
        asm volatile("cp.async.wait_group 0;");   // stage cc complete
        __syncthreads();
        if (cc + 1 < 8) {
            stageB(cc + 1, (cc + 1) & 1);
            asm volatile("cp.async.commit_group;");
        }
        const __half* a_s = s_A + cc * 3072;
        const __half* b_s = s_B + (cc & 1) * 12288;
#pragma unroll
        for (int s = 0; s < 2; s++) {
            uint2 va[2][2];
#pragma unroll
            for (int i = 0; i < 2; i++) {
                const int rb = (2 * wm + i) * 16;
                va[i][0] = *(const uint2*)&a_s[(rb + g)     * 48 + s * 16 + 4 * t];
                va[i][1] = *(const uint2*)&a_s[(rb + g + 8) * 48 + s * 16 + 4 * t];
            }
            uint2 vb[8];
#pragma unroll
            for (int j = 0; j < 8; j++)
                vb[j] = *(const uint2*)&b_s[(wn * 64 + j * 8 + g) * 48 + s * 16 + 4 * t];
#pragma unroll
            for (int i = 0; i < 2; i++)
#pragma unroll
                for (int j = 0; j < 8; j++)
                    mma16(c[i][j], va[i][0].x, va[i][1].x, va[i][0].y, va[i][1].y,
                          vb[j].x, vb[j].y);
        }
        __syncthreads();   // retire A/B reads before restage / epilogue reuse
    }

    // ---- epilogue: bias + half residual + LN1 -> x1h ----
    float* se = (float*)smh;   // 64 x LNPITCH f32 (aliases A+B, both dead)
#pragma unroll
    for (int j = 0; j < 8; j++) {
        const int col = wn * 64 + j * 8 + t * 2;
        const float b0 = __ldg(&bias[col]);
        const float b1 = __ldg(&bias[col + 1]);
#pragma unroll
        for (int i = 0; i < 2; i++) {
            const int r = (2 * wm + i) * 16 + g;
            *(float2*)&se[r * LNPITCH + col] = make_float2(c[i][j][0] + b0, c[i][j][1] + b1);
            *(float2*)&se[(r + 8) * LNPITCH + col] = make_float2(c[i][j][2] + b0, c[i][j][3] + b1);
        }
    }
    __syncthreads();

#pragma unroll
    for (int rr = 0; rr < 8; rr++) {
        const int row = wid * 8 + rr;
        const size_t rb = (size_t)(tok0 + row) * D_;
        float vals[8];
        float sum = 0.f, sq = 0.f;
#pragma unroll
        for (int i = 0; i < 8; i++) {
            float v = se[row * LNPITCH + lane + i * 32]
                    + __half2float(res[rb + lane + i * 32]);
            vals[i] = v; sum += v; sq += v * v;
        }
#pragma unroll
        for (int off = 16; off > 0; off >>= 1) {
            sum += __shfl_xor_sync(0xffffffffu, sum, off);
            sq  += __shfl_xor_sync(0xffffffffu, sq,  off);
        }
        float mu  = sum * (1.f / 256.f);
        float var = sq * (1.f / 256.f) - mu * mu;
        float rs  = rsqrtf(var + 1e-5f);
#pragma unroll
        for (int i = 0; i < 8; i++) {
            const int col = lane + i * 32;
            float v = (vals[i] - mu) * rs * lg[col] + lb[col];
            oh[rb + col] = __float2half(v);
        }
    }
}

// ============================================================================
// kv reduction via tensor cores; k/v dense head-major [(bh)][L][32].
// ============================================================================
__global__ __launch_bounds__(256) void k_kvred()
{
    extern __shared__ __half sred[];
    const int bh = blockIdx.x;
    const int ch = blockIdx.y;
    const int w = threadIdx.x >> 5, lane = threadIdx.x & 31;
    const int g = lane >> 2, t = lane & 3;

    __half* k_s = sred + w * 5120;
    const uint32_t uk = smem_u32(k_s);
    const uint32_t uv = uk + 2560 * 2;

    const int tok0 = ch * CHTOK + w * 64;
    const __half* kg = g_kh + ((size_t)bh * L_ + tok0) * 32;
    const __half* vg = g_vh + ((size_t)bh * L_ + tok0) * 32;

#pragma unroll
    for (int it = 0; it < 8; it++) {
        int i = lane + it * 32;
        int tok = i >> 2, c4 = i & 3;
        cp16(uk + tok * 80 + c4 * 16, kg + (size_t)i * 8);
        cp16(uv + tok * 80 + c4 * 16, vg + (size_t)i * 8);
    }
    asm volatile("cp.async.commit_group;");
    asm volatile("cp.async.wait_group 0;");
    __syncwarp();

    float acc[2][4][4] = {};
    float cs[2][4] = {};
    const uint32_t ones2 = 0x3C003C00u;

    const int tokA = (lane & 7) + ((lane >> 4) << 3);
    const int dA   = ((lane >> 3) & 1) * 8;
    const int tokB = (lane & 7) + (((lane >> 3) & 1) << 3);
    const int eB   = ((lane >> 4) & 1) * 8;

#pragma unroll
    for (int st = 0; st < 64; st += 16) {
        uint32_t a[2][4], bb[2][4];
#pragma unroll
        for (int mi = 0; mi < 2; mi++)
            LDMX4T(a[mi], uk + (st + tokA) * 80 + (mi * 16 + dA) * 2);
#pragma unroll
        for (int np = 0; np < 2; np++)
            LDMX4T(bb[np], uv + (st + tokB) * 80 + (np * 16 + eB) * 2);
#pragma unroll
        for (int mi = 0; mi < 2; mi++) {
#pragma unroll
            for (int nb = 0; nb < 4; nb++) {
                const int np = nb >> 1, hi = nb & 1;
                mma16(acc[mi][nb], a[mi][0], a[mi][1], a[mi][2], a[mi][3],
                      bb[np][hi * 2], bb[np][hi * 2 + 1]);
            }
            mma16(cs[mi], a[mi][0], a[mi][1], a[mi][2], a[mi][3], ones2, ones2);
        }
    }
    __syncthreads();

    float* s_part = (float*)sred;
    float* s_ksp  = s_part + 8 * 1024;
#pragma unroll
    for (int mi = 0; mi < 2; mi++) {
#pragma unroll
        for (int nb = 0; nb < 4; nb++) {
            const int d0 = mi * 16 + g, e0 = nb * 8 + 2 * t;
            *(float2*)&s_part[w * 1024 + d0 * 32 + e0] =
                make_float2(acc[mi][nb][0], acc[mi][nb][1]);
            *(float2*)&s_part[w * 1024 + (d0 + 8) * 32 + e0] =
                make_float2(acc[mi][nb][2], acc[mi][nb][3]);
        }
        if (t == 0) {
            s_ksp[w * 32 + mi * 16 + g]     = cs[mi][0];
            s_ksp[w * 32 + mi * 16 + g + 8] = cs[mi][2];
        }
    }
    __syncthreads();

    const int tid = threadIdx.x;
    for (int j = tid; j < 1024; j += 256) {
        float s = 0.f;
#pragma unroll
        for (int ww = 0; ww < 8; ww++) s += s_part[ww * 1024 + j];
        g_kvpart[((size_t)ch * 32 + bh) * 1024 + j] = s;
    }
    if (tid < 32) {
        float s = 0.f;
#pragma unroll
        for (int ww = 0; ww < 8; ww++) s += s_ksp[ww * 32 + tid];
        g_kspart[(ch * 32 + bh) * 32 + tid] = s;
    }
}

// kvfin: final chunk reduction; kv -> HALF pitch-40 layout, ksum stays f32.
__global__ __launch_bounds__(256) void k_kvfin()
{
    const int bh = blockIdx.x;
    for (int j = threadIdx.x; j < 1024; j += 256) {
        float s = 0.f;
#pragma unroll
        for (int c = 0; c < NCH; c++) s += g_kvpart[((size_t)c * 32 + bh) * 1024 + j];
        const int d = j >> 5, e = j & 31;
        g_kvh[(size_t)bh * 1280 + d * 40 + e] = __float2half(s);
    }
    if (threadIdx.x < 32) {
        float s = 0.f;
#pragma unroll
        for (int c = 0; c < NCH; c++) s += g_kspart[(c * 32 + bh) * 32 + threadIdx.x];
        g_ksum[bh * 32 + threadIdx.x] = s;
    }
}

// ============================================================================
extern "C" void kernel_launch(void* const* d_in, const int* in_sizes, int n_in,
                              void* d_out, int out_size)
{
    const float* x    = (const float*)d_in[0];
    const float* Wq   = (const float*)d_in[1];
    const float* bq   = (const float*)d_in[2];
    const float* Wk   = (const float*)d_in[3];
    const float* bk   = (const float*)d_in[4];
    const float* Wv   = (const float*)d_in[5];
    const float* bv   = (const float*)d_in[6];
    const float* Wo   = (const float*)d_in[7];
    const float* bo   = (const float*)d_in[8];
    const float* W1   = (const float*)d_in[9];
    const float* b1   = (const float*)d_in[10];
    const float* W2   = (const float*)d_in[11];
    const float* b2   = (const float*)d_in[12];
    const float* ln1g = (const float*)d_in[13];
    const float* ln1b = (const float*)d_in[14];
    const float* ln2g = (const float*)d_in[15];
    const float* ln2b = (const float*)d_in[16];
    float* out = (float*)d_out;

    __half *xh, *x1h, *hh, *wqkvT, *woT, *w1T, *w2T;
    float *bqkv;
    cudaGetSymbolAddress((void**)&xh,    g_xh);
    cudaGetSymbolAddress((void**)&x1h,   g_x1h);
    cudaGetSymbolAddress((void**)&hh,    g_hh);
    cudaGetSymbolAddress((void**)&wqkvT, g_wqkvT);
    cudaGetSymbolAddress((void**)&woT,   g_woT);
    cudaGetSymbolAddress((void**)&w1T,   g_w1T);
    cudaGetSymbolAddress((void**)&w2T,   g_w2T);
    cudaGetSymbolAddress((void**)&bqkv,  g_bqkv);

    const int GSM   = 98304;               // k_gemm 4-stage
    const int GSMLN = 92160;               // k_gemm_ln 3-stage BM=64
    const int GSMKV = 8 * 5120 * 2;        // 81920
    const int GSMAT = 53248 * 2;           // 106496: fused attn+Wo+LN
    cudaFuncSetAttribute((k_gemm<2>), cudaFuncAttributeMaxDynamicSharedMemorySize, GSM);
    cudaFuncSetAttribute((k_gemm<3>), cudaFuncAttributeMaxDynamicSharedMemorySize, GSM);
    cudaFuncSetAttribute((k_gemm_ln<1>), cudaFuncAttributeMaxDynamicSharedMemorySize, GSMLN);
    cudaFuncSetAttribute(k_attn_ln, cudaFuncAttributeMaxDynamicSharedMemorySize, GSMAT);
    cudaFuncSetAttribute(k_kvred, cudaFuncAttributeMaxDynamicSharedMemorySize, GSMKV);

    k_cvtx<<<MTOK * D_ / 4 / 512, 512>>>(x);
    k_trall<<<769, dim3(32, 8)>>>(Wq, Wk, Wv, Wo, W1, W2, bq, bk, bv);

    // merged QKV projection: phi for q,k; head-major scatter for k,v
    k_gemm<3><<<dim3(6, 512), 256, GSM>>>(xh, wqkvT, bqkv, nullptr, D_, 768);

    k_kvred<<<dim3(32, NCH), 256, GSMKV>>>();
    k_kvfin<<<32, 256>>>();

    // fused attn readout + Wo + half residual (xh) + LN1 -> x1h
    k_attn_ln<<<1024, 256, GSMAT>>>(woT, bo, xh, ln1g, ln1b, x1h);

    // FFN1 (relu), half out
    k_gemm<2><<<dim3(8, 512), 256, GSM>>>(x1h, w1T, b1, hh, D_, FF_);

    // FFN2 + half residual (x1h) + LN2 -> out (f32)
    k_gemm_ln<1><<<1024, 256, GSMLN>>>(hh, w2T, b2, x1h, ln2g, ln2b, out, nullptr, FF_);
}

// round 17
// speedup vs baseline: 1.3307x; 1.0507x over previous
#include <cuda_runtime.h>
#include <cuda_fp16.h>
#include <math.h>
#include <stdint.h>

#define B_    4
#define L_    16384
#define D_    256
#define H_    8
#define DH_   32
#define FF_   1024
#define MTOK  65536
#define NCH   32
#define CHTOK 512

// ---------------- scratch ----------------
__device__ __half g_xh  [MTOK * D_];     // x as half (QKV A + LN1 residual)
__device__ __half g_qh  [MTOK * D_];     // q_phi, [tok][256]
__device__ __half g_kh  [MTOK * D_];     // k_phi, [(b*8+h)][L][32]
__device__ __half g_vh  [MTOK * D_];     // v,     [(b*8+h)][L][32]
__device__ __half g_x1h [MTOK * D_];     // LN1 out (half: FFN A + LN2 residual)
__device__ float  g_kvpart[NCH * 32 * 1024];
__device__ float  g_kspart[NCH * 32 * 32];
__device__ __half g_kvh[32 * 32 * 40];   // [bh][d][40] half, ldmatrix pitch
__device__ float  g_ksum[32 * 32];
// transposed weights [N,K] row-major, half
__device__ __half g_wqkvT[768 * D_];
__device__ __half g_woT[D_ * D_];
__device__ __half g_w1T[FF_ * D_];
__device__ __half g_w2T[D_ * FF_];
__device__ float  g_bqkv[768];

// ---------------- helpers ----------------
__device__ __forceinline__ uint32_t smem_u32(const void* p) {
    uint32_t a;
    asm("{ .reg .u64 t; cvta.to.shared.u64 t, %1; cvt.u32.u64 %0, t; }" : "=r"(a) : "l"(p));
    return a;
}
__device__ __forceinline__ void cp16(uint32_t dst, const void* src) {
    asm volatile("cp.async.cg.shared.global [%0], [%1], 16;" :: "r"(dst), "l"(src));
}
__device__ __forceinline__ void mma16(float* c, uint32_t a0, uint32_t a1,
                                      uint32_t a2, uint32_t a3,
                                      uint32_t b0, uint32_t b1) {
    asm volatile("mma.sync.aligned.m16n8k16.row.col.f32.f16.f16.f32 "
        "{%0,%1,%2,%3}, {%4,%5,%6,%7}, {%8,%9}, {%0,%1,%2,%3};"
        : "+f"(c[0]), "+f"(c[1]), "+f"(c[2]), "+f"(c[3])
        : "r"(a0), "r"(a1), "r"(a2), "r"(a3), "r"(b0), "r"(b1));
}
#define LDMX4T(r, addr) \
    asm volatile("ldmatrix.sync.aligned.m8n8.x4.trans.shared.b16 {%0,%1,%2,%3}, [%4];" \
        : "=r"((r)[0]), "=r"((r)[1]), "=r"((r)[2]), "=r"((r)[3]) : "r"(addr))
#define LDMX4(r, addr) \
    asm volatile("ldmatrix.sync.aligned.m8n8.x4.shared.b16 {%0,%1,%2,%3}, [%4];" \
        : "=r"((r)[0]), "=r"((r)[1]), "=r"((r)[2]), "=r"((r)[3]) : "r"(addr))

// ============================================================================
// x -> half copy
// ============================================================================
__global__ __launch_bounds__(512) void k_cvtx(const float* __restrict__ x)
{
    int i = blockIdx.x * 512 + threadIdx.x;
    float4 v = *(const float4*)&x[(size_t)i * 4];
    __half2 h0 = __floats2half2_rn(v.x, v.y);
    __half2 h1 = __floats2half2_rn(v.z, v.w);
    *(uint2*)&g_xh[(size_t)i * 4] = make_uint2(*(uint32_t*)&h0, *(uint32_t*)&h1);
}

// ============================================================================
// ALL weight transposes + bias concat in ONE launch.
// ============================================================================
__global__ void k_trall(const float* __restrict__ Wq, const float* __restrict__ Wk,
                        const float* __restrict__ Wv, const float* __restrict__ Wo,
                        const float* __restrict__ W1, const float* __restrict__ W2,
                        const float* __restrict__ bq, const float* __restrict__ bk,
                        const float* __restrict__ bv)
{
    const int bid = blockIdx.x;
    if (bid == 768) {
        int t = threadIdx.y * 32 + threadIdx.x;
        g_bqkv[t] = bq[t]; g_bqkv[256 + t] = bk[t]; g_bqkv[512 + t] = bv[t];
        return;
    }
    const float* W; __half* Wt; int K, N, idx;
    if (bid < 256) {
        idx = bid & 63; K = D_; N = D_;
        int sel = bid >> 6;
        W  = (sel == 0) ? Wq : (sel == 1) ? Wk : (sel == 2) ? Wv : Wo;
        Wt = (sel == 0) ? g_wqkvT : (sel == 1) ? g_wqkvT + 256 * D_
           : (sel == 2) ? g_wqkvT + 512 * D_ : g_woT;
    } else if (bid < 512) {
        idx = bid - 256; K = D_; N = FF_; W = W1; Wt = g_w1T;
    } else {
        idx = bid - 512; K = FF_; N = D_; W = W2; Wt = g_w2T;
    }
    const int xt = N >> 5;
    const int n0 = (idx % xt) * 32, k0 = (idx / xt) * 32;

    __shared__ float t[32][33];
    int x = threadIdx.x, y = threadIdx.y;
    for (int i = y; i < 32; i += 8) t[i][x] = W[(size_t)(k0 + i) * N + n0 + x];
    __syncthreads();
    for (int i = y; i < 32; i += 8)
        Wt[(size_t)(n0 + i) * K + k0 + x] = __float2half(t[x][i]);
}

// ============================================================================
// fp16 mma.sync GEMM (BN=128, 256 thr, 4-stage).  QKV projection only.
// phi for q,k; head-major scatter for k,v.
// ============================================================================
__device__ __forceinline__ void stage256(const __half* __restrict__ Ap,
                                         const __half* __restrict__ Bp,
                                         int K, uint32_t sa, uint32_t sb, int tid)
{
#pragma unroll
    for (int t = 0; t < 2; t++) {
        int i = tid + t * 256;
        int row = i >> 2, c = i & 3;
        cp16(sa + row * 96 + c * 16, Ap + (size_t)row * K + c * 8);
    }
#pragma unroll
    for (int t = 0; t < 2; t++) {
        int i = tid + t * 256;
        int row = i >> 2, c = i & 3;
        cp16(sb + row * 96 + c * 16, Bp + (size_t)row * K + c * 8);
    }
}

__global__ __launch_bounds__(256, 2) void k_gemm_qkv(
    const __half* __restrict__ A, const __half* __restrict__ Bt,
    const float* __restrict__ bias, int K)
{
    extern __shared__ __half smh[];
    const int tid  = threadIdx.x;
    const int wid  = tid >> 5;
    const int lane = tid & 31;
    const int g = lane >> 2, t = lane & 3;
    const int wm = wid & 3, wn = wid >> 2;
    const int m0 = blockIdx.y * 128;
    const int n0 = blockIdx.x * 128;
    const int NC = K >> 5;

    uint32_t uA[4], uB[4];
#pragma unroll
    for (int s = 0; s < 4; s++) {
        uA[s] = smem_u32(smh + s * 6144);
        uB[s] = smem_u32(smh + 24576 + s * 6144);
    }

    float c[2][8][4] = {};
    const __half* Abase = A + (size_t)m0 * K;
    const __half* Bbase = Bt + (size_t)n0 * K;

    stage256(Abase,      Bbase,      K, uA[0], uB[0], tid);
    asm volatile("cp.async.commit_group;");
    stage256(Abase + 32, Bbase + 32, K, uA[1], uB[1], tid);
    asm volatile("cp.async.commit_group;");
    stage256(Abase + 64, Bbase + 64, K, uA[2], uB[2], tid);
    asm volatile("cp.async.commit_group;");

    for (int cc = 0; cc < NC; cc++) {
        if (cc + 2 < NC)      asm volatile("cp.async.wait_group 2;");
        else if (cc + 1 < NC) asm volatile("cp.async.wait_group 1;");
        else                  asm volatile("cp.async.wait_group 0;");
        __syncthreads();
        if (cc + 3 < NC) {
            const int bs = (cc + 3) & 3;
            stage256(Abase + (cc + 3) * 32, Bbase + (cc + 3) * 32, K, uA[bs], uB[bs], tid);
            asm volatile("cp.async.commit_group;");
        }
        const int cur = cc & 3;
        const __half* a_s = smh + cur * 6144;
        const __half* b_s = smh + 24576 + cur * 6144;
#pragma unroll
        for (int s = 0; s < 2; s++) {
            uint2 va[2][2];
#pragma unroll
            for (int i = 0; i < 2; i++) {
                const int rb = (2 * wm + i) * 16;
                va[i][0] = *(const uint2*)&a_s[(rb + g)     * 48 + s * 16 + 4 * t];
                va[i][1] = *(const uint2*)&a_s[(rb + g + 8) * 48 + s * 16 + 4 * t];
            }
            uint2 vb[8];
#pragma unroll
            for (int j = 0; j < 8; j++) {
                const int n = (wn * 8 + j) * 8 + g;
                vb[j] = *(const uint2*)&b_s[n * 48 + s * 16 + 4 * t];
            }
#pragma unroll
            for (int i = 0; i < 2; i++)
#pragma unroll
                for (int j = 0; j < 8; j++)
                    mma16(c[i][j], va[i][0].x, va[i][1].x, va[i][0].y, va[i][1].y,
                          vb[j].x, vb[j].y);
        }
    }

    const bool do_phi = (n0 < 512);
#pragma unroll
    for (int j = 0; j < 8; j++) {
        const int col = n0 + (wn * 8 + j) * 8 + t * 2;
        const float b0 = __ldg(&bias[col]);
        const float b1 = __ldg(&bias[col + 1]);
#pragma unroll
        for (int i = 0; i < 2; i++) {
            const int r0 = m0 + (2 * wm + i) * 16 + g;
            float v0 = c[i][j][0] + b0, v1 = c[i][j][1] + b1;
            float v2 = c[i][j][2] + b0, v3 = c[i][j][3] + b1;
            if (do_phi) {
                v0 = (v0 > 0.f) ? (v0 + 1.f) : expf(v0);
                v1 = (v1 > 0.f) ? (v1 + 1.f) : expf(v1);
                v2 = (v2 > 0.f) ? (v2 + 1.f) : expf(v2);
                v3 = (v3 > 0.f) ? (v3 + 1.f) : expf(v3);
            }
            __half2 h0 = __floats2half2_rn(v0, v1);
            __half2 h1 = __floats2half2_rn(v2, v3);
            if (n0 < 256) {
                *(__half2*)&g_qh[(size_t)r0 * D_ + col]       = h0;
                *(__half2*)&g_qh[(size_t)(r0 + 8) * D_ + col] = h1;
            } else {
                __half* dst = (n0 < 512) ? g_kh : g_vh;
                const int colr = col & 255;
                const int head = colr >> 5, e = colr & 31;
                const int b = r0 >> 14, l = r0 & (L_ - 1);
                const size_t base0 = ((size_t)(b * 8 + head) * L_ + l) * 32 + e;
                *(__half2*)&dst[base0]          = h0;
                *(__half2*)&dst[base0 + 8 * 32] = h1;
            }
        }
    }
}

#define LNPITCH 264

// ============================================================================
// FUSED FFN + LN2:  out = LN2( x1h + relu(x1h@W1^T+b1) @ W2^T + b2 )
// BM=64, 256 thr, 2 CTAs/SM.  Hidden lives only in smem.
// smem halves: A_x [64][272] @0 (17408) | B shared 24576 @17408
//              (B1 3x6144 / B2 2x12288) | h 4x3072 @41984 | total 54272
// ============================================================================
__global__ __launch_bounds__(256, 2) void k_ffn_ln(
    const __half* __restrict__ A, const __half* __restrict__ W1t,
    const __half* __restrict__ W2t, const float* __restrict__ b1,
    const float* __restrict__ b2, const __half* __restrict__ res,
    const float* __restrict__ lg, const float* __restrict__ lb,
    float* __restrict__ o)
{
    extern __shared__ __half smh[];
    __half* s_Ax = smh;                  // 64 x 272
    __half* s_B  = smh + 17408;          // 24576 shared B1/B2
    __half* s_h  = smh + 41984;          // 4 x 3072

    const int tid  = threadIdx.x;
    const int wid  = tid >> 5;
    const int lane = tid & 31;
    const int g = lane >> 2, t = lane & 3;
    const int wm = wid & 1, wn = wid >> 1;   // 2m x 4n
    const int m0 = blockIdx.x * 64;

    const uint32_t uAx = smem_u32(s_Ax);
    const uint32_t uB  = smem_u32(s_B);

    // ---- load A_x once (2048 cp16, 8/thread), group folded into first wait
#pragma unroll
    for (int tt = 0; tt < 8; tt++) {
        int i = tid + tt * 256;
        int r = i >> 5, c = i & 31;
        cp16(uAx + r * 544 + c * 16, A + (size_t)(m0 + r) * D_ + c * 8);
    }
    asm volatile("cp.async.commit_group;");

    auto stageB1 = [&](int jc, int kc, int s) {
#pragma unroll
        for (int tt = 0; tt < 2; tt++) {
            int i = tid + tt * 256;
            int row = i >> 2, c4 = i & 3;
            cp16(uB + s * 12288 + row * 96 + c4 * 16,
                 W1t + (size_t)(jc * 128 + row) * D_ + kc * 32 + c4 * 8);
        }
    };
    auto stageB2 = [&](int jc, int cc, int s) {
#pragma unroll
        for (int tt = 0; tt < 4; tt++) {
            int i = tid + tt * 256;
            int row = i >> 2, c4 = i & 3;
            cp16(uB + s * 24576 + row * 96 + c4 * 16,
                 W2t + (size_t)row * FF_ + jc * 128 + cc * 32 + c4 * 8);
        }
    };

    float c2[2][8][4] = {};

    for (int jc = 0; jc < 8; jc++) {
        // ---- phase 1: h[64,128] = relu(x1h @ W1 slab + b1), 3-stage B1 ----
        stageB1(jc, 0, 0);
        asm volatile("cp.async.commit_group;");
        stageB1(jc, 1, 1);
        asm volatile("cp.async.commit_group;");

        float c1[2][4][4] = {};
#pragma unroll 1
        for (int kc = 0; kc < 8; kc++) {
            if (kc + 1 < 8) asm volatile("cp.async.wait_group 1;");
            else            asm volatile("cp.async.wait_group 0;");
            __syncthreads();
            if (kc + 2 < 8) {
                stageB1(jc, kc + 2, (kc + 2) % 3);
                asm volatile("cp.async.commit_group;");
            }
            const __half* b_s = s_B + (kc % 3) * 6144;
#pragma unroll
            for (int s = 0; s < 2; s++) {
                uint2 va[2][2];
#pragma unroll
                for (int i = 0; i < 2; i++) {
                    const int rb = (2 * wm + i) * 16;
                    va[i][0] = *(const uint2*)&s_Ax[(rb + g)     * 272 + kc * 32 + s * 16 + 4 * t];
                    va[i][1] = *(const uint2*)&s_Ax[(rb + g + 8) * 272 + kc * 32 + s * 16 + 4 * t];
                }
                uint2 vb[4];
#pragma unroll
                for (int j = 0; j < 4; j++)
                    vb[j] = *(const uint2*)&b_s[(wn * 32 + j * 8 + g) * 48 + s * 16 + 4 * t];
#pragma unroll
                for (int i = 0; i < 2; i++)
#pragma unroll
                    for (int j = 0; j < 4; j++)
                        mma16(c1[i][j], va[i][0].x, va[i][1].x, va[i][0].y, va[i][1].y,
                              vb[j].x, vb[j].y);
            }
        }

        // ---- h -> smem (chunk = wn, natural k order, pitch 48) ----
        __half* h_w = s_h + wn * 3072;
#pragma unroll
        for (int j = 0; j < 4; j++) {
            const int pos = j * 8 + 2 * t;
            const float bb0 = __ldg(&b1[jc * 128 + wn * 32 + pos]);
            const float bb1 = __ldg(&b1[jc * 128 + wn * 32 + pos + 1]);
#pragma unroll
            for (int i = 0; i < 2; i++) {
                const int r = (2 * wm + i) * 16 + g;
                *(__half2*)&h_w[r * 48 + pos] =
                    __floats2half2_rn(fmaxf(c1[i][j][0] + bb0, 0.f),
                                      fmaxf(c1[i][j][1] + bb1, 0.f));
                *(__half2*)&h_w[(r + 8) * 48 + pos] =
                    __floats2half2_rn(fmaxf(c1[i][j][2] + bb0, 0.f),
                                      fmaxf(c1[i][j][3] + bb1, 0.f));
            }
        }
        __syncthreads();   // h visible; B1 reads retired -> B region reusable

        // ---- phase 2: c2 += h @ W2 slab, 2-stage B2 ----
        stageB2(jc, 0, 0);
        asm volatile("cp.async.commit_group;");
        stageB2(jc, 1, 1);
        asm volatile("cp.async.commit_group;");
#pragma unroll 1
        for (int cc = 0; cc < 4; cc++) {
            if (cc + 1 < 4) asm volatile("cp.async.wait_group 1;");
            else            asm volatile("cp.async.wait_group 0;");
            __syncthreads();
            const __half* a_s = s_h + cc * 3072;
            const __half* b_s = s_B + (cc & 1) * 12288;
#pragma unroll
            for (int s = 0; s < 2; s++) {
                uint2 va[2][2];
#pragma unroll
                for (int i = 0; i < 2; i++) {
                    const int rb = (2 * wm + i) * 16;
                    va[i][0] = *(const uint2*)&a_s[(rb + g)     * 48 + s * 16 + 4 * t];
                    va[i][1] = *(const uint2*)&a_s[(rb + g + 8) * 48 + s * 16 + 4 * t];
                }
                uint2 vb[8];
#pragma unroll
                for (int j = 0; j < 8; j++)
                    vb[j] = *(const uint2*)&b_s[(wn * 64 + j * 8 + g) * 48 + s * 16 + 4 * t];
#pragma unroll
                for (int i = 0; i < 2; i++)
#pragma unroll
                    for (int j = 0; j < 8; j++)
                        mma16(c2[i][j], va[i][0].x, va[i][1].x, va[i][0].y, va[i][1].y,
                              vb[j].x, vb[j].y);
            }
            __syncthreads();
            if (cc + 2 < 4) {
                stageB2(jc, cc + 2, cc & 1);
                asm volatile("cp.async.commit_group;");
            }
        }
        // trailing sync of cc-loop guarantees B/h reusable next jc
    }

    // ---- epilogue: c2 + b2 + half residual + LN2 -> out (f32) ----
    float* se = (float*)smh;   // 64 x LNPITCH f32 (A_x/B/h all dead)
    __syncthreads();
#pragma unroll
    for (int j = 0; j < 8; j++) {
        const int col = wn * 64 + j * 8 + t * 2;
        const float b0 = __ldg(&b2[col]);
        const float b1v = __ldg(&b2[col + 1]);
#pragma unroll
        for (int i = 0; i < 2; i++) {
            const int r = (2 * wm + i) * 16 + g;
            *(float2*)&se[r * LNPITCH + col] = make_float2(c2[i][j][0] + b0, c2[i][j][1] + b1v);
            *(float2*)&se[(r + 8) * LNPITCH + col] = make_float2(c2[i][j][2] + b0, c2[i][j][3] + b1v);
        }
    }
    __syncthreads();

#pragma unroll
    for (int rr = 0; rr < 8; rr++) {
        const int row = wid * 8 + rr;
        const size_t rb = (size_t)(m0 + row) * D_;
        float vals[8];
        float sum = 0.f, sq = 0.f;
#pragma unroll
        for (int i = 0; i < 8; i++) {
            float v = se[row * LNPITCH + lane + i * 32]
                    + __half2float(res[rb + lane + i * 32]);
            vals[i] = v; sum += v; sq += v * v;
        }
#pragma unroll
        for (int off = 16; off > 0; off >>= 1) {
            sum += __shfl_xor_sync(0xffffffffu, sum, off);
            sq  += __shfl_xor_sync(0xffffffffu, sq,  off);
        }
        float mu  = sum * (1.f / 256.f);
        float var = sq * (1.f / 256.f) - mu * mu;
        float rs  = rsqrtf(var + 1e-5f);
#pragma unroll
        for (int i = 0; i < 8; i++) {
            const int col = lane + i * 32;
            o[rb + col] = (vals[i] - mu) * rs * lg[col] + lb[col];
        }
    }
}

// ============================================================================
// FUSED attention readout + Wo GEMM + bias + half residual + LN1 -> x1h.
// (unchanged from R16)
// ============================================================================
__global__ __launch_bounds__(256, 2) void k_attn_ln(
    const __half* __restrict__ Bt, const float* __restrict__ bias,
    const __half* __restrict__ res, const float* __restrict__ lg,
    const float* __restrict__ lb, __half* __restrict__ oh)
{
    extern __shared__ __half smh[];
    __half* s_q  = smh;                    // 64 x 264
    __half* s_kv = smh + 16896;            // 10240
    __half* s_A  = smh;                    // 8 x 3072 (aliases q/kv)
    __half* s_B  = smh + 27136;            // 2 x 12288
    float*  s_ks = (float*)(smh + 51712);  // 256
    float*  s_z  = (float*)(smh + 52224);  // 512

    const int tid  = threadIdx.x;
    const int wid  = tid >> 5;
    const int lane = tid & 31;
    const int g = lane >> 2, t = lane & 3;
    const int wm = wid & 1, wn = wid >> 1;
    const int tok0 = blockIdx.x * 64;
    const int b    = tok0 >> 14;

    const uint32_t uq  = smem_u32(s_q);
    const uint32_t ukv = smem_u32(s_kv);
    const uint32_t uB  = smem_u32(s_B);

    auto stageB = [&](int chunk, int s) {
#pragma unroll
        for (int tt = 0; tt < 4; tt++) {
            int i = tid + tt * 256;
            int row = i >> 2, c4 = i & 3;
            cp16(uB + s * 24576 + row * 96 + c4 * 16,
                 Bt + (size_t)row * D_ + chunk * 32 + c4 * 8);
        }
    };

#pragma unroll
    for (int tt = 0; tt < 8; tt++) {
        int i = tid + tt * 256;
        int r = i >> 5, c = i & 31;
        cp16(uq + r * 528 + c * 16, g_qh + (size_t)(tok0 + r) * D_ + c * 8);
    }
#pragma unroll
    for (int tt = 0; tt < 5; tt++) {
        int i = tid + tt * 256;
        cp16(ukv + i * 16, g_kvh + (size_t)b * 10240 + i * 8);
    }
    if (tid < 64)
        cp16(smem_u32(s_ks) + tid * 16, g_ksum + b * 256 + tid * 4);
    asm volatile("cp.async.commit_group;");
    stageB(0, 0);
    asm volatile("cp.async.commit_group;");
    asm volatile("cp.async.wait_group 1;");
    __syncthreads();

    for (int e = tid; e < 512; e += 256) {
        const int r = e >> 3, hh = e & 7;
        float s = 0.f;
#pragma unroll
        for (int d2 = 0; d2 < 16; d2++) {
            float2 f = __half22float2(*(__half2*)&s_q[r * 264 + hh * 32 + d2 * 2]);
            s += f.x * s_ks[hh * 32 + d2 * 2] + f.y * s_ks[hh * 32 + d2 * 2 + 1];
        }
        s_z[e] = 1.f / (s + 1e-6f);
    }
    __syncthreads();

    const int lr = lane & 15, lc = lane >> 4;
    uint32_t bb[2][2][4];
#pragma unroll
    for (int ks = 0; ks < 2; ks++)
#pragma unroll
        for (int eh = 0; eh < 2; eh++)
            LDMX4T(bb[ks][eh], ukv + (wid * 32 + ks * 16 + lr) * 80 + (eh * 16 + lc * 8) * 2);
    uint32_t am[4][2][4];
#pragma unroll
    for (int mt = 0; mt < 4; mt++)
#pragma unroll
        for (int ks = 0; ks < 2; ks++)
            LDMX4(am[mt][ks], uq + (mt * 16 + lr) * 528 + (wid * 32 + ks * 16 + lc * 8) * 2);
    __syncthreads();

    __half* a_h = s_A + wid * 3072;
#pragma unroll
    for (int mt = 0; mt < 4; mt++) {
        float c[4][4] = {};
#pragma unroll
        for (int nb = 0; nb < 4; nb++) {
            const int eh = nb >> 1, hi = nb & 1;
#pragma unroll
            for (int ks = 0; ks < 2; ks++)
                mma16(c[nb], am[mt][ks][0], am[mt][ks][1], am[mt][ks][2], am[mt][ks][3],
                      bb[ks][eh][hi * 2], bb[ks][eh][hi * 2 + 1]);
        }
        const int r0 = mt * 16 + g;
        const float z0 = s_z[r0 * 8 + wid];
        const float z1 = s_z[(r0 + 8) * 8 + wid];
#pragma unroll
        for (int nb = 0; nb < 4; nb++) {
            const int e = nb * 8 + 2 * t;
            *(__half2*)&a_h[r0 * 48 + e]       = __floats2half2_rn(c[nb][0] * z0, c[nb][1] * z0);
            *(__half2*)&a_h[(r0 + 8) * 48 + e] = __floats2half2_rn(c[nb][2] * z1, c[nb][3] * z1);
        }
    }
    __syncthreads();

    float c[2][8][4] = {};
#pragma unroll 1
    for (int cc = 0; cc < 8; cc++) {
        asm volatile("cp.async.wait_group 0;");
        __syncthreads();
        if (cc + 1 < 8) {
            stageB(cc + 1, (cc + 1) & 1);
            asm volatile("cp.async.commit_group;");
        }
        const __half* a_s = s_A + cc * 3072;
        const __half* b_s = s_B + (cc & 1) * 12288;
#pragma unroll
        for (int s = 0; s < 2; s++) {
            uint2 va[2][2];
#pragma unroll
            for (int i = 0; i < 2; i++) {
                const int rb = (2 * wm + i) * 16;
                va[i][0] = *(const uint2*)&a_s[(rb + g)     * 48 + s * 16 + 4 * t];
                va[i][1] = *(const uint2*)&a_s[(rb + g + 8) * 48 + s * 16 + 4 * t];
            }
            uint2 vb[8];
#pragma unroll
            for (int j = 0; j < 8; j++)
                vb[j] = *(const uint2*)&b_s[(wn * 64 + j * 8 + g) * 48 + s * 16 + 4 * t];
#pragma unroll
            for (int i = 0; i < 2; i++)
#pragma unroll
                for (int j = 0; j < 8; j++)
                    mma16(c[i][j], va[i][0].x, va[i][1].x, va[i][0].y, va[i][1].y,
                          vb[j].x, vb[j].y);
        }
        __syncthreads();
    }

    float* se = (float*)smh;
#pragma unroll
    for (int j = 0; j < 8; j++) {
        const int col = wn * 64 + j * 8 + t * 2;
        const float b0 = __ldg(&bias[col]);
        const float b1 = __ldg(&bias[col + 1]);
#pragma unroll
        for (int i = 0; i < 2; i++) {
            const int r = (2 * wm + i) * 16 + g;
            *(float2*)&se[r * LNPITCH + col] = make_float2(c[i][j][0] + b0, c[i][j][1] + b1);
            *(float2*)&se[(r + 8) * LNPITCH + col] = make_float2(c[i][j][2] + b0, c[i][j][3] + b1);
        }
    }
    __syncthreads();

#pragma unroll
    for (int rr = 0; rr < 8; rr++) {
        const int row = wid * 8 + rr;
        const size_t rb = (size_t)(tok0 + row) * D_;
        float vals[8];
        float sum = 0.f, sq = 0.f;
#pragma unroll
        for (int i = 0; i < 8; i++) {
            float v = se[row * LNPITCH + lane + i * 32]
                    + __half2float(res[rb + lane + i * 32]);
            vals[i] = v; sum += v; sq += v * v;
        }
#pragma unroll
        for (int off = 16; off > 0; off >>= 1) {
            sum += __shfl_xor_sync(0xffffffffu, sum, off);
            sq  += __shfl_xor_sync(0xffffffffu, sq,  off);
        }
        float mu  = sum * (1.f / 256.f);
        float var = sq * (1.f / 256.f) - mu * mu;
        float rs  = rsqrtf(var + 1e-5f);
#pragma unroll
        for (int i = 0; i < 8; i++) {
            const int col = lane + i * 32;
            float v = (vals[i] - mu) * rs * lg[col] + lb[col];
            oh[rb + col] = __float2half(v);
        }
    }
}

// ============================================================================
// kv reduction via tensor cores; k/v dense head-major [(bh)][L][32].
// ============================================================================
__global__ __launch_bounds__(256) void k_kvred()
{
    extern __shared__ __half sred[];
    const int bh = blockIdx.x;
    const int ch = blockIdx.y;
    const int w = threadIdx.x >> 5, lane = threadIdx.x & 31;
    const int g = lane >> 2, t = lane & 3;

    __half* k_s = sred + w * 5120;
    const uint32_t uk = smem_u32(k_s);
    const uint32_t uv = uk + 2560 * 2;

    const int tok0 = ch * CHTOK + w * 64;
    const __half* kg = g_kh + ((size_t)bh * L_ + tok0) * 32;
    const __half* vg = g_vh + ((size_t)bh * L_ + tok0) * 32;

#pragma unroll
    for (int it = 0; it < 8; it++) {
        int i = lane + it * 32;
        int tok = i >> 2, c4 = i & 3;
        cp16(uk + tok * 80 + c4 * 16, kg + (size_t)i * 8);
        cp16(uv + tok * 80 + c4 * 16, vg + (size_t)i * 8);
    }
    asm volatile("cp.async.commit_group;");
    asm volatile("cp.async.wait_group 0;");
    __syncwarp();

    float acc[2][4][4] = {};
    float cs[2][4] = {};
    const uint32_t ones2 = 0x3C003C00u;

    const int tokA = (lane & 7) + ((lane >> 4) << 3);
    const int dA   = ((lane >> 3) & 1) * 8;
    const int tokB = (lane & 7) + (((lane >> 3) & 1) << 3);
    const int eB   = ((lane >> 4) & 1) * 8;

#pragma unroll
    for (int st = 0; st < 64; st += 16) {
        uint32_t a[2][4], bb[2][4];
#pragma unroll
        for (int mi = 0; mi < 2; mi++)
            LDMX4T(a[mi], uk + (st + tokA) * 80 + (mi * 16 + dA) * 2);
#pragma unroll
        for (int np = 0; np < 2; np++)
            LDMX4T(bb[np], uv + (st + tokB) * 80 + (np * 16 + eB) * 2);
#pragma unroll
        for (int mi = 0; mi < 2; mi++) {
#pragma unroll
            for (int nb = 0; nb < 4; nb++) {
                const int np = nb >> 1, hi = nb & 1;
                mma16(acc[mi][nb], a[mi][0], a[mi][1], a[mi][2], a[mi][3],
                      bb[np][hi * 2], bb[np][hi * 2 + 1]);
            }
            mma16(cs[mi], a[mi][0], a[mi][1], a[mi][2], a[mi][3], ones2, ones2);
        }
    }
    __syncthreads();

    float* s_part = (float*)sred;
    float* s_ksp  = s_part + 8 * 1024;
#pragma unroll
    for (int mi = 0; mi < 2; mi++) {
#pragma unroll
        for (int nb = 0; nb < 4; nb++) {
            const int d0 = mi * 16 + g, e0 = nb * 8 + 2 * t;
            *(float2*)&s_part[w * 1024 + d0 * 32 + e0] =
                make_float2(acc[mi][nb][0], acc[mi][nb][1]);
            *(float2*)&s_part[w * 1024 + (d0 + 8) * 32 + e0] =
                make_float2(acc[mi][nb][2], acc[mi][nb][3]);
        }
        if (t == 0) {
            s_ksp[w * 32 + mi * 16 + g]     = cs[mi][0];
            s_ksp[w * 32 + mi * 16 + g + 8] = cs[mi][2];
        }
    }
    __syncthreads();

    const int tid = threadIdx.x;
    for (int j = tid; j < 1024; j += 256) {
        float s = 0.f;
#pragma unroll
        for (int ww = 0; ww < 8; ww++) s += s_part[ww * 1024 + j];
        g_kvpart[((size_t)ch * 32 + bh) * 1024 + j] = s;
    }
    if (tid < 32) {
        float s = 0.f;
#pragma unroll
        for (int ww = 0; ww < 8; ww++) s += s_ksp[ww * 32 + tid];
        g_kspart[(ch * 32 + bh) * 32 + tid] = s;
    }
}

// kvfin: final chunk reduction; kv -> HALF pitch-40 layout, ksum stays f32.
__global__ __launch_bounds__(256) void k_kvfin()
{
    const int bh = blockIdx.x;
    for (int j = threadIdx.x; j < 1024; j += 256) {
        float s = 0.f;
#pragma unroll
        for (int c = 0; c < NCH; c++) s += g_kvpart[((size_t)c * 32 + bh) * 1024 + j];
        const int d = j >> 5, e = j & 31;
        g_kvh[(size_t)bh * 1280 + d * 40 + e] = __float2half(s);
    }
    if (threadIdx.x < 32) {
        float s = 0.f;
#pragma unroll
        for (int c = 0; c < NCH; c++) s += g_kspart[(c * 32 + bh) * 32 + threadIdx.x];
        g_ksum[bh * 32 + threadIdx.x] = s;
    }
}

// ============================================================================
extern "C" void kernel_launch(void* const* d_in, const int* in_sizes, int n_in,
                              void* d_out, int out_size)
{
    const float* x    = (const float*)d_in[0];
    const float* Wq   = (const float*)d_in[1];
    const float* bq   = (const float*)d_in[2];
    const float* Wk   = (const float*)d_in[3];
    const float* bk   = (const float*)d_in[4];
    const float* Wv   = (const float*)d_in[5];
    const float* bv   = (const float*)d_in[6];
    const float* Wo   = (const float*)d_in[7];
    const float* bo   = (const float*)d_in[8];
    const float* W1   = (const float*)d_in[9];
    const float* b1   = (const float*)d_in[10];
    const float* W2   = (const float*)d_in[11];
    const float* b2   = (const float*)d_in[12];
    const float* ln1g = (const float*)d_in[13];
    const float* ln1b = (const float*)d_in[14];
    const float* ln2g = (const float*)d_in[15];
    const float* ln2b = (const float*)d_in[16];
    float* out = (float*)d_out;

    __half *xh, *x1h, *wqkvT, *woT, *w1T, *w2T;
    float *bqkv;
    cudaGetSymbolAddress((void**)&xh,    g_xh);
    cudaGetSymbolAddress((void**)&x1h,   g_x1h);
    cudaGetSymbolAddress((void**)&wqkvT, g_wqkvT);
    cudaGetSymbolAddress((void**)&woT,   g_woT);
    cudaGetSymbolAddress((void**)&w1T,   g_w1T);
    cudaGetSymbolAddress((void**)&w2T,   g_w2T);
    cudaGetSymbolAddress((void**)&bqkv,  g_bqkv);

    const int GSM   = 98304;               // QKV gemm 4-stage
    const int GSMKV = 8 * 5120 * 2;        // 81920
    const int GSMAT = 53248 * 2;           // 106496: fused attn+Wo+LN1
    const int GSMFF = 54272 * 2;           // 108544: fused FFN+LN2
    cudaFuncSetAttribute(k_gemm_qkv, cudaFuncAttributeMaxDynamicSharedMemorySize, GSM);
    cudaFuncSetAttribute(k_attn_ln, cudaFuncAttributeMaxDynamicSharedMemorySize, GSMAT);
    cudaFuncSetAttribute(k_ffn_ln, cudaFuncAttributeMaxDynamicSharedMemorySize, GSMFF);
    cudaFuncSetAttribute(k_kvred, cudaFuncAttributeMaxDynamicSharedMemorySize, GSMKV);

    k_cvtx<<<MTOK * D_ / 4 / 512, 512>>>(x);
    k_trall<<<769, dim3(32, 8)>>>(Wq, Wk, Wv, Wo, W1, W2, bq, bk, bv);

    // merged QKV projection: phi for q,k; head-major scatter for k,v
    k_gemm_qkv<<<dim3(6, 512), 256, GSM>>>(xh, wqkvT, bqkv, D_);

    k_kvred<<<dim3(32, NCH), 256, GSMKV>>>();
    k_kvfin<<<32, 256>>>();

    // fused attn readout + Wo + half residual (xh) + LN1 -> x1h
    k_attn_ln<<<1024, 256, GSMAT>>>(woT, bo, xh, ln1g, ln1b, x1h);

    // fused FFN + half residual (x1h) + LN2 -> out (hidden never hits HBM)
    k_ffn_ln<<<1024, 256, GSMFF>>>(x1h, w1T, w2T, b1, b2, x1h, ln2g, ln2b, out);
}